// round 1
// baseline (speedup 1.0000x reference)
#include <cuda_runtime.h>
#include <math.h>

#define BATCH 2
#define SEQ   2048
#define MTOT  (BATCH*SEQ)      // 4096
#define DE    1024
#define NH    16
#define DK    64
#define VOCAB 32000
#define NL    4
#define PI_F  3.14159265358979323846f

// ---------------- scratch (static device globals; no allocation) ----------------
__device__ float d_rnorm[VOCAB];
__device__ float d_x [MTOT*DE];
__device__ float d_qb[MTOT*DE];
__device__ float d_kb[MTOT*DE];
__device__ float d_vb[MTOT*DE];
__device__ float d_gb[MTOT*DE];
__device__ float d_hh[MTOT*DE];

__device__ __forceinline__ float wredsum(float x) {
#pragma unroll
    for (int o = 16; o > 0; o >>= 1) x += __shfl_xor_sync(0xFFFFFFFFu, x, o);
    return x;
}

// ---------------- reciprocal row norms of embed ----------------
__global__ void rnorm_kernel(const float* __restrict__ embed, float* __restrict__ rnorm) {
    int v = blockIdx.x;
    const float* row = embed + (size_t)v * DE;
    float s = 0.f;
    for (int i = threadIdx.x; i < DE; i += 256) { float e = row[i]; s += e * e; }
    __shared__ float sh[256];
    sh[threadIdx.x] = s; __syncthreads();
    for (int o = 128; o > 0; o >>= 1) {
        if (threadIdx.x < o) sh[threadIdx.x] += sh[threadIdx.x + o];
        __syncthreads();
    }
    if (threadIdx.x == 0) rnorm[v] = 1.0f / fmaxf(sqrtf(sh[0]), 1e-12f);
}

// ---------------- embedding lookup: x = W_norm[id] * exp(s_E) ----------------
__global__ void embed_kernel(const int* __restrict__ ids, const float* __restrict__ embed,
                             const float* __restrict__ rnorm, const float* __restrict__ sE,
                             float* __restrict__ x) {
    int m = blockIdx.x;
    int id = ids[m];
    float sc = rnorm[id] * expf(*sE);
    const float4* row = (const float4*)(embed + (size_t)id * DE);
    float4* out = (float4*)(x + (size_t)m * DE);
    int i = threadIdx.x;                 // 256 threads, 256 float4s
    float4 r = row[i];
    r.x *= sc; r.y *= sc; r.z *= sc; r.w *= sc;
    out[i] = r;
}

// ---------------- generic NT GEMM: C[m,n] = sum_k A[m,k]*B[n,k] ----------------
// M,N multiples of 64; K multiple of 16. Optional per-column scale and exp(scalar) scale;
// optional accumulate (residual).
__global__ __launch_bounds__(256) void gemm_nt(
    const float* __restrict__ A, const float* __restrict__ B, float* __restrict__ C,
    int M, int N, int K,
    const float* __restrict__ colScale, const float* __restrict__ scalarLogPtr,
    int accumulate)
{
    __shared__ float As[16][64];
    __shared__ float Bs[16][64];
    int bm = blockIdx.y * 64;
    int bn = blockIdx.x * 64;
    int tid = threadIdx.x;
    int lr = tid >> 2;              // 0..63
    int lk = (tid & 3) << 2;        // 0,4,8,12
    int ty = tid >> 4;              // 0..15 (M groups of 4)
    int tx = tid & 15;              // 0..15 (N groups of 4)

    float acc[4][4];
#pragma unroll
    for (int i = 0; i < 4; i++)
#pragma unroll
        for (int j = 0; j < 4; j++) acc[i][j] = 0.f;

    const float* Aptr = A + (size_t)(bm + lr) * K + lk;
    const float* Bptr = B + (size_t)(bn + lr) * K + lk;

    for (int k0 = 0; k0 < K; k0 += 16) {
        float4 a = *(const float4*)(Aptr + k0);
        float4 b = *(const float4*)(Bptr + k0);
        As[lk + 0][lr] = a.x; As[lk + 1][lr] = a.y; As[lk + 2][lr] = a.z; As[lk + 3][lr] = a.w;
        Bs[lk + 0][lr] = b.x; Bs[lk + 1][lr] = b.y; Bs[lk + 2][lr] = b.z; Bs[lk + 3][lr] = b.w;
        __syncthreads();
#pragma unroll
        for (int kk = 0; kk < 16; kk++) {
            float4 av = *(const float4*)&As[kk][ty << 2];
            float4 bv = *(const float4*)&Bs[kk][tx << 2];
            float ar[4] = {av.x, av.y, av.z, av.w};
            float br[4] = {bv.x, bv.y, bv.z, bv.w};
#pragma unroll
            for (int i = 0; i < 4; i++)
#pragma unroll
                for (int j = 0; j < 4; j++)
                    acc[i][j] += ar[i] * br[j];
        }
        __syncthreads();
    }

    float sc = scalarLogPtr ? expf(*scalarLogPtr) : 1.0f;
#pragma unroll
    for (int i = 0; i < 4; i++) {
        int row = bm + (ty << 2) + i;
#pragma unroll
        for (int j = 0; j < 4; j++) {
            int col = bn + (tx << 2) + j;
            float val = acc[i][j] * sc;
            if (colScale) val *= colScale[col];
            size_t idx = (size_t)row * N + col;
            if (accumulate) C[idx] += val; else C[idx] = val;
        }
    }
}

// ---------------- per-head normalize + MiPE rotate (q,k,v) + g_hat ----------------
// one warp handles one (b,t,h): 64 elems = float2 per lane
__global__ void normrot_kernel(float* __restrict__ q, float* __restrict__ k,
                               float* __restrict__ v, float* __restrict__ g,
                               const float* __restrict__ sw) {
    int gwarp = (blockIdx.x * blockDim.x + threadIdx.x) >> 5;
    int lane = threadIdx.x & 31;
    int h = gwarp & (NH - 1);
    int m = gwarp >> 4;
    int t = m & (SEQ - 1);
    size_t base = (size_t)m * DE + h * DK + 2 * lane;

    float2 qv = *(float2*)(q + base);
    float2 kv = *(float2*)(k + base);
    float2 vv = *(float2*)(v + base);
    float2 gv = *(float2*)(g + base);

    float sq = wredsum(qv.x * qv.x + qv.y * qv.y);
    float sk = wredsum(kv.x * kv.x + kv.y * kv.y);
    float sv = wredsum(vv.x * vv.x + vv.y * vv.y);
    float iq = 1.0f / fmaxf(sqrtf(sq), 1e-12f);
    float ik = 1.0f / fmaxf(sqrtf(sk), 1e-12f);
    float iv = 1.0f / fmaxf(sqrtf(sv), 1e-12f);
    qv.x *= iq; qv.y *= iq;
    kv.x *= ik; kv.y *= ik;
    vv.x *= iv; vv.y *= iv;

    // MiPE rotation on dims 0,1 (held entirely by lane 0)
    float w = expf(sw[h]) + 1.0f;
    float phi = (w < 128.0f) ? 0.5f * (cosf(PI_F * w / 128.0f) + 1.0f) : 0.0f;
    float ang = (float)t * (phi / w);
    float c = cosf(ang), s = sinf(ang);
    if (lane == 0) {
        float q0 = qv.x, q1 = qv.y;
        qv.x = q0 * c - q1 * s; qv.y = q0 * s + q1 * c;
        float k0 = kv.x, k1 = kv.y;
        kv.x = k0 * c - k1 * s; kv.y = k0 * s + k1 * c;
    }

    // g_hat = tanh(silu(g))
    float s0 = gv.x / (1.0f + expf(-gv.x));
    float s1 = gv.y / (1.0f + expf(-gv.y));
    gv.x = tanhf(s0); gv.y = tanhf(s1);

    *(float2*)(q + base) = qv;
    *(float2*)(k + base) = kv;
    *(float2*)(v + base) = vv;
    *(float2*)(g + base) = gv;
}

// ---------------- windowed attention + epilogue (u * g_hat * exp(sO)) ----------------
// one warp per (b,t,h); window lookback <= ceil(w)-1 <= ~129
__global__ void attn_kernel(const float* __restrict__ q, const float* __restrict__ k,
                            const float* __restrict__ v, const float* __restrict__ g,
                            const float* __restrict__ sw, const float* __restrict__ sr,
                            const float* __restrict__ sO, float* __restrict__ hh) {
    int gwarp = (blockIdx.x * blockDim.x + threadIdx.x) >> 5;
    int lane = threadIdx.x & 31;
    int h = gwarp & (NH - 1);
    int m = gwarp >> 4;
    int t = m & (SEQ - 1);

    float w  = expf(sw[h]) + 1.0f;
    float r  = expf(sr[h]) + 1.0f;
    float es = expf(sO[h]);

    size_t base = (size_t)m * DE + h * DK + 2 * lane;
    float2 qv = *(const float2*)(q + base);

    float acc0 = 0.f, acc1 = 0.f;
    int lb = (int)ceilf(w) - 1;
    if (lb > t) lb = t;

    for (int s = t - lb; s <= t; ++s) {
        float rel = (float)(s - t);          // <= 0
        if (-rel >= w) continue;             // need rel > -w
        size_t kb = (size_t)(m - t + s) * DE + h * DK + 2 * lane;
        float2 kv = *(const float2*)(k + kb);
        float sim = wredsum(qv.x * kv.x + qv.y * kv.y);
        float mask = 0.5f * (cosf(PI_F * rel / w) + 1.0f);
        float tmp = fmaxf(1.0f - r * (1.0f - sim), 0.0f);
        float rho = tmp * tmp * mask;
        float2 vv = *(const float2*)(v + kb);
        acc0 += rho * vv.x;
        acc1 += rho * vv.y;
    }

    float hn2 = wredsum(acc0 * acc0 + acc1 * acc1);
    float hn = fmaxf(sqrtf(hn2), 1e-8f);
    float us = tanhf(hn) / hn;

    float2 gv = *(const float2*)(g + base);   // already tanh(silu(g))
    float2 o;
    o.x = acc0 * us * gv.x * es;
    o.y = acc1 * us * gv.y * es;
    *(float2*)(hh + base) = o;
}

// ---------------- launch ----------------
extern "C" void kernel_launch(void* const* d_in, const int* in_sizes, int n_in,
                              void* d_out, int out_size) {
    const int*   ids   = (const int*)d_in[0];
    const float* embed = (const float*)d_in[1];
    const float* sE    = (const float*)d_in[2];
    const float* sF    = (const float*)d_in[3];
    const float* Wq    = (const float*)d_in[4];
    const float* Wk    = (const float*)d_in[5];
    const float* Wv    = (const float*)d_in[6];
    const float* Wg    = (const float*)d_in[7];
    const float* Wo    = (const float*)d_in[8];
    const float* sw    = (const float*)d_in[9];
    const float* sr    = (const float*)d_in[10];
    const float* sO    = (const float*)d_in[11];
    float* out = (float*)d_out;

    float *x, *qb, *kb, *vb, *gb, *hh, *rn;
    cudaGetSymbolAddress((void**)&x,  d_x);
    cudaGetSymbolAddress((void**)&qb, d_qb);
    cudaGetSymbolAddress((void**)&kb, d_kb);
    cudaGetSymbolAddress((void**)&vb, d_vb);
    cudaGetSymbolAddress((void**)&gb, d_gb);
    cudaGetSymbolAddress((void**)&hh, d_hh);
    cudaGetSymbolAddress((void**)&rn, d_rnorm);

    rnorm_kernel<<<VOCAB, 256>>>(embed, rn);
    embed_kernel<<<MTOT, 256>>>(ids, embed, rn, sE, x);

    dim3 gproj(DE / 64, MTOT / 64);          // (16, 64)
    int warps_total = MTOT * NH;             // 65536 warps
    int nblk = (warps_total * 32) / 256;     // 8192 blocks of 256

    for (int l = 0; l < NL; ++l) {
        const float* wq = Wq + (size_t)l * DE * DE;
        const float* wk = Wk + (size_t)l * DE * DE;
        const float* wv = Wv + (size_t)l * DE * DE;
        const float* wg = Wg + (size_t)l * DE * DE;
        const float* wo = Wo + (size_t)l * DE * DE;
        const float* swl = sw + l * NH;
        const float* srl = sr + l * NH;
        const float* sOl = sO + l * NH;

        gemm_nt<<<gproj, 256>>>(x, wq, qb, MTOT, DE, DE, nullptr, nullptr, 0);
        gemm_nt<<<gproj, 256>>>(x, wk, kb, MTOT, DE, DE, nullptr, nullptr, 0);
        gemm_nt<<<gproj, 256>>>(x, wv, vb, MTOT, DE, DE, nullptr, nullptr, 0);
        gemm_nt<<<gproj, 256>>>(x, wg, gb, MTOT, DE, DE, nullptr, nullptr, 0);

        normrot_kernel<<<nblk, 256>>>(qb, kb, vb, gb, swl);
        attn_kernel<<<nblk, 256>>>(qb, kb, vb, gb, swl, srl, sOl, hh);

        gemm_nt<<<gproj, 256>>>(hh, wo, x, MTOT, DE, DE, nullptr, nullptr, 1);
    }

    dim3 gfin(VOCAB / 64, MTOT / 64);        // (500, 64)
    gemm_nt<<<gfin, 256>>>(x, embed, out, MTOT, VOCAB, DE, rn, sF, 0);
}

// round 3
// speedup vs baseline: 2.3591x; 2.3591x over previous
#include <cuda_runtime.h>
#include <cuda_bf16.h>
#include <math.h>

#define BATCH 2
#define SEQ   2048
#define MTOT  (BATCH*SEQ)      // 4096
#define DE    1024
#define NH    16
#define DK    64
#define VOCAB 32000
#define NL    4
#define PI_F  3.14159265358979323846f

#define BM 128
#define BN 128
#define BK 32
#define SPAD 40                // smem row stride in bf16 elems

// ---------------- scratch (static device globals; no allocation) ----------------
__device__ float d_rnorm[VOCAB];
__device__ float d_x [MTOT*DE];
__device__ float d_qb[MTOT*DE];
__device__ float d_kb[MTOT*DE];
__device__ float d_vb[MTOT*DE];
__device__ float d_gb[MTOT*DE];
__device__ float d_hh[MTOT*DE];
__device__ __nv_bfloat16 d_ehi[(size_t)VOCAB*DE];
__device__ __nv_bfloat16 d_elo[(size_t)VOCAB*DE];
__device__ __nv_bfloat16 d_whi[(size_t)5*NL*DE*DE];
__device__ __nv_bfloat16 d_wlo[(size_t)5*NL*DE*DE];
__device__ __nv_bfloat16 d_xhi[MTOT*DE];
__device__ __nv_bfloat16 d_xlo[MTOT*DE];
__device__ __nv_bfloat16 d_hhi[MTOT*DE];
__device__ __nv_bfloat16 d_hlo[MTOT*DE];

__device__ __forceinline__ float wredsum(float x) {
#pragma unroll
    for (int o = 16; o > 0; o >>= 1) x += __shfl_xor_sync(0xFFFFFFFFu, x, o);
    return x;
}

__device__ __forceinline__ unsigned smem_u32(const void* p) {
    return (unsigned)__cvta_generic_to_shared(p);
}

// ---------------- reciprocal row norms of embed ----------------
__global__ void rnorm_kernel(const float* __restrict__ embed, float* __restrict__ rnorm) {
    int v = blockIdx.x;
    const float* row = embed + (size_t)v * DE;
    float s = 0.f;
    for (int i = threadIdx.x; i < DE; i += 256) { float e = row[i]; s += e * e; }
    __shared__ float sh[256];
    sh[threadIdx.x] = s; __syncthreads();
    for (int o = 128; o > 0; o >>= 1) {
        if (threadIdx.x < o) sh[threadIdx.x] += sh[threadIdx.x + o];
        __syncthreads();
    }
    if (threadIdx.x == 0) rnorm[v] = 1.0f / fmaxf(sqrtf(sh[0]), 1e-12f);
}

// ---------------- embedding lookup: x = W_norm[id] * exp(s_E) ----------------
__global__ void embed_kernel(const int* __restrict__ ids, const float* __restrict__ embed,
                             const float* __restrict__ rnorm, const float* __restrict__ sE,
                             float* __restrict__ x) {
    int m = blockIdx.x;
    int id = ids[m];
    float sc = rnorm[id] * expf(*sE);
    const float4* row = (const float4*)(embed + (size_t)id * DE);
    float4* out = (float4*)(x + (size_t)m * DE);
    int i = threadIdx.x;
    float4 r = row[i];
    r.x *= sc; r.y *= sc; r.z *= sc; r.w *= sc;
    out[i] = r;
}

// ---------------- fp32 -> bf16 hi/lo split (Markidis) ----------------
__global__ void conv_kernel(const float* __restrict__ src, __nv_bfloat16* __restrict__ hi,
                            __nv_bfloat16* __restrict__ lo, int n4) {
    int i = blockIdx.x * blockDim.x + threadIdx.x;
    if (i >= n4) return;
    float4 f = ((const float4*)src)[i];
    __nv_bfloat16 h0 = __float2bfloat16(f.x);
    __nv_bfloat16 h1 = __float2bfloat16(f.y);
    __nv_bfloat16 h2 = __float2bfloat16(f.z);
    __nv_bfloat16 h3 = __float2bfloat16(f.w);
    __nv_bfloat16 l0 = __float2bfloat16(f.x - __bfloat162float(h0));
    __nv_bfloat16 l1 = __float2bfloat16(f.y - __bfloat162float(h1));
    __nv_bfloat16 l2 = __float2bfloat16(f.z - __bfloat162float(h2));
    __nv_bfloat16 l3 = __float2bfloat16(f.w - __bfloat162float(h3));
    __nv_bfloat162* H = (__nv_bfloat162*)hi;
    __nv_bfloat162* L = (__nv_bfloat162*)lo;
    __nv_bfloat162 p;
    p.x = h0; p.y = h1; H[2*i]   = p;
    p.x = h2; p.y = h3; H[2*i+1] = p;
    p.x = l0; p.y = l1; L[2*i]   = p;
    p.x = l2; p.y = l3; L[2*i+1] = p;
}

// ---------------- split-bf16 tensor-core NT GEMM ----------------
#define MMA_BF16(C, A, B)                                                      \
    asm volatile(                                                              \
        "mma.sync.aligned.m16n8k16.row.col.f32.bf16.bf16.f32 "                 \
        "{%0,%1,%2,%3}, {%4,%5,%6,%7}, {%8,%9}, {%0,%1,%2,%3};\n"              \
        : "+f"((C)[0]), "+f"((C)[1]), "+f"((C)[2]), "+f"((C)[3])               \
        : "r"((A)[0]), "r"((A)[1]), "r"((A)[2]), "r"((A)[3]),                  \
          "r"((B)[0]), "r"((B)[1]))

__global__ __launch_bounds__(256) void gemm_split(
    const __nv_bfloat16* __restrict__ Ahi, const __nv_bfloat16* __restrict__ Alo,
    const __nv_bfloat16* __restrict__ Bhi, const __nv_bfloat16* __restrict__ Blo,
    float* __restrict__ C, int M, int N, int K,
    const float* __restrict__ colScale, const float* __restrict__ scalarLog,
    int accumulate)
{
    __shared__ __nv_bfloat16 sAh[BM*SPAD];
    __shared__ __nv_bfloat16 sAl[BM*SPAD];
    __shared__ __nv_bfloat16 sBh[BN*SPAD];
    __shared__ __nv_bfloat16 sBl[BN*SPAD];

    int tid  = threadIdx.x;
    int lane = tid & 31;
    int warp = tid >> 5;
    int wm = (warp >> 2) * 64;   // warp M offset within CTA tile
    int wn = (warp & 3) * 32;    // warp N offset
    int bm = blockIdx.y * BM;
    int bn = blockIdx.x * BN;

    int lcol  = (tid & 7) * 4;   // k offset within BK
    int lrow0 = tid >> 3;        // row 0..31, +32 per chunk

    uint2 ah[4], al[4], bh[4], bl[4];

    float c[4][4][4];
#pragma unroll
    for (int i = 0; i < 4; i++)
#pragma unroll
        for (int j = 0; j < 4; j++)
#pragma unroll
            for (int q = 0; q < 4; q++) c[i][j][q] = 0.f;

    // ldmatrix lane addressing: identical scheme for A and B (both [row][k] layout).
    // x4 matrices: 0=(r0-7,k0-7) 1=(r8-15,k0-7) 2=(r0-7,k8-15) 3=(r8-15,k8-15) for A,
    // B uses:      0=(n0-7,k0-7) 1=(n0-7,k8-15) 2=(n8-15,k0-7) 3=(n8-15,k8-15)
    int arow_l = lane & 15;
    int acol_l = (lane >> 4) << 3;                       // 0 or 8
    int brow_l = (lane & 7) + ((lane >> 4) << 3);        // 0..15
    int bcol_l = ((lane >> 3) & 1) << 3;                 // 0 or 8

#define LDG_TILE(k0)                                                           \
    {                                                                          \
        _Pragma("unroll")                                                      \
        for (int i = 0; i < 4; i++) {                                          \
            int row = lrow0 + i * 32;                                          \
            size_t offA = (size_t)(bm + row) * K + (k0) + lcol;                \
            size_t offB = (size_t)(bn + row) * K + (k0) + lcol;                \
            ah[i] = *(const uint2*)(Ahi + offA);                               \
            al[i] = *(const uint2*)(Alo + offA);                               \
            bh[i] = *(const uint2*)(Bhi + offB);                               \
            bl[i] = *(const uint2*)(Blo + offB);                               \
        }                                                                      \
    }

#define STS_TILE()                                                             \
    {                                                                          \
        _Pragma("unroll")                                                      \
        for (int i = 0; i < 4; i++) {                                          \
            int s = (lrow0 + i * 32) * SPAD + lcol;                            \
            *(uint2*)&sAh[s] = ah[i];                                          \
            *(uint2*)&sAl[s] = al[i];                                          \
            *(uint2*)&sBh[s] = bh[i];                                          \
            *(uint2*)&sBl[s] = bl[i];                                          \
        }                                                                      \
    }

    LDG_TILE(0);
    STS_TILE();
    __syncthreads();

    for (int k0 = BK; k0 <= K; k0 += BK) {
        bool more = (k0 < K);
        if (more) LDG_TILE(k0);

#pragma unroll
        for (int ks = 0; ks < 2; ks++) {
            unsigned Ah[4][4], Al[4][4], Bh[4][2], Bl[4][2];
            int acol = ks * 16 + acol_l;
            int bcol = ks * 16 + bcol_l;
#pragma unroll
            for (int mt = 0; mt < 4; mt++) {
                unsigned sa = smem_u32(&sAh[(wm + mt*16 + arow_l) * SPAD + acol]);
                asm volatile("ldmatrix.sync.aligned.m8n8.x4.shared.b16 {%0,%1,%2,%3}, [%4];\n"
                    : "=r"(Ah[mt][0]), "=r"(Ah[mt][1]), "=r"(Ah[mt][2]), "=r"(Ah[mt][3]) : "r"(sa));
                unsigned sl = smem_u32(&sAl[(wm + mt*16 + arow_l) * SPAD + acol]);
                asm volatile("ldmatrix.sync.aligned.m8n8.x4.shared.b16 {%0,%1,%2,%3}, [%4];\n"
                    : "=r"(Al[mt][0]), "=r"(Al[mt][1]), "=r"(Al[mt][2]), "=r"(Al[mt][3]) : "r"(sl));
            }
#pragma unroll
            for (int p = 0; p < 2; p++) {
                // NON-trans: B stored [n][k] row-major == K x N col-major == mma's B layout.
                unsigned sb = smem_u32(&sBh[(wn + p*16 + brow_l) * SPAD + bcol]);
                unsigned r0, r1, r2, r3;
                asm volatile("ldmatrix.sync.aligned.m8n8.x4.shared.b16 {%0,%1,%2,%3}, [%4];\n"
                    : "=r"(r0), "=r"(r1), "=r"(r2), "=r"(r3) : "r"(sb));
                Bh[p*2][0] = r0; Bh[p*2][1] = r1; Bh[p*2+1][0] = r2; Bh[p*2+1][1] = r3;
                unsigned sbl = smem_u32(&sBl[(wn + p*16 + brow_l) * SPAD + bcol]);
                asm volatile("ldmatrix.sync.aligned.m8n8.x4.shared.b16 {%0,%1,%2,%3}, [%4];\n"
                    : "=r"(r0), "=r"(r1), "=r"(r2), "=r"(r3) : "r"(sbl));
                Bl[p*2][0] = r0; Bl[p*2][1] = r1; Bl[p*2+1][0] = r2; Bl[p*2+1][1] = r3;
            }
#pragma unroll
            for (int mt = 0; mt < 4; mt++)
#pragma unroll
                for (int nt = 0; nt < 4; nt++) {
                    MMA_BF16(c[mt][nt], Ah[mt], Bh[nt]);   // hi*hi
                    MMA_BF16(c[mt][nt], Ah[mt], Bl[nt]);   // hi*lo
                    MMA_BF16(c[mt][nt], Al[mt], Bh[nt]);   // lo*hi
                }
        }
        __syncthreads();
        if (more) { STS_TILE(); __syncthreads(); }
    }

    // epilogue
    float sc = scalarLog ? expf(*scalarLog) : 1.0f;
    int g  = lane >> 2;
    int t2 = (lane & 3) * 2;
#pragma unroll
    for (int mt = 0; mt < 4; mt++) {
#pragma unroll
        for (int nt = 0; nt < 4; nt++) {
            int row = bm + wm + mt*16 + g;
            int col = bn + wn + nt*8 + t2;
            float cs0 = colScale ? colScale[col]   : 1.0f;
            float cs1 = colScale ? colScale[col+1] : 1.0f;
            float v0 = c[mt][nt][0] * sc * cs0;
            float v1 = c[mt][nt][1] * sc * cs1;
            float v2 = c[mt][nt][2] * sc * cs0;
            float v3 = c[mt][nt][3] * sc * cs1;
            float* p0 = C + (size_t)row * N + col;
            float* p1 = C + (size_t)(row + 8) * N + col;
            if (accumulate) {
                p0[0] += v0; p0[1] += v1;
                p1[0] += v2; p1[1] += v3;
            } else {
                float2 a; a.x = v0; a.y = v1; *(float2*)p0 = a;
                float2 b; b.x = v2; b.y = v3; *(float2*)p1 = b;
            }
        }
    }
}

// ---------------- per-head normalize + MiPE rotate (q,k,v) + g_hat ----------------
__global__ void normrot_kernel(float* __restrict__ q, float* __restrict__ k,
                               float* __restrict__ v, float* __restrict__ g,
                               const float* __restrict__ sw) {
    int gwarp = (blockIdx.x * blockDim.x + threadIdx.x) >> 5;
    int lane = threadIdx.x & 31;
    int h = gwarp & (NH - 1);
    int m = gwarp >> 4;
    int t = m & (SEQ - 1);
    size_t base = (size_t)m * DE + h * DK + 2 * lane;

    float2 qv = *(float2*)(q + base);
    float2 kv = *(float2*)(k + base);
    float2 vv = *(float2*)(v + base);
    float2 gv = *(float2*)(g + base);

    float sq = wredsum(qv.x * qv.x + qv.y * qv.y);
    float sk = wredsum(kv.x * kv.x + kv.y * kv.y);
    float sv = wredsum(vv.x * vv.x + vv.y * vv.y);
    float iq = 1.0f / fmaxf(sqrtf(sq), 1e-12f);
    float ik = 1.0f / fmaxf(sqrtf(sk), 1e-12f);
    float iv = 1.0f / fmaxf(sqrtf(sv), 1e-12f);
    qv.x *= iq; qv.y *= iq;
    kv.x *= ik; kv.y *= ik;
    vv.x *= iv; vv.y *= iv;

    float w = expf(sw[h]) + 1.0f;
    float phi = (w < 128.0f) ? 0.5f * (cosf(PI_F * w / 128.0f) + 1.0f) : 0.0f;
    float ang = (float)t * (phi / w);
    float cc = cosf(ang), ss = sinf(ang);
    if (lane == 0) {
        float q0 = qv.x, q1 = qv.y;
        qv.x = q0 * cc - q1 * ss; qv.y = q0 * ss + q1 * cc;
        float k0 = kv.x, k1 = kv.y;
        kv.x = k0 * cc - k1 * ss; kv.y = k0 * ss + k1 * cc;
    }

    float s0 = gv.x / (1.0f + expf(-gv.x));
    float s1 = gv.y / (1.0f + expf(-gv.y));
    gv.x = tanhf(s0); gv.y = tanhf(s1);

    *(float2*)(q + base) = qv;
    *(float2*)(k + base) = kv;
    *(float2*)(v + base) = vv;
    *(float2*)(g + base) = gv;
}

// ---------------- windowed attention + epilogue ----------------
__global__ void attn_kernel(const float* __restrict__ q, const float* __restrict__ k,
                            const float* __restrict__ v, const float* __restrict__ g,
                            const float* __restrict__ sw, const float* __restrict__ sr,
                            const float* __restrict__ sO, float* __restrict__ hh) {
    int gwarp = (blockIdx.x * blockDim.x + threadIdx.x) >> 5;
    int lane = threadIdx.x & 31;
    int h = gwarp & (NH - 1);
    int m = gwarp >> 4;
    int t = m & (SEQ - 1);

    float w  = expf(sw[h]) + 1.0f;
    float r  = expf(sr[h]) + 1.0f;
    float es = expf(sO[h]);

    size_t base = (size_t)m * DE + h * DK + 2 * lane;
    float2 qv = *(const float2*)(q + base);

    float acc0 = 0.f, acc1 = 0.f;
    int lb = (int)ceilf(w) - 1;
    if (lb > t) lb = t;

    for (int s = t - lb; s <= t; ++s) {
        float rel = (float)(s - t);
        if (-rel >= w) continue;
        size_t kb = (size_t)(m - t + s) * DE + h * DK + 2 * lane;
        float2 kv = *(const float2*)(k + kb);
        float sim = wredsum(qv.x * kv.x + qv.y * kv.y);
        float mask = 0.5f * (cosf(PI_F * rel / w) + 1.0f);
        float tmp = fmaxf(1.0f - r * (1.0f - sim), 0.0f);
        float rho = tmp * tmp * mask;
        float2 vv = *(const float2*)(v + kb);
        acc0 += rho * vv.x;
        acc1 += rho * vv.y;
    }

    float hn2 = wredsum(acc0 * acc0 + acc1 * acc1);
    float hn = fmaxf(sqrtf(hn2), 1e-8f);
    float us = tanhf(hn) / hn;

    float2 gv = *(const float2*)(g + base);
    float2 o;
    o.x = acc0 * us * gv.x * es;
    o.y = acc1 * us * gv.y * es;
    *(float2*)(hh + base) = o;
}

// ---------------- launch ----------------
extern "C" void kernel_launch(void* const* d_in, const int* in_sizes, int n_in,
                              void* d_out, int out_size) {
    const int*   ids   = (const int*)d_in[0];
    const float* embed = (const float*)d_in[1];
    const float* sE    = (const float*)d_in[2];
    const float* sF    = (const float*)d_in[3];
    const float* Wq    = (const float*)d_in[4];
    const float* Wk    = (const float*)d_in[5];
    const float* Wv    = (const float*)d_in[6];
    const float* Wg    = (const float*)d_in[7];
    const float* Wo    = (const float*)d_in[8];
    const float* sw    = (const float*)d_in[9];
    const float* sr    = (const float*)d_in[10];
    const float* sO    = (const float*)d_in[11];
    float* out = (float*)d_out;

    float *x, *qb, *kb, *vb, *gb, *hh, *rn;
    cudaGetSymbolAddress((void**)&x,  d_x);
    cudaGetSymbolAddress((void**)&qb, d_qb);
    cudaGetSymbolAddress((void**)&kb, d_kb);
    cudaGetSymbolAddress((void**)&vb, d_vb);
    cudaGetSymbolAddress((void**)&gb, d_gb);
    cudaGetSymbolAddress((void**)&hh, d_hh);
    cudaGetSymbolAddress((void**)&rn, d_rnorm);
    __nv_bfloat16 *ehi, *elo, *whi, *wlo, *xhi, *xlo, *hhi, *hlo;
    cudaGetSymbolAddress((void**)&ehi, d_ehi);
    cudaGetSymbolAddress((void**)&elo, d_elo);
    cudaGetSymbolAddress((void**)&whi, d_whi);
    cudaGetSymbolAddress((void**)&wlo, d_wlo);
    cudaGetSymbolAddress((void**)&xhi, d_xhi);
    cudaGetSymbolAddress((void**)&xlo, d_xlo);
    cudaGetSymbolAddress((void**)&hhi, d_hhi);
    cudaGetSymbolAddress((void**)&hlo, d_hlo);

    const size_t WSTRIDE = (size_t)NL * DE * DE;  // per weight-family stride

    rnorm_kernel<<<VOCAB, 256>>>(embed, rn);
    embed_kernel<<<MTOT, 256>>>(ids, embed, rn, sE, x);

    conv_kernel<<<(VOCAB*DE/4 + 255)/256, 256>>>(embed, ehi, elo, VOCAB*DE/4);
    conv_kernel<<<(int)(WSTRIDE/4/256), 256>>>(Wq, whi + 0*WSTRIDE, wlo + 0*WSTRIDE, (int)(WSTRIDE/4));
    conv_kernel<<<(int)(WSTRIDE/4/256), 256>>>(Wk, whi + 1*WSTRIDE, wlo + 1*WSTRIDE, (int)(WSTRIDE/4));
    conv_kernel<<<(int)(WSTRIDE/4/256), 256>>>(Wv, whi + 2*WSTRIDE, wlo + 2*WSTRIDE, (int)(WSTRIDE/4));
    conv_kernel<<<(int)(WSTRIDE/4/256), 256>>>(Wg, whi + 3*WSTRIDE, wlo + 3*WSTRIDE, (int)(WSTRIDE/4));
    conv_kernel<<<(int)(WSTRIDE/4/256), 256>>>(Wo, whi + 4*WSTRIDE, wlo + 4*WSTRIDE, (int)(WSTRIDE/4));

    dim3 gproj(DE / BN, MTOT / BM);          // (8, 32)
    int warps_total = MTOT * NH;
    int nblk = (warps_total * 32) / 256;

    for (int l = 0; l < NL; ++l) {
        size_t lo_off = (size_t)l * DE * DE;
        const __nv_bfloat16* wqh = whi + 0*WSTRIDE + lo_off; const __nv_bfloat16* wql = wlo + 0*WSTRIDE + lo_off;
        const __nv_bfloat16* wkh = whi + 1*WSTRIDE + lo_off; const __nv_bfloat16* wkl = wlo + 1*WSTRIDE + lo_off;
        const __nv_bfloat16* wvh = whi + 2*WSTRIDE + lo_off; const __nv_bfloat16* wvl = wlo + 2*WSTRIDE + lo_off;
        const __nv_bfloat16* wgh = whi + 3*WSTRIDE + lo_off; const __nv_bfloat16* wgl = wlo + 3*WSTRIDE + lo_off;
        const __nv_bfloat16* woh = whi + 4*WSTRIDE + lo_off; const __nv_bfloat16* wol = wlo + 4*WSTRIDE + lo_off;
        const float* swl = sw + l * NH;
        const float* srl = sr + l * NH;
        const float* sOl = sO + l * NH;

        conv_kernel<<<MTOT*DE/4/256, 256>>>(x, xhi, xlo, MTOT*DE/4);

        gemm_split<<<gproj, 256>>>(xhi, xlo, wqh, wql, qb, MTOT, DE, DE, nullptr, nullptr, 0);
        gemm_split<<<gproj, 256>>>(xhi, xlo, wkh, wkl, kb, MTOT, DE, DE, nullptr, nullptr, 0);
        gemm_split<<<gproj, 256>>>(xhi, xlo, wvh, wvl, vb, MTOT, DE, DE, nullptr, nullptr, 0);
        gemm_split<<<gproj, 256>>>(xhi, xlo, wgh, wgl, gb, MTOT, DE, DE, nullptr, nullptr, 0);

        normrot_kernel<<<nblk, 256>>>(qb, kb, vb, gb, swl);
        attn_kernel<<<nblk, 256>>>(qb, kb, vb, gb, swl, srl, sOl, hh);

        conv_kernel<<<MTOT*DE/4/256, 256>>>(hh, hhi, hlo, MTOT*DE/4);
        gemm_split<<<gproj, 256>>>(hhi, hlo, woh, wol, x, MTOT, DE, DE, nullptr, nullptr, 1);
    }

    conv_kernel<<<MTOT*DE/4/256, 256>>>(x, xhi, xlo, MTOT*DE/4);
    dim3 gfin(VOCAB / BN, MTOT / BM);        // (250, 32)
    gemm_split<<<gfin, 256>>>(xhi, xlo, ehi, elo, out, MTOT, VOCAB, DE, rn, sF, 0);
}

// round 5
// speedup vs baseline: 2.5912x; 1.0984x over previous
#include <cuda_runtime.h>
#include <cuda_bf16.h>
#include <math.h>
#include <stdint.h>

#define BATCH 2
#define SEQ   2048
#define MTOT  (BATCH*SEQ)      // 4096
#define DE    1024
#define NH    16
#define DK    64
#define VOCAB 32000
#define NL    4
#define PI_F  3.14159265358979323846f

#define BM 128
#define BN 128
#define BK 32
#define SPAD 40                    // bf16 elems per smem row (80B, conflict-free)
#define PLANE_BYTES (128*SPAD*2)   // 10240
#define STAGE_BYTES (4*PLANE_BYTES) // 40960
#define NSTAGE 3
#define SMEM_GEMM (NSTAGE*STAGE_BYTES) // 122880

// ---------------- scratch (static device globals; no allocation) ----------------
__device__ float d_rnorm[VOCAB];
__device__ float d_x [MTOT*DE];
__device__ float d_qb[MTOT*DE];
__device__ float d_kb[MTOT*DE];
__device__ float d_vb[MTOT*DE];
__device__ float d_gb[MTOT*DE];
__device__ float d_hh[MTOT*DE];
__device__ __nv_bfloat16 d_ehi[(size_t)VOCAB*DE];
__device__ __nv_bfloat16 d_elo[(size_t)VOCAB*DE];
__device__ __nv_bfloat16 d_whi[(size_t)5*NL*DE*DE];
__device__ __nv_bfloat16 d_wlo[(size_t)5*NL*DE*DE];
__device__ __nv_bfloat16 d_xhi[MTOT*DE];
__device__ __nv_bfloat16 d_xlo[MTOT*DE];
__device__ __nv_bfloat16 d_hhi[MTOT*DE];
__device__ __nv_bfloat16 d_hlo[MTOT*DE];

__device__ __forceinline__ float wredsum(float x) {
#pragma unroll
    for (int o = 16; o > 0; o >>= 1) x += __shfl_xor_sync(0xFFFFFFFFu, x, o);
    return x;
}
__device__ __forceinline__ unsigned smem_u32(const void* p) {
    return (unsigned)__cvta_generic_to_shared(p);
}

#define CP16(dst_u32, src_ptr) \
    asm volatile("cp.async.cg.shared.global [%0], [%1], 16;" :: "r"(dst_u32), "l"(src_ptr))
#define CP_COMMIT() asm volatile("cp.async.commit_group;" ::: "memory")
#define CP_WAIT(N)  asm volatile("cp.async.wait_group %0;" :: "n"(N) : "memory")

// ---------------- reciprocal row norms of embed ----------------
__global__ void rnorm_kernel(const float* __restrict__ embed, float* __restrict__ rnorm) {
    int v = blockIdx.x;
    const float* row = embed + (size_t)v * DE;
    float s = 0.f;
    for (int i = threadIdx.x; i < DE; i += 256) { float e = row[i]; s += e * e; }
    __shared__ float sh[256];
    sh[threadIdx.x] = s; __syncthreads();
    for (int o = 128; o > 0; o >>= 1) {
        if (threadIdx.x < o) sh[threadIdx.x] += sh[threadIdx.x + o];
        __syncthreads();
    }
    if (threadIdx.x == 0) rnorm[v] = 1.0f / fmaxf(sqrtf(sh[0]), 1e-12f);
}

// ---------------- embedding lookup ----------------
__global__ void embed_kernel(const int* __restrict__ ids, const float* __restrict__ embed,
                             const float* __restrict__ rnorm, const float* __restrict__ sE,
                             float* __restrict__ x) {
    int m = blockIdx.x;
    int id = ids[m];
    float sc = rnorm[id] * expf(*sE);
    const float4* row = (const float4*)(embed + (size_t)id * DE);
    float4* out = (float4*)(x + (size_t)m * DE);
    int i = threadIdx.x;
    float4 r = row[i];
    r.x *= sc; r.y *= sc; r.z *= sc; r.w *= sc;
    out[i] = r;
}

// ---------------- fp32 -> bf16 hi/lo split ----------------
__global__ void conv_kernel(const float* __restrict__ src, __nv_bfloat16* __restrict__ hi,
                            __nv_bfloat16* __restrict__ lo, int n4) {
    int i = blockIdx.x * blockDim.x + threadIdx.x;
    if (i >= n4) return;
    float4 f = ((const float4*)src)[i];
    __nv_bfloat16 h0 = __float2bfloat16(f.x);
    __nv_bfloat16 h1 = __float2bfloat16(f.y);
    __nv_bfloat16 h2 = __float2bfloat16(f.z);
    __nv_bfloat16 h3 = __float2bfloat16(f.w);
    __nv_bfloat16 l0 = __float2bfloat16(f.x - __bfloat162float(h0));
    __nv_bfloat16 l1 = __float2bfloat16(f.y - __bfloat162float(h1));
    __nv_bfloat16 l2 = __float2bfloat16(f.z - __bfloat162float(h2));
    __nv_bfloat16 l3 = __float2bfloat16(f.w - __bfloat162float(h3));
    __nv_bfloat162* H = (__nv_bfloat162*)hi;
    __nv_bfloat162* L = (__nv_bfloat162*)lo;
    __nv_bfloat162 p;
    p.x = h0; p.y = h1; H[2*i]   = p;
    p.x = h2; p.y = h3; H[2*i+1] = p;
    p.x = l0; p.y = l1; L[2*i]   = p;
    p.x = l2; p.y = l3; L[2*i+1] = p;
}

// ---------------- split-bf16 tensor-core NT GEMM, cp.async 3-stage pipeline ----------------
#define MMA_BF16(C, A, B)                                                      \
    asm volatile(                                                              \
        "mma.sync.aligned.m16n8k16.row.col.f32.bf16.bf16.f32 "                 \
        "{%0,%1,%2,%3}, {%4,%5,%6,%7}, {%8,%9}, {%0,%1,%2,%3};\n"              \
        : "+f"((C)[0]), "+f"((C)[1]), "+f"((C)[2]), "+f"((C)[3])               \
        : "r"((A)[0]), "r"((A)[1]), "r"((A)[2]), "r"((A)[3]),                  \
          "r"((B)[0]), "r"((B)[1]))

__global__ __launch_bounds__(256) void gemm_split(
    const __nv_bfloat16* __restrict__ Ahi, const __nv_bfloat16* __restrict__ Alo,
    const __nv_bfloat16* __restrict__ Bhi, const __nv_bfloat16* __restrict__ Blo,
    float* __restrict__ C, int M, int N, int K,
    const float* __restrict__ colScale, const float* __restrict__ scalarLog,
    int accumulate)
{
    extern __shared__ __align__(128) char smem[];
    uint32_t sbase = smem_u32(smem);

    int tid  = threadIdx.x;
    int lane = tid & 31;
    int warp = tid >> 5;
    int wm = (warp >> 2) * 64;
    int wn = (warp & 3) * 32;
    int bm = blockIdx.y * BM;
    int bn = blockIdx.x * BN;

    // cp.async mapping: each thread owns 2 rows (r0, r0+64) x one 16B chunk per plane
    int r0  = tid >> 2;            // 0..63
    int c16 = tid & 3;             // 16B chunk within 64B row data
    // per-thread global byte sources (advance by k0 elems each stage)
    const char* gA0h = (const char*)(Ahi + (size_t)(bm + r0     ) * K + c16 * 8);
    const char* gA1h = (const char*)(Ahi + (size_t)(bm + r0 + 64) * K + c16 * 8);
    const char* gA0l = (const char*)(Alo + (size_t)(bm + r0     ) * K + c16 * 8);
    const char* gA1l = (const char*)(Alo + (size_t)(bm + r0 + 64) * K + c16 * 8);
    const char* gB0h = (const char*)(Bhi + (size_t)(bn + r0     ) * K + c16 * 8);
    const char* gB1h = (const char*)(Bhi + (size_t)(bn + r0 + 64) * K + c16 * 8);
    const char* gB0l = (const char*)(Blo + (size_t)(bn + r0     ) * K + c16 * 8);
    const char* gB1l = (const char*)(Blo + (size_t)(bn + r0 + 64) * K + c16 * 8);
    // per-thread smem dest offsets (within stage)
    uint32_t s0 = r0 * (SPAD*2) + c16 * 16;
    uint32_t s1 = (r0 + 64) * (SPAD*2) + c16 * 16;

#define PREFETCH(st, k0)                                                       \
    {                                                                          \
        uint32_t sd = sbase + (st) * STAGE_BYTES;                              \
        size_t gk = (size_t)(k0) * 2;                                          \
        CP16(sd + 0*PLANE_BYTES + s0, gA0h + gk);                              \
        CP16(sd + 0*PLANE_BYTES + s1, gA1h + gk);                              \
        CP16(sd + 1*PLANE_BYTES + s0, gA0l + gk);                              \
        CP16(sd + 1*PLANE_BYTES + s1, gA1l + gk);                              \
        CP16(sd + 2*PLANE_BYTES + s0, gB0h + gk);                              \
        CP16(sd + 2*PLANE_BYTES + s1, gB1h + gk);                              \
        CP16(sd + 3*PLANE_BYTES + s0, gB0l + gk);                              \
        CP16(sd + 3*PLANE_BYTES + s1, gB1l + gk);                              \
        CP_COMMIT();                                                           \
    }

    float c[4][4][4];
#pragma unroll
    for (int i = 0; i < 4; i++)
#pragma unroll
        for (int j = 0; j < 4; j++)
#pragma unroll
            for (int q = 0; q < 4; q++) c[i][j][q] = 0.f;

    int arow_l = lane & 15;
    int acol_l = (lane >> 4) << 3;
    int brow_l = (lane & 7) + ((lane >> 4) << 3);
    int bcol_l = ((lane >> 3) & 1) << 3;

    int niter = K / BK;
    PREFETCH(0, 0);
    if (niter > 1) PREFETCH(1, BK);
    CP_WAIT(1);
    __syncthreads();

    for (int it = 0; it < niter; ++it) {
        int st = it % NSTAGE;
        if (it + 2 < niter) PREFETCH((it + 2) % NSTAGE, (it + 2) * BK);

        const __nv_bfloat16* sAh = (const __nv_bfloat16*)(smem + st*STAGE_BYTES + 0*PLANE_BYTES);
        const __nv_bfloat16* sAl = (const __nv_bfloat16*)(smem + st*STAGE_BYTES + 1*PLANE_BYTES);
        const __nv_bfloat16* sBh = (const __nv_bfloat16*)(smem + st*STAGE_BYTES + 2*PLANE_BYTES);
        const __nv_bfloat16* sBl = (const __nv_bfloat16*)(smem + st*STAGE_BYTES + 3*PLANE_BYTES);

#pragma unroll
        for (int ks = 0; ks < 2; ks++) {
            unsigned Ah[4][4], Al[4][4], Bh[4][2], Bl[4][2];
            int acol = ks * 16 + acol_l;
            int bcol = ks * 16 + bcol_l;
#pragma unroll
            for (int mt = 0; mt < 4; mt++) {
                unsigned sa = smem_u32(&sAh[(wm + mt*16 + arow_l) * SPAD + acol]);
                asm volatile("ldmatrix.sync.aligned.m8n8.x4.shared.b16 {%0,%1,%2,%3}, [%4];\n"
                    : "=r"(Ah[mt][0]), "=r"(Ah[mt][1]), "=r"(Ah[mt][2]), "=r"(Ah[mt][3]) : "r"(sa));
                unsigned sl = smem_u32(&sAl[(wm + mt*16 + arow_l) * SPAD + acol]);
                asm volatile("ldmatrix.sync.aligned.m8n8.x4.shared.b16 {%0,%1,%2,%3}, [%4];\n"
                    : "=r"(Al[mt][0]), "=r"(Al[mt][1]), "=r"(Al[mt][2]), "=r"(Al[mt][3]) : "r"(sl));
            }
#pragma unroll
            for (int p = 0; p < 2; p++) {
                unsigned sb = smem_u32(&sBh[(wn + p*16 + brow_l) * SPAD + bcol]);
                unsigned q0, q1, q2, q3;
                asm volatile("ldmatrix.sync.aligned.m8n8.x4.shared.b16 {%0,%1,%2,%3}, [%4];\n"
                    : "=r"(q0), "=r"(q1), "=r"(q2), "=r"(q3) : "r"(sb));
                Bh[p*2][0] = q0; Bh[p*2][1] = q1; Bh[p*2+1][0] = q2; Bh[p*2+1][1] = q3;
                unsigned sbl = smem_u32(&sBl[(wn + p*16 + brow_l) * SPAD + bcol]);
                asm volatile("ldmatrix.sync.aligned.m8n8.x4.shared.b16 {%0,%1,%2,%3}, [%4];\n"
                    : "=r"(q0), "=r"(q1), "=r"(q2), "=r"(q3) : "r"(sbl));
                Bl[p*2][0] = q0; Bl[p*2][1] = q1; Bl[p*2+1][0] = q2; Bl[p*2+1][1] = q3;
            }
#pragma unroll
            for (int mt = 0; mt < 4; mt++)
#pragma unroll
                for (int nt = 0; nt < 4; nt++) {
                    MMA_BF16(c[mt][nt], Ah[mt], Bh[nt]);
                    MMA_BF16(c[mt][nt], Ah[mt], Bl[nt]);
                    MMA_BF16(c[mt][nt], Al[mt], Bh[nt]);
                }
        }

        if (it + 1 < niter) {
            if (it + 2 < niter) { CP_WAIT(1); } else { CP_WAIT(0); }
            __syncthreads();
        }
    }

    // epilogue
    float sc = scalarLog ? expf(*scalarLog) : 1.0f;
    int g  = lane >> 2;
    int t2 = (lane & 3) * 2;
#pragma unroll
    for (int mt = 0; mt < 4; mt++) {
#pragma unroll
        for (int nt = 0; nt < 4; nt++) {
            int row = bm + wm + mt*16 + g;
            int col = bn + wn + nt*8 + t2;
            float cs0 = colScale ? colScale[col]   : 1.0f;
            float cs1 = colScale ? colScale[col+1] : 1.0f;
            float v0 = c[mt][nt][0] * sc * cs0;
            float v1 = c[mt][nt][1] * sc * cs1;
            float v2 = c[mt][nt][2] * sc * cs0;
            float v3 = c[mt][nt][3] * sc * cs1;
            float* p0 = C + (size_t)row * N + col;
            float* p1 = C + (size_t)(row + 8) * N + col;
            if (accumulate) {
                p0[0] += v0; p0[1] += v1;
                p1[0] += v2; p1[1] += v3;
            } else {
                float2 a; a.x = v0; a.y = v1; *(float2*)p0 = a;
                float2 b; b.x = v2; b.y = v3; *(float2*)p1 = b;
            }
        }
    }
}

// ---------------- per-head normalize + MiPE rotate (q,k,v) + g_hat ----------------
__global__ void normrot_kernel(float* __restrict__ q, float* __restrict__ k,
                               float* __restrict__ v, float* __restrict__ g,
                               const float* __restrict__ sw) {
    int gwarp = (blockIdx.x * blockDim.x + threadIdx.x) >> 5;
    int lane = threadIdx.x & 31;
    int h = gwarp & (NH - 1);
    int m = gwarp >> 4;
    int t = m & (SEQ - 1);
    size_t base = (size_t)m * DE + h * DK + 2 * lane;

    float2 qv = *(float2*)(q + base);
    float2 kv = *(float2*)(k + base);
    float2 vv = *(float2*)(v + base);
    float2 gv = *(float2*)(g + base);

    float sq = wredsum(qv.x * qv.x + qv.y * qv.y);
    float sk = wredsum(kv.x * kv.x + kv.y * kv.y);
    float sv = wredsum(vv.x * vv.x + vv.y * vv.y);
    float iq = 1.0f / fmaxf(sqrtf(sq), 1e-12f);
    float ik = 1.0f / fmaxf(sqrtf(sk), 1e-12f);
    float iv = 1.0f / fmaxf(sqrtf(sv), 1e-12f);
    qv.x *= iq; qv.y *= iq;
    kv.x *= ik; kv.y *= ik;
    vv.x *= iv; vv.y *= iv;

    float w = expf(sw[h]) + 1.0f;
    float phi = (w < 128.0f) ? 0.5f * (cosf(PI_F * w / 128.0f) + 1.0f) : 0.0f;
    float ang = (float)t * (phi / w);
    float cc = cosf(ang), ss = sinf(ang);
    if (lane == 0) {
        float q0 = qv.x, q1 = qv.y;
        qv.x = q0 * cc - q1 * ss; qv.y = q0 * ss + q1 * cc;
        float k0 = kv.x, k1 = kv.y;
        kv.x = k0 * cc - k1 * ss; kv.y = k0 * ss + k1 * cc;
    }

    float s0 = gv.x / (1.0f + expf(-gv.x));
    float s1 = gv.y / (1.0f + expf(-gv.y));
    gv.x = tanhf(s0); gv.y = tanhf(s1);

    *(float2*)(q + base) = qv;
    *(float2*)(k + base) = kv;
    *(float2*)(v + base) = vv;
    *(float2*)(g + base) = gv;
}

// ---------------- windowed attention + epilogue ----------------
__global__ void attn_kernel(const float* __restrict__ q, const float* __restrict__ k,
                            const float* __restrict__ v, const float* __restrict__ g,
                            const float* __restrict__ sw, const float* __restrict__ sr,
                            const float* __restrict__ sO, float* __restrict__ hh) {
    int gwarp = (blockIdx.x * blockDim.x + threadIdx.x) >> 5;
    int lane = threadIdx.x & 31;
    int h = gwarp & (NH - 1);
    int m = gwarp >> 4;
    int t = m & (SEQ - 1);

    float w  = expf(sw[h]) + 1.0f;
    float r  = expf(sr[h]) + 1.0f;
    float es = expf(sO[h]);

    size_t base = (size_t)m * DE + h * DK + 2 * lane;
    float2 qv = *(const float2*)(q + base);

    float acc0 = 0.f, acc1 = 0.f;
    int lb = (int)ceilf(w) - 1;
    if (lb > t) lb = t;

    for (int s = t - lb; s <= t; ++s) {
        float rel = (float)(s - t);
        if (-rel >= w) continue;
        size_t kb = (size_t)(m - t + s) * DE + h * DK + 2 * lane;
        float2 kv = *(const float2*)(k + kb);
        float sim = wredsum(qv.x * kv.x + qv.y * kv.y);
        float mask = 0.5f * (cosf(PI_F * rel / w) + 1.0f);
        float tmp = fmaxf(1.0f - r * (1.0f - sim), 0.0f);
        float rho = tmp * tmp * mask;
        float2 vv = *(const float2*)(v + kb);
        acc0 += rho * vv.x;
        acc1 += rho * vv.y;
    }

    float hn2 = wredsum(acc0 * acc0 + acc1 * acc1);
    float hn = fmaxf(sqrtf(hn2), 1e-8f);
    float us = tanhf(hn) / hn;

    float2 gv = *(const float2*)(g + base);
    float2 o;
    o.x = acc0 * us * gv.x * es;
    o.y = acc1 * us * gv.y * es;
    *(float2*)(hh + base) = o;
}

// ---------------- launch ----------------
extern "C" void kernel_launch(void* const* d_in, const int* in_sizes, int n_in,
                              void* d_out, int out_size) {
    const int*   ids   = (const int*)d_in[0];
    const float* embed = (const float*)d_in[1];
    const float* sE    = (const float*)d_in[2];
    const float* sF    = (const float*)d_in[3];
    const float* Wq    = (const float*)d_in[4];
    const float* Wk    = (const float*)d_in[5];
    const float* Wv    = (const float*)d_in[6];
    const float* Wg    = (const float*)d_in[7];
    const float* Wo    = (const float*)d_in[8];
    const float* sw    = (const float*)d_in[9];
    const float* sr    = (const float*)d_in[10];
    const float* sO    = (const float*)d_in[11];
    float* out = (float*)d_out;

    cudaFuncSetAttribute(gemm_split, cudaFuncAttributeMaxDynamicSharedMemorySize, SMEM_GEMM);

    float *x, *qb, *kb, *vb, *gb, *hh, *rn;
    cudaGetSymbolAddress((void**)&x,  d_x);
    cudaGetSymbolAddress((void**)&qb, d_qb);
    cudaGetSymbolAddress((void**)&kb, d_kb);
    cudaGetSymbolAddress((void**)&vb, d_vb);
    cudaGetSymbolAddress((void**)&gb, d_gb);
    cudaGetSymbolAddress((void**)&hh, d_hh);
    cudaGetSymbolAddress((void**)&rn, d_rnorm);
    __nv_bfloat16 *ehi, *elo, *whi, *wlo, *xhi, *xlo, *hhi, *hlo;
    cudaGetSymbolAddress((void**)&ehi, d_ehi);
    cudaGetSymbolAddress((void**)&elo, d_elo);
    cudaGetSymbolAddress((void**)&whi, d_whi);
    cudaGetSymbolAddress((void**)&wlo, d_wlo);
    cudaGetSymbolAddress((void**)&xhi, d_xhi);
    cudaGetSymbolAddress((void**)&xlo, d_xlo);
    cudaGetSymbolAddress((void**)&hhi, d_hhi);
    cudaGetSymbolAddress((void**)&hlo, d_hlo);

    const size_t WSTRIDE = (size_t)NL * DE * DE;

    rnorm_kernel<<<VOCAB, 256>>>(embed, rn);
    embed_kernel<<<MTOT, 256>>>(ids, embed, rn, sE, x);

    conv_kernel<<<(VOCAB*DE/4 + 255)/256, 256>>>(embed, ehi, elo, VOCAB*DE/4);
    conv_kernel<<<(int)(WSTRIDE/4/256), 256>>>(Wq, whi + 0*WSTRIDE, wlo + 0*WSTRIDE, (int)(WSTRIDE/4));
    conv_kernel<<<(int)(WSTRIDE/4/256), 256>>>(Wk, whi + 1*WSTRIDE, wlo + 1*WSTRIDE, (int)(WSTRIDE/4));
    conv_kernel<<<(int)(WSTRIDE/4/256), 256>>>(Wv, whi + 2*WSTRIDE, wlo + 2*WSTRIDE, (int)(WSTRIDE/4));
    conv_kernel<<<(int)(WSTRIDE/4/256), 256>>>(Wg, whi + 3*WSTRIDE, wlo + 3*WSTRIDE, (int)(WSTRIDE/4));
    conv_kernel<<<(int)(WSTRIDE/4/256), 256>>>(Wo, whi + 4*WSTRIDE, wlo + 4*WSTRIDE, (int)(WSTRIDE/4));

    dim3 gproj(DE / BN, MTOT / BM);          // (8, 32)
    int warps_total = MTOT * NH;
    int nblk = (warps_total * 32) / 256;

    for (int l = 0; l < NL; ++l) {
        size_t lo_off = (size_t)l * DE * DE;
        const __nv_bfloat16* wqh = whi + 0*WSTRIDE + lo_off; const __nv_bfloat16* wql = wlo + 0*WSTRIDE + lo_off;
        const __nv_bfloat16* wkh = whi + 1*WSTRIDE + lo_off; const __nv_bfloat16* wkl = wlo + 1*WSTRIDE + lo_off;
        const __nv_bfloat16* wvh = whi + 2*WSTRIDE + lo_off; const __nv_bfloat16* wvl = wlo + 2*WSTRIDE + lo_off;
        const __nv_bfloat16* wgh = whi + 3*WSTRIDE + lo_off; const __nv_bfloat16* wgl = wlo + 3*WSTRIDE + lo_off;
        const __nv_bfloat16* woh = whi + 4*WSTRIDE + lo_off; const __nv_bfloat16* wol = wlo + 4*WSTRIDE + lo_off;
        const float* swl = sw + l * NH;
        const float* srl = sr + l * NH;
        const float* sOl = sO + l * NH;

        conv_kernel<<<MTOT*DE/4/256, 256>>>(x, xhi, xlo, MTOT*DE/4);

        gemm_split<<<gproj, 256, SMEM_GEMM>>>(xhi, xlo, wqh, wql, qb, MTOT, DE, DE, nullptr, nullptr, 0);
        gemm_split<<<gproj, 256, SMEM_GEMM>>>(xhi, xlo, wkh, wkl, kb, MTOT, DE, DE, nullptr, nullptr, 0);
        gemm_split<<<gproj, 256, SMEM_GEMM>>>(xhi, xlo, wvh, wvl, vb, MTOT, DE, DE, nullptr, nullptr, 0);
        gemm_split<<<gproj, 256, SMEM_GEMM>>>(xhi, xlo, wgh, wgl, gb, MTOT, DE, DE, nullptr, nullptr, 0);

        normrot_kernel<<<nblk, 256>>>(qb, kb, vb, gb, swl);
        attn_kernel<<<nblk, 256>>>(qb, kb, vb, gb, swl, srl, sOl, hh);

        conv_kernel<<<MTOT*DE/4/256, 256>>>(hh, hhi, hlo, MTOT*DE/4);
        gemm_split<<<gproj, 256, SMEM_GEMM>>>(hhi, hlo, woh, wol, x, MTOT, DE, DE, nullptr, nullptr, 1);
    }

    conv_kernel<<<MTOT*DE/4/256, 256>>>(x, xhi, xlo, MTOT*DE/4);
    dim3 gfin(VOCAB / BN, MTOT / BM);        // (250, 32)
    gemm_split<<<gfin, 256, SMEM_GEMM>>>(xhi, xlo, ehi, elo, out, MTOT, VOCAB, DE, rn, sF, 0);
}

// round 6
// speedup vs baseline: 4.0121x; 1.5484x over previous
#include <cuda_runtime.h>
#include <cuda_fp16.h>
#include <math.h>
#include <stdint.h>

#define BATCH 2
#define SEQ   2048
#define MTOT  (BATCH*SEQ)      // 4096
#define DE    1024
#define NH    16
#define DK    64
#define VOCAB 32000
#define NL    4
#define QS    (4*DE)           // fused qkvg row stride
#define PI_F  3.14159265358979323846f

#define BM 128
#define BN 128
#define BK 32
#define SPAD 40                     // fp16 elems per smem row (80B)
#define PLANE_BYTES (128*SPAD*2)    // 10240
#define STAGE_BYTES (3*PLANE_BYTES) // 30720 (A, Bhi, Blo)
#define NSTAGE 3
#define SMEM_GEMM (NSTAGE*STAGE_BYTES) // 92160

// ---------------- scratch (static device globals; no allocation) ----------------
__device__ float d_rnorm[VOCAB];
__device__ float d_x   [MTOT*DE];
__device__ float d_qkvg[(size_t)MTOT*QS];
__device__ __half d_xh [MTOT*DE];
__device__ __half d_hhh[MTOT*DE];
__device__ __half d_ehi[(size_t)VOCAB*DE];
__device__ __half d_elo[(size_t)VOCAB*DE];
__device__ __half d_whi[(size_t)5*NL*DE*DE];   // [l][4DE,DE] fused qkvg, then [l][DE,DE] wo
__device__ __half d_wlo[(size_t)5*NL*DE*DE];

__device__ __forceinline__ float wredsum(float x) {
#pragma unroll
    for (int o = 16; o > 0; o >>= 1) x += __shfl_xor_sync(0xFFFFFFFFu, x, o);
    return x;
}
__device__ __forceinline__ unsigned smem_u32(const void* p) {
    return (unsigned)__cvta_generic_to_shared(p);
}

#define CP16(dst_u32, src_ptr) \
    asm volatile("cp.async.cg.shared.global [%0], [%1], 16;" :: "r"(dst_u32), "l"(src_ptr))
#define CP_COMMIT() asm volatile("cp.async.commit_group;" ::: "memory")
#define CP_WAIT(N)  asm volatile("cp.async.wait_group %0;" :: "n"(N) : "memory")

// ---------------- reciprocal row norms of embed ----------------
__global__ void rnorm_kernel(const float* __restrict__ embed, float* __restrict__ rnorm) {
    int v = blockIdx.x;
    const float* row = embed + (size_t)v * DE;
    float s = 0.f;
    for (int i = threadIdx.x; i < DE; i += 256) { float e = row[i]; s += e * e; }
    __shared__ float sh[256];
    sh[threadIdx.x] = s; __syncthreads();
    for (int o = 128; o > 0; o >>= 1) {
        if (threadIdx.x < o) sh[threadIdx.x] += sh[threadIdx.x + o];
        __syncthreads();
    }
    if (threadIdx.x == 0) rnorm[v] = 1.0f / fmaxf(sqrtf(sh[0]), 1e-12f);
}

// ---------------- embedding lookup: writes x fp32 and xh fp16 ----------------
__global__ void embed_kernel(const int* __restrict__ ids, const float* __restrict__ embed,
                             const float* __restrict__ rnorm, const float* __restrict__ sE,
                             float* __restrict__ x, __half* __restrict__ xh) {
    int m = blockIdx.x;
    int id = ids[m];
    float sc = rnorm[id] * expf(*sE);
    const float4* row = (const float4*)(embed + (size_t)id * DE);
    int i = threadIdx.x;
    float4 r = row[i];
    r.x *= sc; r.y *= sc; r.z *= sc; r.w *= sc;
    ((float4*)(x + (size_t)m * DE))[i] = r;
    __half2* hp = (__half2*)(xh + (size_t)m * DE);
    hp[2*i]   = __floats2half2_rn(r.x, r.y);
    hp[2*i+1] = __floats2half2_rn(r.z, r.w);
}

// ---------------- fp32 -> fp16 hi/lo split (weights, embed; one-time) ----------------
__global__ void convsplit_kernel(const float* __restrict__ src, __half* __restrict__ hi,
                                 __half* __restrict__ lo, int n4) {
    int i = blockIdx.x * blockDim.x + threadIdx.x;
    if (i >= n4) return;
    float4 f = ((const float4*)src)[i];
    __half h0 = __float2half_rn(f.x);
    __half h1 = __float2half_rn(f.y);
    __half h2 = __float2half_rn(f.z);
    __half h3 = __float2half_rn(f.w);
    __half l0 = __float2half_rn(f.x - __half2float(h0));
    __half l1 = __float2half_rn(f.y - __half2float(h1));
    __half l2 = __float2half_rn(f.z - __half2float(h2));
    __half l3 = __float2half_rn(f.w - __half2float(h3));
    __half2* H = (__half2*)hi;
    __half2* L = (__half2*)lo;
    __half2 p;
    p.x = h0; p.y = h1; H[2*i]   = p;
    p.x = h2; p.y = h3; H[2*i+1] = p;
    p.x = l0; p.y = l1; L[2*i]   = p;
    p.x = l2; p.y = l3; L[2*i+1] = p;
}

// ---------------- fp16 split-B tensor-core NT GEMM, cp.async 3-stage ----------------
// C[m,n] = sum_k A[m,k] * (Bhi[n,k]+Blo[n,k]); fp32 accum.
#define MMA_F16(C, A, B)                                                       \
    asm volatile(                                                              \
        "mma.sync.aligned.m16n8k16.row.col.f32.f16.f16.f32 "                   \
        "{%0,%1,%2,%3}, {%4,%5,%6,%7}, {%8,%9}, {%0,%1,%2,%3};\n"              \
        : "+f"((C)[0]), "+f"((C)[1]), "+f"((C)[2]), "+f"((C)[3])               \
        : "r"((A)[0]), "r"((A)[1]), "r"((A)[2]), "r"((A)[3]),                  \
          "r"((B)[0]), "r"((B)[1]))

__global__ __launch_bounds__(256) void gemm_f16(
    const __half* __restrict__ A,
    const __half* __restrict__ Bhi, const __half* __restrict__ Blo,
    float* __restrict__ C, int M, int N, int K,
    const float* __restrict__ colScale, const float* __restrict__ scalarLog,
    int accumulate, __half* __restrict__ Chalf)
{
    extern __shared__ __align__(128) char smem[];
    uint32_t sbase = smem_u32(smem);

    int tid  = threadIdx.x;
    int lane = tid & 31;
    int warp = tid >> 5;
    int wm = (warp >> 2) * 64;
    int wn = (warp & 3) * 32;
    int bm = blockIdx.y * BM;
    int bn = blockIdx.x * BN;

    int r0  = tid >> 2;            // 0..63
    int c16 = tid & 3;             // 16B chunk
    const char* gA0  = (const char*)(A   + (size_t)(bm + r0     ) * K + c16 * 8);
    const char* gA1  = (const char*)(A   + (size_t)(bm + r0 + 64) * K + c16 * 8);
    const char* gB0h = (const char*)(Bhi + (size_t)(bn + r0     ) * K + c16 * 8);
    const char* gB1h = (const char*)(Bhi + (size_t)(bn + r0 + 64) * K + c16 * 8);
    const char* gB0l = (const char*)(Blo + (size_t)(bn + r0     ) * K + c16 * 8);
    const char* gB1l = (const char*)(Blo + (size_t)(bn + r0 + 64) * K + c16 * 8);
    uint32_t s0 = r0 * (SPAD*2) + c16 * 16;
    uint32_t s1 = (r0 + 64) * (SPAD*2) + c16 * 16;

#define PREFETCH(st, k0)                                                       \
    {                                                                          \
        uint32_t sd = sbase + (st) * STAGE_BYTES;                              \
        size_t gk = (size_t)(k0) * 2;                                          \
        CP16(sd + 0*PLANE_BYTES + s0, gA0  + gk);                              \
        CP16(sd + 0*PLANE_BYTES + s1, gA1  + gk);                              \
        CP16(sd + 1*PLANE_BYTES + s0, gB0h + gk);                              \
        CP16(sd + 1*PLANE_BYTES + s1, gB1h + gk);                              \
        CP16(sd + 2*PLANE_BYTES + s0, gB0l + gk);                              \
        CP16(sd + 2*PLANE_BYTES + s1, gB1l + gk);                              \
        CP_COMMIT();                                                           \
    }

    float c[4][4][4];
#pragma unroll
    for (int i = 0; i < 4; i++)
#pragma unroll
        for (int j = 0; j < 4; j++)
#pragma unroll
            for (int q = 0; q < 4; q++) c[i][j][q] = 0.f;

    int arow_l = lane & 15;
    int acol_l = (lane >> 4) << 3;
    int brow_l = (lane & 7) + ((lane >> 4) << 3);
    int bcol_l = ((lane >> 3) & 1) << 3;

    int niter = K / BK;
    PREFETCH(0, 0);
    if (niter > 1) PREFETCH(1, BK);
    CP_WAIT(1);
    __syncthreads();

    for (int it = 0; it < niter; ++it) {
        int st = it % NSTAGE;
        if (it + 2 < niter) PREFETCH((it + 2) % NSTAGE, (it + 2) * BK);

        const __half* sA  = (const __half*)(smem + st*STAGE_BYTES + 0*PLANE_BYTES);
        const __half* sBh = (const __half*)(smem + st*STAGE_BYTES + 1*PLANE_BYTES);
        const __half* sBl = (const __half*)(smem + st*STAGE_BYTES + 2*PLANE_BYTES);

#pragma unroll
        for (int ks = 0; ks < 2; ks++) {
            unsigned Af[4][4], Bh[4][2], Bl[4][2];
            int acol = ks * 16 + acol_l;
            int bcol = ks * 16 + bcol_l;
#pragma unroll
            for (int mt = 0; mt < 4; mt++) {
                unsigned sa = smem_u32(&sA[(wm + mt*16 + arow_l) * SPAD + acol]);
                asm volatile("ldmatrix.sync.aligned.m8n8.x4.shared.b16 {%0,%1,%2,%3}, [%4];\n"
                    : "=r"(Af[mt][0]), "=r"(Af[mt][1]), "=r"(Af[mt][2]), "=r"(Af[mt][3]) : "r"(sa));
            }
#pragma unroll
            for (int p = 0; p < 2; p++) {
                unsigned sb = smem_u32(&sBh[(wn + p*16 + brow_l) * SPAD + bcol]);
                unsigned q0, q1, q2, q3;
                asm volatile("ldmatrix.sync.aligned.m8n8.x4.shared.b16 {%0,%1,%2,%3}, [%4];\n"
                    : "=r"(q0), "=r"(q1), "=r"(q2), "=r"(q3) : "r"(sb));
                Bh[p*2][0] = q0; Bh[p*2][1] = q1; Bh[p*2+1][0] = q2; Bh[p*2+1][1] = q3;
                unsigned sbl = smem_u32(&sBl[(wn + p*16 + brow_l) * SPAD + bcol]);
                asm volatile("ldmatrix.sync.aligned.m8n8.x4.shared.b16 {%0,%1,%2,%3}, [%4];\n"
                    : "=r"(q0), "=r"(q1), "=r"(q2), "=r"(q3) : "r"(sbl));
                Bl[p*2][0] = q0; Bl[p*2][1] = q1; Bl[p*2+1][0] = q2; Bl[p*2+1][1] = q3;
            }
#pragma unroll
            for (int mt = 0; mt < 4; mt++)
#pragma unroll
                for (int nt = 0; nt < 4; nt++) {
                    MMA_F16(c[mt][nt], Af[mt], Bh[nt]);
                    MMA_F16(c[mt][nt], Af[mt], Bl[nt]);
                }
        }

        if (it + 1 < niter) {
            if (it + 2 < niter) { CP_WAIT(1); } else { CP_WAIT(0); }
            __syncthreads();
        }
    }

    // epilogue
    float sc = scalarLog ? expf(*scalarLog) : 1.0f;
    int g  = lane >> 2;
    int t2 = (lane & 3) * 2;
#pragma unroll
    for (int mt = 0; mt < 4; mt++) {
#pragma unroll
        for (int nt = 0; nt < 4; nt++) {
            int row = bm + wm + mt*16 + g;
            int col = bn + wn + nt*8 + t2;
            float cs0 = colScale ? colScale[col]   : 1.0f;
            float cs1 = colScale ? colScale[col+1] : 1.0f;
            float v0 = c[mt][nt][0] * sc * cs0;
            float v1 = c[mt][nt][1] * sc * cs1;
            float v2 = c[mt][nt][2] * sc * cs0;
            float v3 = c[mt][nt][3] * sc * cs1;
            float* p0 = C + (size_t)row * N + col;
            float* p1 = C + (size_t)(row + 8) * N + col;
            if (accumulate) {
                v0 += p0[0]; v1 += p0[1];
                v2 += p1[0]; v3 += p1[1];
            }
            float2 a; a.x = v0; a.y = v1; *(float2*)p0 = a;
            float2 b; b.x = v2; b.y = v3; *(float2*)p1 = b;
            if (Chalf) {
                *(__half2*)(Chalf + (size_t)row * N + col)       = __floats2half2_rn(v0, v1);
                *(__half2*)(Chalf + (size_t)(row + 8) * N + col) = __floats2half2_rn(v2, v3);
            }
        }
    }
}

// ---------------- per-head normalize + MiPE rotate + g_hat (fused qkvg buffer) ----------------
__global__ void normrot_kernel(float* __restrict__ qkvg, const float* __restrict__ sw) {
    int gwarp = (blockIdx.x * blockDim.x + threadIdx.x) >> 5;
    int lane = threadIdx.x & 31;
    int h = gwarp & (NH - 1);
    int m = gwarp >> 4;
    int t = m & (SEQ - 1);
    size_t base = (size_t)m * QS + h * DK + 2 * lane;

    float2 qv = *(float2*)(qkvg + base);
    float2 kv = *(float2*)(qkvg + base + DE);
    float2 vv = *(float2*)(qkvg + base + 2*DE);
    float2 gv = *(float2*)(qkvg + base + 3*DE);

    float sq = wredsum(qv.x * qv.x + qv.y * qv.y);
    float sk = wredsum(kv.x * kv.x + kv.y * kv.y);
    float sv = wredsum(vv.x * vv.x + vv.y * vv.y);
    float iq = 1.0f / fmaxf(sqrtf(sq), 1e-12f);
    float ik = 1.0f / fmaxf(sqrtf(sk), 1e-12f);
    float iv = 1.0f / fmaxf(sqrtf(sv), 1e-12f);
    qv.x *= iq; qv.y *= iq;
    kv.x *= ik; kv.y *= ik;
    vv.x *= iv; vv.y *= iv;

    float w = expf(sw[h]) + 1.0f;
    float phi = (w < 128.0f) ? 0.5f * (cosf(PI_F * w / 128.0f) + 1.0f) : 0.0f;
    float ang = (float)t * (phi / w);
    float cc = cosf(ang), ss = sinf(ang);
    if (lane == 0) {
        float q0 = qv.x, q1 = qv.y;
        qv.x = q0 * cc - q1 * ss; qv.y = q0 * ss + q1 * cc;
        float k0 = kv.x, k1 = kv.y;
        kv.x = k0 * cc - k1 * ss; kv.y = k0 * ss + k1 * cc;
    }

    float s0 = gv.x / (1.0f + expf(-gv.x));
    float s1 = gv.y / (1.0f + expf(-gv.y));
    gv.x = tanhf(s0); gv.y = tanhf(s1);

    *(float2*)(qkvg + base)        = qv;
    *(float2*)(qkvg + base + DE)   = kv;
    *(float2*)(qkvg + base + 2*DE) = vv;
    *(float2*)(qkvg + base + 3*DE) = gv;
}

// ---------------- windowed attention + epilogue; writes hh directly as fp16 ----------------
__global__ void attn_kernel(const float* __restrict__ qkvg,
                            const float* __restrict__ sw, const float* __restrict__ sr,
                            const float* __restrict__ sO, __half* __restrict__ hhh) {
    int gwarp = (blockIdx.x * blockDim.x + threadIdx.x) >> 5;
    int lane = threadIdx.x & 31;
    int h = gwarp & (NH - 1);
    int m = gwarp >> 4;
    int t = m & (SEQ - 1);

    float w  = expf(sw[h]) + 1.0f;
    float r  = expf(sr[h]) + 1.0f;
    float es = expf(sO[h]);

    size_t base = (size_t)m * QS + h * DK + 2 * lane;
    float2 qv = *(const float2*)(qkvg + base);

    float acc0 = 0.f, acc1 = 0.f;
    int lb = (int)ceilf(w) - 1;
    if (lb > t) lb = t;

    for (int s = t - lb; s <= t; ++s) {
        float rel = (float)(s - t);
        if (-rel >= w) continue;
        size_t kb = (size_t)(m - t + s) * QS + h * DK + 2 * lane;
        float2 kv = *(const float2*)(qkvg + kb + DE);
        float sim = wredsum(qv.x * kv.x + qv.y * kv.y);
        float mask = 0.5f * (cosf(PI_F * rel / w) + 1.0f);
        float tmp = fmaxf(1.0f - r * (1.0f - sim), 0.0f);
        float rho = tmp * tmp * mask;
        float2 vv = *(const float2*)(qkvg + kb + 2*DE);
        acc0 += rho * vv.x;
        acc1 += rho * vv.y;
    }

    float hn2 = wredsum(acc0 * acc0 + acc1 * acc1);
    float hn = fmaxf(sqrtf(hn2), 1e-8f);
    float us = tanhf(hn) / hn;

    float2 gv = *(const float2*)(qkvg + base + 3*DE);
    float o0 = acc0 * us * gv.x * es;
    float o1 = acc1 * us * gv.y * es;
    size_t ob = (size_t)m * DE + h * DK + 2 * lane;
    *(__half2*)(hhh + ob) = __floats2half2_rn(o0, o1);
}

// ---------------- launch ----------------
extern "C" void kernel_launch(void* const* d_in, const int* in_sizes, int n_in,
                              void* d_out, int out_size) {
    const int*   ids   = (const int*)d_in[0];
    const float* embed = (const float*)d_in[1];
    const float* sE    = (const float*)d_in[2];
    const float* sF    = (const float*)d_in[3];
    const float* Wq    = (const float*)d_in[4];
    const float* Wk    = (const float*)d_in[5];
    const float* Wv    = (const float*)d_in[6];
    const float* Wg    = (const float*)d_in[7];
    const float* Wo    = (const float*)d_in[8];
    const float* sw    = (const float*)d_in[9];
    const float* sr    = (const float*)d_in[10];
    const float* sO    = (const float*)d_in[11];
    float* out = (float*)d_out;

    cudaFuncSetAttribute(gemm_f16, cudaFuncAttributeMaxDynamicSharedMemorySize, SMEM_GEMM);

    float *x, *qkvg, *rn;
    cudaGetSymbolAddress((void**)&x,    d_x);
    cudaGetSymbolAddress((void**)&qkvg, d_qkvg);
    cudaGetSymbolAddress((void**)&rn,   d_rnorm);
    __half *xh, *hhh, *ehi, *elo, *whi, *wlo;
    cudaGetSymbolAddress((void**)&xh,  d_xh);
    cudaGetSymbolAddress((void**)&hhh, d_hhh);
    cudaGetSymbolAddress((void**)&ehi, d_ehi);
    cudaGetSymbolAddress((void**)&elo, d_elo);
    cudaGetSymbolAddress((void**)&whi, d_whi);
    cudaGetSymbolAddress((void**)&wlo, d_wlo);

    const size_t LW = (size_t)DE * DE;           // one weight matrix
    const size_t WO_BASE = (size_t)NL * 4 * LW;  // wo planes start here

    rnorm_kernel<<<VOCAB, 256>>>(embed, rn);
    embed_kernel<<<MTOT, 256>>>(ids, embed, rn, sE, x, xh);

    // one-time conversions: embed table + packed weights
    convsplit_kernel<<<(int)((size_t)VOCAB*DE/4/256), 256>>>(embed, ehi, elo, (int)((size_t)VOCAB*DE/4));
    int wgrid = (int)(LW/4/256);
    for (int l = 0; l < NL; ++l) {
        size_t fb = (size_t)l * 4 * LW;   // fused qkvg block for layer l
        convsplit_kernel<<<wgrid, 256>>>(Wq + l*LW, whi + fb + 0*LW, wlo + fb + 0*LW, (int)(LW/4));
        convsplit_kernel<<<wgrid, 256>>>(Wk + l*LW, whi + fb + 1*LW, wlo + fb + 1*LW, (int)(LW/4));
        convsplit_kernel<<<wgrid, 256>>>(Wv + l*LW, whi + fb + 2*LW, wlo + fb + 2*LW, (int)(LW/4));
        convsplit_kernel<<<wgrid, 256>>>(Wg + l*LW, whi + fb + 3*LW, wlo + fb + 3*LW, (int)(LW/4));
        convsplit_kernel<<<wgrid, 256>>>(Wo + l*LW, whi + WO_BASE + l*LW, wlo + WO_BASE + l*LW, (int)(LW/4));
    }

    dim3 gfused(QS / BN, MTOT / BM);   // (32, 32)
    dim3 gwo(DE / BN, MTOT / BM);      // (8, 32)
    int warps_total = MTOT * NH;
    int nblk = (warps_total * 32) / 256;

    for (int l = 0; l < NL; ++l) {
        size_t fb = (size_t)l * 4 * LW;
        const float* swl = sw + l * NH;
        const float* srl = sr + l * NH;
        const float* sOl = sO + l * NH;

        gemm_f16<<<gfused, 256, SMEM_GEMM>>>(xh, whi + fb, wlo + fb, qkvg,
                                             MTOT, QS, DE, nullptr, nullptr, 0, nullptr);
        normrot_kernel<<<nblk, 256>>>(qkvg, swl);
        attn_kernel<<<nblk, 256>>>(qkvg, swl, srl, sOl, hhh);
        gemm_f16<<<gwo, 256, SMEM_GEMM>>>(hhh, whi + WO_BASE + l*LW, wlo + WO_BASE + l*LW, x,
                                          MTOT, DE, DE, nullptr, nullptr, 1, xh);
    }

    dim3 gfin(VOCAB / BN, MTOT / BM);  // (250, 32)
    gemm_f16<<<gfin, 256, SMEM_GEMM>>>(xh, ehi, elo, out, MTOT, VOCAB, DE, rn, sF, 0, nullptr);
}

// round 7
// speedup vs baseline: 5.2124x; 1.2992x over previous
#include <cuda_runtime.h>
#include <cuda_fp16.h>
#include <math.h>
#include <stdint.h>

#define BATCH 2
#define SEQ   2048
#define MTOT  (BATCH*SEQ)      // 4096
#define DE    1024
#define NH    16
#define DK    64
#define VOCAB 32000
#define NL    4
#define QS    (4*DE)           // fused qkvg row stride
#define PI_F  3.14159265358979323846f

#define BM 128
#define BN 128
#define BK 32
#define SPAD 40                     // fp16 elems per smem row (80B)
#define PLANE_BYTES (128*SPAD*2)    // 10240
#define STAGE_BYTES (2*PLANE_BYTES) // 20480 (A, B)
#define NSTAGE 3
#define SMEM_GEMM (NSTAGE*STAGE_BYTES) // 61440

// ---------------- scratch (static device globals; no allocation) ----------------
__device__ float d_rnorm[VOCAB];
__device__ float d_x   [MTOT*DE];
__device__ float d_qkvg[(size_t)MTOT*QS];
__device__ __half d_xh [MTOT*DE];
__device__ __half d_hhh[MTOT*DE];
__device__ __half d_eh [(size_t)VOCAB*DE];
__device__ __half d_wh [(size_t)5*NL*DE*DE];   // [l][4DE,DE] fused qkvg, then [l][DE,DE] wo

__device__ __forceinline__ float wredsum(float x) {
#pragma unroll
    for (int o = 16; o > 0; o >>= 1) x += __shfl_xor_sync(0xFFFFFFFFu, x, o);
    return x;
}
__device__ __forceinline__ unsigned smem_u32(const void* p) {
    return (unsigned)__cvta_generic_to_shared(p);
}

#define CP16(dst_u32, src_ptr) \
    asm volatile("cp.async.cg.shared.global [%0], [%1], 16;" :: "r"(dst_u32), "l"(src_ptr))
#define CP_COMMIT() asm volatile("cp.async.commit_group;" ::: "memory")
#define CP_WAIT(N)  asm volatile("cp.async.wait_group %0;" :: "n"(N) : "memory")

// ---------------- reciprocal row norms of embed ----------------
__global__ void rnorm_kernel(const float* __restrict__ embed, float* __restrict__ rnorm) {
    int v = blockIdx.x;
    const float* row = embed + (size_t)v * DE;
    float s = 0.f;
    for (int i = threadIdx.x; i < DE; i += 256) { float e = row[i]; s += e * e; }
    __shared__ float sh[256];
    sh[threadIdx.x] = s; __syncthreads();
    for (int o = 128; o > 0; o >>= 1) {
        if (threadIdx.x < o) sh[threadIdx.x] += sh[threadIdx.x + o];
        __syncthreads();
    }
    if (threadIdx.x == 0) rnorm[v] = 1.0f / fmaxf(sqrtf(sh[0]), 1e-12f);
}

// ---------------- embedding lookup: writes x fp32 and xh fp16 ----------------
__global__ void embed_kernel(const int* __restrict__ ids, const float* __restrict__ embed,
                             const float* __restrict__ rnorm, const float* __restrict__ sE,
                             float* __restrict__ x, __half* __restrict__ xh) {
    int m = blockIdx.x;
    int id = ids[m];
    float sc = rnorm[id] * expf(*sE);
    const float4* row = (const float4*)(embed + (size_t)id * DE);
    int i = threadIdx.x;
    float4 r = row[i];
    r.x *= sc; r.y *= sc; r.z *= sc; r.w *= sc;
    ((float4*)(x + (size_t)m * DE))[i] = r;
    __half2* hp = (__half2*)(xh + (size_t)m * DE);
    hp[2*i]   = __floats2half2_rn(r.x, r.y);
    hp[2*i+1] = __floats2half2_rn(r.z, r.w);
}

// ---------------- fp32 -> fp16 (weights, embed; one-time) ----------------
__global__ void conv_kernel(const float* __restrict__ src, __half* __restrict__ dst, int n4) {
    int i = blockIdx.x * blockDim.x + threadIdx.x;
    if (i >= n4) return;
    float4 f = ((const float4*)src)[i];
    __half2* H = (__half2*)dst;
    H[2*i]   = __floats2half2_rn(f.x, f.y);
    H[2*i+1] = __floats2half2_rn(f.z, f.w);
}

// ---------------- fp16 tensor-core NT GEMM, cp.async 3-stage ----------------
// C[m,n] = sum_k A[m,k]*B[n,k]; fp32 accum.
#define MMA_F16(C, A, B)                                                       \
    asm volatile(                                                              \
        "mma.sync.aligned.m16n8k16.row.col.f32.f16.f16.f32 "                   \
        "{%0,%1,%2,%3}, {%4,%5,%6,%7}, {%8,%9}, {%0,%1,%2,%3};\n"              \
        : "+f"((C)[0]), "+f"((C)[1]), "+f"((C)[2]), "+f"((C)[3])               \
        : "r"((A)[0]), "r"((A)[1]), "r"((A)[2]), "r"((A)[3]),                  \
          "r"((B)[0]), "r"((B)[1]))

__global__ __launch_bounds__(256) void gemm_f16(
    const __half* __restrict__ A, const __half* __restrict__ B,
    float* __restrict__ C, int M, int N, int K,
    const float* __restrict__ colScale, const float* __restrict__ scalarLog,
    int accumulate, __half* __restrict__ Chalf)
{
    extern __shared__ __align__(128) char smem[];
    uint32_t sbase = smem_u32(smem);

    int tid  = threadIdx.x;
    int lane = tid & 31;
    int warp = tid >> 5;
    int wm = (warp >> 2) * 64;
    int wn = (warp & 3) * 32;
    int bm = blockIdx.y * BM;
    int bn = blockIdx.x * BN;

    int r0  = tid >> 2;            // 0..63
    int c16 = tid & 3;             // 16B chunk
    const char* gA0 = (const char*)(A + (size_t)(bm + r0     ) * K + c16 * 8);
    const char* gA1 = (const char*)(A + (size_t)(bm + r0 + 64) * K + c16 * 8);
    const char* gB0 = (const char*)(B + (size_t)(bn + r0     ) * K + c16 * 8);
    const char* gB1 = (const char*)(B + (size_t)(bn + r0 + 64) * K + c16 * 8);
    uint32_t s0 = r0 * (SPAD*2) + c16 * 16;
    uint32_t s1 = (r0 + 64) * (SPAD*2) + c16 * 16;

#define PREFETCH(st, k0)                                                       \
    {                                                                          \
        uint32_t sd = sbase + (st) * STAGE_BYTES;                              \
        size_t gk = (size_t)(k0) * 2;                                          \
        CP16(sd + 0*PLANE_BYTES + s0, gA0 + gk);                               \
        CP16(sd + 0*PLANE_BYTES + s1, gA1 + gk);                               \
        CP16(sd + 1*PLANE_BYTES + s0, gB0 + gk);                               \
        CP16(sd + 1*PLANE_BYTES + s1, gB1 + gk);                               \
        CP_COMMIT();                                                           \
    }

    float c[4][4][4];
#pragma unroll
    for (int i = 0; i < 4; i++)
#pragma unroll
        for (int j = 0; j < 4; j++)
#pragma unroll
            for (int q = 0; q < 4; q++) c[i][j][q] = 0.f;

    int arow_l = lane & 15;
    int acol_l = (lane >> 4) << 3;
    int brow_l = (lane & 7) + ((lane >> 4) << 3);
    int bcol_l = ((lane >> 3) & 1) << 3;

    int niter = K / BK;
    PREFETCH(0, 0);
    if (niter > 1) PREFETCH(1, BK);
    CP_WAIT(1);
    __syncthreads();

    for (int it = 0; it < niter; ++it) {
        int st = it % NSTAGE;
        if (it + 2 < niter) PREFETCH((it + 2) % NSTAGE, (it + 2) * BK);

        const __half* sA = (const __half*)(smem + st*STAGE_BYTES + 0*PLANE_BYTES);
        const __half* sB = (const __half*)(smem + st*STAGE_BYTES + 1*PLANE_BYTES);

#pragma unroll
        for (int ks = 0; ks < 2; ks++) {
            unsigned Af[4][4], Bf[4][2];
            int acol = ks * 16 + acol_l;
            int bcol = ks * 16 + bcol_l;
#pragma unroll
            for (int mt = 0; mt < 4; mt++) {
                unsigned sa = smem_u32(&sA[(wm + mt*16 + arow_l) * SPAD + acol]);
                asm volatile("ldmatrix.sync.aligned.m8n8.x4.shared.b16 {%0,%1,%2,%3}, [%4];\n"
                    : "=r"(Af[mt][0]), "=r"(Af[mt][1]), "=r"(Af[mt][2]), "=r"(Af[mt][3]) : "r"(sa));
            }
#pragma unroll
            for (int p = 0; p < 2; p++) {
                unsigned sb = smem_u32(&sB[(wn + p*16 + brow_l) * SPAD + bcol]);
                unsigned q0, q1, q2, q3;
                asm volatile("ldmatrix.sync.aligned.m8n8.x4.shared.b16 {%0,%1,%2,%3}, [%4];\n"
                    : "=r"(q0), "=r"(q1), "=r"(q2), "=r"(q3) : "r"(sb));
                Bf[p*2][0] = q0; Bf[p*2][1] = q1; Bf[p*2+1][0] = q2; Bf[p*2+1][1] = q3;
            }
#pragma unroll
            for (int mt = 0; mt < 4; mt++)
#pragma unroll
                for (int nt = 0; nt < 4; nt++)
                    MMA_F16(c[mt][nt], Af[mt], Bf[nt]);
        }

        if (it + 1 < niter) {
            if (it + 2 < niter) { CP_WAIT(1); } else { CP_WAIT(0); }
            __syncthreads();
        }
    }

    // epilogue
    float sc = scalarLog ? expf(*scalarLog) : 1.0f;
    int g  = lane >> 2;
    int t2 = (lane & 3) * 2;
#pragma unroll
    for (int mt = 0; mt < 4; mt++) {
#pragma unroll
        for (int nt = 0; nt < 4; nt++) {
            int row = bm + wm + mt*16 + g;
            int col = bn + wn + nt*8 + t2;
            float cs0 = colScale ? colScale[col]   : 1.0f;
            float cs1 = colScale ? colScale[col+1] : 1.0f;
            float v0 = c[mt][nt][0] * sc * cs0;
            float v1 = c[mt][nt][1] * sc * cs1;
            float v2 = c[mt][nt][2] * sc * cs0;
            float v3 = c[mt][nt][3] * sc * cs1;
            float* p0 = C + (size_t)row * N + col;
            float* p1 = C + (size_t)(row + 8) * N + col;
            if (accumulate) {
                v0 += p0[0]; v1 += p0[1];
                v2 += p1[0]; v3 += p1[1];
            }
            float2 a; a.x = v0; a.y = v1; *(float2*)p0 = a;
            float2 b; b.x = v2; b.y = v3; *(float2*)p1 = b;
            if (Chalf) {
                *(__half2*)(Chalf + (size_t)row * N + col)       = __floats2half2_rn(v0, v1);
                *(__half2*)(Chalf + (size_t)(row + 8) * N + col) = __floats2half2_rn(v2, v3);
            }
        }
    }
}

// ---------------- per-head normalize + MiPE rotate + g_hat (fused qkvg buffer) ----------------
__global__ void normrot_kernel(float* __restrict__ qkvg, const float* __restrict__ sw) {
    int gwarp = (blockIdx.x * blockDim.x + threadIdx.x) >> 5;
    int lane = threadIdx.x & 31;
    int h = gwarp & (NH - 1);
    int m = gwarp >> 4;
    int t = m & (SEQ - 1);
    size_t base = (size_t)m * QS + h * DK + 2 * lane;

    float2 qv = *(float2*)(qkvg + base);
    float2 kv = *(float2*)(qkvg + base + DE);
    float2 vv = *(float2*)(qkvg + base + 2*DE);
    float2 gv = *(float2*)(qkvg + base + 3*DE);

    float sq = wredsum(qv.x * qv.x + qv.y * qv.y);
    float sk = wredsum(kv.x * kv.x + kv.y * kv.y);
    float sv = wredsum(vv.x * vv.x + vv.y * vv.y);
    float iq = 1.0f / fmaxf(sqrtf(sq), 1e-12f);
    float ik = 1.0f / fmaxf(sqrtf(sk), 1e-12f);
    float iv = 1.0f / fmaxf(sqrtf(sv), 1e-12f);
    qv.x *= iq; qv.y *= iq;
    kv.x *= ik; kv.y *= ik;
    vv.x *= iv; vv.y *= iv;

    float w = expf(sw[h]) + 1.0f;
    float phi = (w < 128.0f) ? 0.5f * (cosf(PI_F * w / 128.0f) + 1.0f) : 0.0f;
    float ang = (float)t * (phi / w);
    float cc = cosf(ang), ss = sinf(ang);
    if (lane == 0) {
        float q0 = qv.x, q1 = qv.y;
        qv.x = q0 * cc - q1 * ss; qv.y = q0 * ss + q1 * cc;
        float k0 = kv.x, k1 = kv.y;
        kv.x = k0 * cc - k1 * ss; kv.y = k0 * ss + k1 * cc;
    }

    float s0 = gv.x / (1.0f + expf(-gv.x));
    float s1 = gv.y / (1.0f + expf(-gv.y));
    gv.x = tanhf(s0); gv.y = tanhf(s1);

    *(float2*)(qkvg + base)        = qv;
    *(float2*)(qkvg + base + DE)   = kv;
    *(float2*)(qkvg + base + 2*DE) = vv;
    *(float2*)(qkvg + base + 3*DE) = gv;
}

// ---------------- windowed attention + epilogue; writes hh directly as fp16 ----------------
__global__ void attn_kernel(const float* __restrict__ qkvg,
                            const float* __restrict__ sw, const float* __restrict__ sr,
                            const float* __restrict__ sO, __half* __restrict__ hhh) {
    int gwarp = (blockIdx.x * blockDim.x + threadIdx.x) >> 5;
    int lane = threadIdx.x & 31;
    int h = gwarp & (NH - 1);
    int m = gwarp >> 4;
    int t = m & (SEQ - 1);

    float w  = expf(sw[h]) + 1.0f;
    float r  = expf(sr[h]) + 1.0f;
    float es = expf(sO[h]);

    size_t base = (size_t)m * QS + h * DK + 2 * lane;
    float2 qv = *(const float2*)(qkvg + base);

    float acc0 = 0.f, acc1 = 0.f;
    int lb = (int)ceilf(w) - 1;
    if (lb > t) lb = t;

    for (int s = t - lb; s <= t; ++s) {
        float rel = (float)(s - t);
        if (-rel >= w) continue;
        size_t kb = (size_t)(m - t + s) * QS + h * DK + 2 * lane;
        float2 kv = *(const float2*)(qkvg + kb + DE);
        float sim = wredsum(qv.x * kv.x + qv.y * kv.y);
        float mask = 0.5f * (cosf(PI_F * rel / w) + 1.0f);
        float tmp = fmaxf(1.0f - r * (1.0f - sim), 0.0f);
        float rho = tmp * tmp * mask;
        float2 vv = *(const float2*)(qkvg + kb + 2*DE);
        acc0 += rho * vv.x;
        acc1 += rho * vv.y;
    }

    float hn2 = wredsum(acc0 * acc0 + acc1 * acc1);
    float hn = fmaxf(sqrtf(hn2), 1e-8f);
    float us = tanhf(hn) / hn;

    float2 gv = *(const float2*)(qkvg + base + 3*DE);
    float o0 = acc0 * us * gv.x * es;
    float o1 = acc1 * us * gv.y * es;
    size_t ob = (size_t)m * DE + h * DK + 2 * lane;
    *(__half2*)(hhh + ob) = __floats2half2_rn(o0, o1);
}

// ---------------- launch ----------------
extern "C" void kernel_launch(void* const* d_in, const int* in_sizes, int n_in,
                              void* d_out, int out_size) {
    const int*   ids   = (const int*)d_in[0];
    const float* embed = (const float*)d_in[1];
    const float* sE    = (const float*)d_in[2];
    const float* sF    = (const float*)d_in[3];
    const float* Wq    = (const float*)d_in[4];
    const float* Wk    = (const float*)d_in[5];
    const float* Wv    = (const float*)d_in[6];
    const float* Wg    = (const float*)d_in[7];
    const float* Wo    = (const float*)d_in[8];
    const float* sw    = (const float*)d_in[9];
    const float* sr    = (const float*)d_in[10];
    const float* sO    = (const float*)d_in[11];
    float* out = (float*)d_out;

    cudaFuncSetAttribute(gemm_f16, cudaFuncAttributeMaxDynamicSharedMemorySize, SMEM_GEMM);

    float *x, *qkvg, *rn;
    cudaGetSymbolAddress((void**)&x,    d_x);
    cudaGetSymbolAddress((void**)&qkvg, d_qkvg);
    cudaGetSymbolAddress((void**)&rn,   d_rnorm);
    __half *xh, *hhh, *eh, *wh;
    cudaGetSymbolAddress((void**)&xh,  d_xh);
    cudaGetSymbolAddress((void**)&hhh, d_hhh);
    cudaGetSymbolAddress((void**)&eh,  d_eh);
    cudaGetSymbolAddress((void**)&wh,  d_wh);

    const size_t LW = (size_t)DE * DE;           // one weight matrix
    const size_t WO_BASE = (size_t)NL * 4 * LW;  // wo planes start here

    rnorm_kernel<<<VOCAB, 256>>>(embed, rn);
    embed_kernel<<<MTOT, 256>>>(ids, embed, rn, sE, x, xh);

    // one-time conversions: embed table + packed weights
    conv_kernel<<<(int)((size_t)VOCAB*DE/4/256), 256>>>(embed, eh, (int)((size_t)VOCAB*DE/4));
    int wgrid = (int)(LW/4/256);
    for (int l = 0; l < NL; ++l) {
        size_t fb = (size_t)l * 4 * LW;   // fused qkvg block for layer l
        conv_kernel<<<wgrid, 256>>>(Wq + l*LW, wh + fb + 0*LW, (int)(LW/4));
        conv_kernel<<<wgrid, 256>>>(Wk + l*LW, wh + fb + 1*LW, (int)(LW/4));
        conv_kernel<<<wgrid, 256>>>(Wv + l*LW, wh + fb + 2*LW, (int)(LW/4));
        conv_kernel<<<wgrid, 256>>>(Wg + l*LW, wh + fb + 3*LW, (int)(LW/4));
        conv_kernel<<<wgrid, 256>>>(Wo + l*LW, wh + WO_BASE + l*LW, (int)(LW/4));
    }

    dim3 gfused(QS / BN, MTOT / BM);   // (32, 32)
    dim3 gwo(DE / BN, MTOT / BM);      // (8, 32)
    int warps_total = MTOT * NH;
    int nblk = (warps_total * 32) / 256;

    for (int l = 0; l < NL; ++l) {
        size_t fb = (size_t)l * 4 * LW;
        const float* swl = sw + l * NH;
        const float* srl = sr + l * NH;
        const float* sOl = sO + l * NH;

        gemm_f16<<<gfused, 256, SMEM_GEMM>>>(xh, wh + fb, qkvg,
                                             MTOT, QS, DE, nullptr, nullptr, 0, nullptr);
        normrot_kernel<<<nblk, 256>>>(qkvg, swl);
        attn_kernel<<<nblk, 256>>>(qkvg, swl, srl, sOl, hhh);
        gemm_f16<<<gwo, 256, SMEM_GEMM>>>(hhh, wh + WO_BASE + l*LW, x,
                                          MTOT, DE, DE, nullptr, nullptr, 1, xh);
    }

    dim3 gfin(VOCAB / BN, MTOT / BM);  // (250, 32)
    gemm_f16<<<gfin, 256, SMEM_GEMM>>>(xh, eh, out, MTOT, VOCAB, DE, rn, sF, 0, nullptr);
}

// round 8
// speedup vs baseline: 5.3455x; 1.0255x over previous
#include <cuda_runtime.h>
#include <cuda_fp16.h>
#include <math.h>
#include <stdint.h>

#define BATCH 2
#define SEQ   2048
#define MTOT  (BATCH*SEQ)      // 4096
#define DE    1024
#define NH    16
#define DK    64
#define VOCAB 32000
#define NL    4
#define QS    (4*DE)           // fused qkvg row stride
#define PI_F  3.14159265358979323846f

#define BM 128
#define BN 128
#define BK 32
#define SPAD 40                     // fp16 elems per smem row (80B)
#define PLANE_BYTES (128*SPAD*2)    // 10240
#define STAGE_BYTES (2*PLANE_BYTES) // 20480 (A, B)
#define NSTAGE 3
#define SMEM_GEMM (NSTAGE*STAGE_BYTES) // 61440

// ---------------- scratch (static device globals; no allocation) ----------------
__device__ float d_rnorm[VOCAB];
__device__ float d_x   [MTOT*DE];
__device__ __half d_qkvg[(size_t)MTOT*QS];
__device__ __half d_xh [MTOT*DE];
__device__ __half d_hhh[MTOT*DE];
__device__ __half d_eh [(size_t)VOCAB*DE];
__device__ __half d_wh [(size_t)5*NL*DE*DE];   // [l][4DE,DE] fused qkvg, then [l][DE,DE] wo

__device__ __forceinline__ float wredsum(float x) {
#pragma unroll
    for (int o = 16; o > 0; o >>= 1) x += __shfl_xor_sync(0xFFFFFFFFu, x, o);
    return x;
}
__device__ __forceinline__ unsigned smem_u32(const void* p) {
    return (unsigned)__cvta_generic_to_shared(p);
}

#define CP16(dst_u32, src_ptr) \
    asm volatile("cp.async.cg.shared.global [%0], [%1], 16;" :: "r"(dst_u32), "l"(src_ptr))
#define CP_COMMIT() asm volatile("cp.async.commit_group;" ::: "memory")
#define CP_WAIT(N)  asm volatile("cp.async.wait_group %0;" :: "n"(N) : "memory")

// ---------------- fused: embed row norm + fp16 conversion (one pass over table) ----------------
__global__ void rnormconv_kernel(const float* __restrict__ embed, float* __restrict__ rnorm,
                                 __half* __restrict__ eh) {
    int v = blockIdx.x;
    const float4* row = (const float4*)(embed + (size_t)v * DE);
    float4 f = row[threadIdx.x];           // 256 threads x 4 floats = 1024
    float s = f.x*f.x + f.y*f.y + f.z*f.z + f.w*f.w;
    __shared__ float sh[256];
    sh[threadIdx.x] = s; __syncthreads();
    for (int o = 128; o > 0; o >>= 1) {
        if (threadIdx.x < o) sh[threadIdx.x] += sh[threadIdx.x + o];
        __syncthreads();
    }
    if (threadIdx.x == 0) rnorm[v] = 1.0f / fmaxf(sqrtf(sh[0]), 1e-12f);
    __half2* H = (__half2*)(eh + (size_t)v * DE);
    H[2*threadIdx.x]   = __floats2half2_rn(f.x, f.y);
    H[2*threadIdx.x+1] = __floats2half2_rn(f.z, f.w);
}

// ---------------- embedding lookup: writes x fp32 and xh fp16 ----------------
__global__ void embed_kernel(const int* __restrict__ ids, const float* __restrict__ embed,
                             const float* __restrict__ rnorm, const float* __restrict__ sE,
                             float* __restrict__ x, __half* __restrict__ xh) {
    int m = blockIdx.x;
    int id = ids[m];
    float sc = rnorm[id] * expf(*sE);
    const float4* row = (const float4*)(embed + (size_t)id * DE);
    int i = threadIdx.x;
    float4 r = row[i];
    r.x *= sc; r.y *= sc; r.z *= sc; r.w *= sc;
    ((float4*)(x + (size_t)m * DE))[i] = r;
    __half2* hp = (__half2*)(xh + (size_t)m * DE);
    hp[2*i]   = __floats2half2_rn(r.x, r.y);
    hp[2*i+1] = __floats2half2_rn(r.z, r.w);
}

// ---------------- fp32 -> fp16 (weights; one-time) ----------------
__global__ void conv_kernel(const float* __restrict__ src, __half* __restrict__ dst, int n4) {
    int i = blockIdx.x * blockDim.x + threadIdx.x;
    if (i >= n4) return;
    float4 f = ((const float4*)src)[i];
    __half2* H = (__half2*)dst;
    H[2*i]   = __floats2half2_rn(f.x, f.y);
    H[2*i+1] = __floats2half2_rn(f.z, f.w);
}

// ---------------- fp16 tensor-core NT GEMM, cp.async 3-stage ----------------
// C[m,n] = sum_k A[m,k]*B[n,k]; fp32 accum. C may be null (fp16-only out via Chalf).
#define MMA_F16(C, A, B)                                                       \
    asm volatile(                                                              \
        "mma.sync.aligned.m16n8k16.row.col.f32.f16.f16.f32 "                   \
        "{%0,%1,%2,%3}, {%4,%5,%6,%7}, {%8,%9}, {%0,%1,%2,%3};\n"              \
        : "+f"((C)[0]), "+f"((C)[1]), "+f"((C)[2]), "+f"((C)[3])               \
        : "r"((A)[0]), "r"((A)[1]), "r"((A)[2]), "r"((A)[3]),                  \
          "r"((B)[0]), "r"((B)[1]))

__global__ __launch_bounds__(256) void gemm_f16(
    const __half* __restrict__ A, const __half* __restrict__ B,
    float* __restrict__ C, int M, int N, int K,
    const float* __restrict__ colScale, const float* __restrict__ scalarLog,
    int accumulate, __half* __restrict__ Chalf)
{
    extern __shared__ __align__(128) char smem[];
    uint32_t sbase = smem_u32(smem);

    int tid  = threadIdx.x;
    int lane = tid & 31;
    int warp = tid >> 5;
    int wm = (warp >> 2) * 64;
    int wn = (warp & 3) * 32;
    int bm = blockIdx.y * BM;
    int bn = blockIdx.x * BN;

    int r0  = tid >> 2;            // 0..63
    int c16 = tid & 3;             // 16B chunk
    const char* gA0 = (const char*)(A + (size_t)(bm + r0     ) * K + c16 * 8);
    const char* gA1 = (const char*)(A + (size_t)(bm + r0 + 64) * K + c16 * 8);
    const char* gB0 = (const char*)(B + (size_t)(bn + r0     ) * K + c16 * 8);
    const char* gB1 = (const char*)(B + (size_t)(bn + r0 + 64) * K + c16 * 8);
    uint32_t s0 = r0 * (SPAD*2) + c16 * 16;
    uint32_t s1 = (r0 + 64) * (SPAD*2) + c16 * 16;

#define PREFETCH(st, k0)                                                       \
    {                                                                          \
        uint32_t sd = sbase + (st) * STAGE_BYTES;                              \
        size_t gk = (size_t)(k0) * 2;                                          \
        CP16(sd + 0*PLANE_BYTES + s0, gA0 + gk);                               \
        CP16(sd + 0*PLANE_BYTES + s1, gA1 + gk);                               \
        CP16(sd + 1*PLANE_BYTES + s0, gB0 + gk);                               \
        CP16(sd + 1*PLANE_BYTES + s1, gB1 + gk);                               \
        CP_COMMIT();                                                           \
    }

    float c[4][4][4];
#pragma unroll
    for (int i = 0; i < 4; i++)
#pragma unroll
        for (int j = 0; j < 4; j++)
#pragma unroll
            for (int q = 0; q < 4; q++) c[i][j][q] = 0.f;

    int arow_l = lane & 15;
    int acol_l = (lane >> 4) << 3;
    int brow_l = (lane & 7) + ((lane >> 4) << 3);
    int bcol_l = ((lane >> 3) & 1) << 3;

    int niter = K / BK;
    PREFETCH(0, 0);
    if (niter > 1) PREFETCH(1, BK);
    CP_WAIT(1);
    __syncthreads();

    for (int it = 0; it < niter; ++it) {
        int st = it % NSTAGE;
        if (it + 2 < niter) PREFETCH((it + 2) % NSTAGE, (it + 2) * BK);

        const __half* sA = (const __half*)(smem + st*STAGE_BYTES + 0*PLANE_BYTES);
        const __half* sB = (const __half*)(smem + st*STAGE_BYTES + 1*PLANE_BYTES);

#pragma unroll
        for (int ks = 0; ks < 2; ks++) {
            unsigned Af[4][4], Bf[4][2];
            int acol = ks * 16 + acol_l;
            int bcol = ks * 16 + bcol_l;
#pragma unroll
            for (int mt = 0; mt < 4; mt++) {
                unsigned sa = smem_u32(&sA[(wm + mt*16 + arow_l) * SPAD + acol]);
                asm volatile("ldmatrix.sync.aligned.m8n8.x4.shared.b16 {%0,%1,%2,%3}, [%4];\n"
                    : "=r"(Af[mt][0]), "=r"(Af[mt][1]), "=r"(Af[mt][2]), "=r"(Af[mt][3]) : "r"(sa));
            }
#pragma unroll
            for (int p = 0; p < 2; p++) {
                unsigned sb = smem_u32(&sB[(wn + p*16 + brow_l) * SPAD + bcol]);
                unsigned q0, q1, q2, q3;
                asm volatile("ldmatrix.sync.aligned.m8n8.x4.shared.b16 {%0,%1,%2,%3}, [%4];\n"
                    : "=r"(q0), "=r"(q1), "=r"(q2), "=r"(q3) : "r"(sb));
                Bf[p*2][0] = q0; Bf[p*2][1] = q1; Bf[p*2+1][0] = q2; Bf[p*2+1][1] = q3;
            }
#pragma unroll
            for (int mt = 0; mt < 4; mt++)
#pragma unroll
                for (int nt = 0; nt < 4; nt++)
                    MMA_F16(c[mt][nt], Af[mt], Bf[nt]);
        }

        if (it + 1 < niter) {
            if (it + 2 < niter) { CP_WAIT(1); } else { CP_WAIT(0); }
            __syncthreads();
        }
    }

    // epilogue
    float sc = scalarLog ? expf(*scalarLog) : 1.0f;
    int g  = lane >> 2;
    int t2 = (lane & 3) * 2;
#pragma unroll
    for (int mt = 0; mt < 4; mt++) {
#pragma unroll
        for (int nt = 0; nt < 4; nt++) {
            int row = bm + wm + mt*16 + g;
            int col = bn + wn + nt*8 + t2;
            float cs0 = colScale ? colScale[col]   : 1.0f;
            float cs1 = colScale ? colScale[col+1] : 1.0f;
            float v0 = c[mt][nt][0] * sc * cs0;
            float v1 = c[mt][nt][1] * sc * cs1;
            float v2 = c[mt][nt][2] * sc * cs0;
            float v3 = c[mt][nt][3] * sc * cs1;
            if (C) {
                float* p0 = C + (size_t)row * N + col;
                float* p1 = C + (size_t)(row + 8) * N + col;
                if (accumulate) {
                    v0 += p0[0]; v1 += p0[1];
                    v2 += p1[0]; v3 += p1[1];
                }
                float2 a; a.x = v0; a.y = v1; *(float2*)p0 = a;
                float2 b; b.x = v2; b.y = v3; *(float2*)p1 = b;
            }
            if (Chalf) {
                *(__half2*)(Chalf + (size_t)row * N + col)       = __floats2half2_rn(v0, v1);
                *(__half2*)(Chalf + (size_t)(row + 8) * N + col) = __floats2half2_rn(v2, v3);
            }
        }
    }
}

// ---------------- per-head normalize + MiPE rotate + g_hat (fp16 qkvg) ----------------
__global__ void normrot_kernel(__half* __restrict__ qkvg, const float* __restrict__ sw) {
    int gwarp = (blockIdx.x * blockDim.x + threadIdx.x) >> 5;
    int lane = threadIdx.x & 31;
    int h = gwarp & (NH - 1);
    int m = gwarp >> 4;
    int t = m & (SEQ - 1);
    size_t base = (size_t)m * QS + h * DK + 2 * lane;

    float2 qv = __half22float2(*(__half2*)(qkvg + base));
    float2 kv = __half22float2(*(__half2*)(qkvg + base + DE));
    float2 vv = __half22float2(*(__half2*)(qkvg + base + 2*DE));
    float2 gv = __half22float2(*(__half2*)(qkvg + base + 3*DE));

    float sq = wredsum(qv.x * qv.x + qv.y * qv.y);
    float sk = wredsum(kv.x * kv.x + kv.y * kv.y);
    float sv = wredsum(vv.x * vv.x + vv.y * vv.y);
    float iq = 1.0f / fmaxf(sqrtf(sq), 1e-12f);
    float ik = 1.0f / fmaxf(sqrtf(sk), 1e-12f);
    float iv = 1.0f / fmaxf(sqrtf(sv), 1e-12f);
    qv.x *= iq; qv.y *= iq;
    kv.x *= ik; kv.y *= ik;
    vv.x *= iv; vv.y *= iv;

    float w = expf(sw[h]) + 1.0f;
    float phi = (w < 128.0f) ? 0.5f * (cosf(PI_F * w / 128.0f) + 1.0f) : 0.0f;
    float ang = (float)t * (phi / w);
    float cc = cosf(ang), ss = sinf(ang);
    if (lane == 0) {
        float q0 = qv.x, q1 = qv.y;
        qv.x = q0 * cc - q1 * ss; qv.y = q0 * ss + q1 * cc;
        float k0 = kv.x, k1 = kv.y;
        kv.x = k0 * cc - k1 * ss; kv.y = k0 * ss + k1 * cc;
    }

    float s0 = gv.x / (1.0f + expf(-gv.x));
    float s1 = gv.y / (1.0f + expf(-gv.y));
    gv.x = tanhf(s0); gv.y = tanhf(s1);

    *(__half2*)(qkvg + base)        = __floats2half2_rn(qv.x, qv.y);
    *(__half2*)(qkvg + base + DE)   = __floats2half2_rn(kv.x, kv.y);
    *(__half2*)(qkvg + base + 2*DE) = __floats2half2_rn(vv.x, vv.y);
    *(__half2*)(qkvg + base + 3*DE) = __floats2half2_rn(gv.x, gv.y);
}

// ---------------- windowed attention + epilogue; fp16 in, fp16 out ----------------
__global__ void attn_kernel(const __half* __restrict__ qkvg,
                            const float* __restrict__ sw, const float* __restrict__ sr,
                            const float* __restrict__ sO, __half* __restrict__ hhh) {
    int gwarp = (blockIdx.x * blockDim.x + threadIdx.x) >> 5;
    int lane = threadIdx.x & 31;
    int h = gwarp & (NH - 1);
    int m = gwarp >> 4;
    int t = m & (SEQ - 1);

    float w  = expf(sw[h]) + 1.0f;
    float r  = expf(sr[h]) + 1.0f;
    float es = expf(sO[h]);

    size_t base = (size_t)m * QS + h * DK + 2 * lane;
    float2 qv = __half22float2(*(const __half2*)(qkvg + base));

    float acc0 = 0.f, acc1 = 0.f;
    int lb = (int)ceilf(w) - 1;
    if (lb > t) lb = t;

    for (int s = t - lb; s <= t; ++s) {
        float rel = (float)(s - t);
        if (-rel >= w) continue;
        size_t kb = (size_t)(m - t + s) * QS + h * DK + 2 * lane;
        float2 kv = __half22float2(*(const __half2*)(qkvg + kb + DE));
        float sim = wredsum(qv.x * kv.x + qv.y * kv.y);
        float mask = 0.5f * (cosf(PI_F * rel / w) + 1.0f);
        float tmp = fmaxf(1.0f - r * (1.0f - sim), 0.0f);
        float rho = tmp * tmp * mask;
        float2 vv = __half22float2(*(const __half2*)(qkvg + kb + 2*DE));
        acc0 += rho * vv.x;
        acc1 += rho * vv.y;
    }

    float hn2 = wredsum(acc0 * acc0 + acc1 * acc1);
    float hn = fmaxf(sqrtf(hn2), 1e-8f);
    float us = tanhf(hn) / hn;

    float2 gv = __half22float2(*(const __half2*)(qkvg + base + 3*DE));
    float o0 = acc0 * us * gv.x * es;
    float o1 = acc1 * us * gv.y * es;
    size_t ob = (size_t)m * DE + h * DK + 2 * lane;
    *(__half2*)(hhh + ob) = __floats2half2_rn(o0, o1);
}

// ---------------- launch ----------------
extern "C" void kernel_launch(void* const* d_in, const int* in_sizes, int n_in,
                              void* d_out, int out_size) {
    const int*   ids   = (const int*)d_in[0];
    const float* embed = (const float*)d_in[1];
    const float* sE    = (const float*)d_in[2];
    const float* sF    = (const float*)d_in[3];
    const float* Wq    = (const float*)d_in[4];
    const float* Wk    = (const float*)d_in[5];
    const float* Wv    = (const float*)d_in[6];
    const float* Wg    = (const float*)d_in[7];
    const float* Wo    = (const float*)d_in[8];
    const float* sw    = (const float*)d_in[9];
    const float* sr    = (const float*)d_in[10];
    const float* sO    = (const float*)d_in[11];
    float* out = (float*)d_out;

    cudaFuncSetAttribute(gemm_f16, cudaFuncAttributeMaxDynamicSharedMemorySize, SMEM_GEMM);

    float *x, *rn;
    cudaGetSymbolAddress((void**)&x,  d_x);
    cudaGetSymbolAddress((void**)&rn, d_rnorm);
    __half *qkvg, *xh, *hhh, *eh, *wh;
    cudaGetSymbolAddress((void**)&qkvg, d_qkvg);
    cudaGetSymbolAddress((void**)&xh,  d_xh);
    cudaGetSymbolAddress((void**)&hhh, d_hhh);
    cudaGetSymbolAddress((void**)&eh,  d_eh);
    cudaGetSymbolAddress((void**)&wh,  d_wh);

    const size_t LW = (size_t)DE * DE;           // one weight matrix
    const size_t WO_BASE = (size_t)NL * 4 * LW;  // wo planes start here

    rnormconv_kernel<<<VOCAB, 256>>>(embed, rn, eh);
    embed_kernel<<<MTOT, 256>>>(ids, embed, rn, sE, x, xh);

    int wgrid = (int)(LW/4/256);
    for (int l = 0; l < NL; ++l) {
        size_t fb = (size_t)l * 4 * LW;   // fused qkvg block for layer l
        conv_kernel<<<wgrid, 256>>>(Wq + l*LW, wh + fb + 0*LW, (int)(LW/4));
        conv_kernel<<<wgrid, 256>>>(Wk + l*LW, wh + fb + 1*LW, (int)(LW/4));
        conv_kernel<<<wgrid, 256>>>(Wv + l*LW, wh + fb + 2*LW, (int)(LW/4));
        conv_kernel<<<wgrid, 256>>>(Wg + l*LW, wh + fb + 3*LW, (int)(LW/4));
        conv_kernel<<<wgrid, 256>>>(Wo + l*LW, wh + WO_BASE + l*LW, (int)(LW/4));
    }

    dim3 gfused(QS / BN, MTOT / BM);   // (32, 32)
    dim3 gwo(DE / BN, MTOT / BM);      // (8, 32)
    int warps_total = MTOT * NH;
    int nblk = (warps_total * 32) / 256;

    for (int l = 0; l < NL; ++l) {
        size_t fb = (size_t)l * 4 * LW;
        const float* swl = sw + l * NH;
        const float* srl = sr + l * NH;
        const float* sOl = sO + l * NH;

        gemm_f16<<<gfused, 256, SMEM_GEMM>>>(xh, wh + fb, nullptr,
                                             MTOT, QS, DE, nullptr, nullptr, 0, qkvg);
        normrot_kernel<<<nblk, 256>>>(qkvg, swl);
        attn_kernel<<<nblk, 256>>>(qkvg, swl, srl, sOl, hhh);
        gemm_f16<<<gwo, 256, SMEM_GEMM>>>(hhh, wh + WO_BASE + l*LW, x,
                                          MTOT, DE, DE, nullptr, nullptr, 1, xh);
    }

    dim3 gfin(VOCAB / BN, MTOT / BM);  // (250, 32)
    gemm_f16<<<gfin, 256, SMEM_GEMM>>>(xh, eh, out, MTOT, VOCAB, DE, rn, sF, 0, nullptr);
}

// round 9
// speedup vs baseline: 6.4754x; 1.2114x over previous
#include <cuda_runtime.h>
#include <cuda_fp16.h>
#include <math.h>
#include <stdint.h>

#define BATCH 2
#define SEQ   2048
#define MTOT  (BATCH*SEQ)      // 4096
#define DE    1024
#define NH    16
#define DK    64
#define VOCAB 32000
#define NL    4
#define QS    (4*DE)           // fused qkvg row stride
#define PI_F  3.14159265358979323846f

#define BM 128
#define BN 128
#define BK 32
#define SPAD 40                     // fp16 elems per smem row (80B)
#define PLANE_BYTES (128*SPAD*2)    // 10240
#define STAGE_BYTES (2*PLANE_BYTES) // 20480 (A, B)
#define NSTAGE 3
#define SMEM_GEMM (NSTAGE*STAGE_BYTES) // 61440

// ---------------- scratch (static device globals; no allocation) ----------------
__device__ float d_rnorm[VOCAB];
__device__ float d_x   [MTOT*DE];
__device__ __half d_qkvg[(size_t)MTOT*QS];
__device__ __half d_xh [MTOT*DE];
__device__ __half d_hhh[MTOT*DE];
__device__ __half d_eh [(size_t)VOCAB*DE];
__device__ __half d_wh [(size_t)5*NL*DE*DE];   // [l][4DE,DE] fused qkvg, then [l][DE,DE] wo

__device__ __forceinline__ float wredsum(float x) {
#pragma unroll
    for (int o = 16; o > 0; o >>= 1) x += __shfl_xor_sync(0xFFFFFFFFu, x, o);
    return x;
}
__device__ __forceinline__ unsigned smem_u32(const void* p) {
    return (unsigned)__cvta_generic_to_shared(p);
}
__device__ __forceinline__ float ftanh(float x) {
    float y;
    asm("tanh.approx.f32 %0, %1;" : "=f"(y) : "f"(x));
    return y;
}

#define CP16(dst_u32, src_ptr) \
    asm volatile("cp.async.cg.shared.global [%0], [%1], 16;" :: "r"(dst_u32), "l"(src_ptr))
#define CP_COMMIT() asm volatile("cp.async.commit_group;" ::: "memory")
#define CP_WAIT(N)  asm volatile("cp.async.wait_group %0;" :: "n"(N) : "memory")

// ---------------- fused: embed row norm + fp16 conversion (one pass over table) ----------------
__global__ void rnormconv_kernel(const float* __restrict__ embed, float* __restrict__ rnorm,
                                 __half* __restrict__ eh) {
    int v = blockIdx.x;
    const float4* row = (const float4*)(embed + (size_t)v * DE);
    float4 f = row[threadIdx.x];           // 256 threads x 4 floats = 1024
    float s = f.x*f.x + f.y*f.y + f.z*f.z + f.w*f.w;
    __shared__ float sh[256];
    sh[threadIdx.x] = s; __syncthreads();
    for (int o = 128; o > 0; o >>= 1) {
        if (threadIdx.x < o) sh[threadIdx.x] += sh[threadIdx.x + o];
        __syncthreads();
    }
    if (threadIdx.x == 0) rnorm[v] = 1.0f / fmaxf(sqrtf(sh[0]), 1e-12f);
    __half2* H = (__half2*)(eh + (size_t)v * DE);
    H[2*threadIdx.x]   = __floats2half2_rn(f.x, f.y);
    H[2*threadIdx.x+1] = __floats2half2_rn(f.z, f.w);
}

// ---------------- embedding lookup: writes x fp32 and xh fp16 ----------------
__global__ void embed_kernel(const int* __restrict__ ids, const float* __restrict__ embed,
                             const float* __restrict__ rnorm, const float* __restrict__ sE,
                             float* __restrict__ x, __half* __restrict__ xh) {
    int m = blockIdx.x;
    int id = ids[m];
    float sc = rnorm[id] * expf(*sE);
    const float4* row = (const float4*)(embed + (size_t)id * DE);
    int i = threadIdx.x;
    float4 r = row[i];
    r.x *= sc; r.y *= sc; r.z *= sc; r.w *= sc;
    ((float4*)(x + (size_t)m * DE))[i] = r;
    __half2* hp = (__half2*)(xh + (size_t)m * DE);
    hp[2*i]   = __floats2half2_rn(r.x, r.y);
    hp[2*i+1] = __floats2half2_rn(r.z, r.w);
}

// ---------------- ALL weights fp32 -> fp16, one launch ----------------
// Layout: wh = [l][Wq,Wk,Wv,Wg each DExDE] for l=0..NL-1, then [l][Wo] at WO_BASE.
__global__ void convall_kernel(const float* __restrict__ Wq, const float* __restrict__ Wk,
                               const float* __restrict__ Wv, const float* __restrict__ Wg,
                               const float* __restrict__ Wo, __half* __restrict__ wh) {
    const size_t LW  = (size_t)DE * DE;
    const size_t QPM = LW / 4;
    size_t q = (size_t)blockIdx.x * blockDim.x + threadIdx.x;   // quad index over 20 matrices
    int mat = (int)(q / QPM);
    size_t off = q % QPM;
    const float* src;
    size_t dst;
    if (mat < 16) {
        int l = mat >> 2, f = mat & 3;
        src = (f == 0 ? Wq : f == 1 ? Wk : f == 2 ? Wv : Wg) + (size_t)l * LW;
        dst = (size_t)l * 4 * LW + (size_t)f * LW;
    } else {
        int l = mat - 16;
        src = Wo + (size_t)l * LW;
        dst = (size_t)NL * 4 * LW + (size_t)l * LW;
    }
    float4 v = ((const float4*)src)[off];
    __half2* H = (__half2*)(wh + dst);
    H[2*off]   = __floats2half2_rn(v.x, v.y);
    H[2*off+1] = __floats2half2_rn(v.z, v.w);
}

// ---------------- fp16 tensor-core NT GEMM, cp.async 3-stage ----------------
// C[m,n] = sum_k A[m,k]*B[n,k]; fp32 accum. C may be null (fp16-only out via Chalf).
#define MMA_F16(C, A, B)                                                       \
    asm volatile(                                                              \
        "mma.sync.aligned.m16n8k16.row.col.f32.f16.f16.f32 "                   \
        "{%0,%1,%2,%3}, {%4,%5,%6,%7}, {%8,%9}, {%0,%1,%2,%3};\n"              \
        : "+f"((C)[0]), "+f"((C)[1]), "+f"((C)[2]), "+f"((C)[3])               \
        : "r"((A)[0]), "r"((A)[1]), "r"((A)[2]), "r"((A)[3]),                  \
          "r"((B)[0]), "r"((B)[1]))

__global__ __launch_bounds__(256) void gemm_f16(
    const __half* __restrict__ A, const __half* __restrict__ B,
    float* __restrict__ C, int M, int N, int K,
    const float* __restrict__ colScale, const float* __restrict__ scalarLog,
    int accumulate, __half* __restrict__ Chalf)
{
    extern __shared__ __align__(128) char smem[];
    uint32_t sbase = smem_u32(smem);

    int tid  = threadIdx.x;
    int lane = tid & 31;
    int warp = tid >> 5;
    int wm = (warp >> 2) * 64;
    int wn = (warp & 3) * 32;
    int bm = blockIdx.y * BM;
    int bn = blockIdx.x * BN;

    int r0  = tid >> 2;            // 0..63
    int c16 = tid & 3;             // 16B chunk
    const char* gA0 = (const char*)(A + (size_t)(bm + r0     ) * K + c16 * 8);
    const char* gA1 = (const char*)(A + (size_t)(bm + r0 + 64) * K + c16 * 8);
    const char* gB0 = (const char*)(B + (size_t)(bn + r0     ) * K + c16 * 8);
    const char* gB1 = (const char*)(B + (size_t)(bn + r0 + 64) * K + c16 * 8);
    uint32_t s0 = r0 * (SPAD*2) + c16 * 16;
    uint32_t s1 = (r0 + 64) * (SPAD*2) + c16 * 16;

#define PREFETCH(st, k0)                                                       \
    {                                                                          \
        uint32_t sd = sbase + (st) * STAGE_BYTES;                              \
        size_t gk = (size_t)(k0) * 2;                                          \
        CP16(sd + 0*PLANE_BYTES + s0, gA0 + gk);                               \
        CP16(sd + 0*PLANE_BYTES + s1, gA1 + gk);                               \
        CP16(sd + 1*PLANE_BYTES + s0, gB0 + gk);                               \
        CP16(sd + 1*PLANE_BYTES + s1, gB1 + gk);                               \
        CP_COMMIT();                                                           \
    }

    float c[4][4][4];
#pragma unroll
    for (int i = 0; i < 4; i++)
#pragma unroll
        for (int j = 0; j < 4; j++)
#pragma unroll
            for (int q = 0; q < 4; q++) c[i][j][q] = 0.f;

    int arow_l = lane & 15;
    int acol_l = (lane >> 4) << 3;
    int brow_l = (lane & 7) + ((lane >> 4) << 3);
    int bcol_l = ((lane >> 3) & 1) << 3;

    int niter = K / BK;
    PREFETCH(0, 0);
    if (niter > 1) PREFETCH(1, BK);
    CP_WAIT(1);
    __syncthreads();

    for (int it = 0; it < niter; ++it) {
        int st = it % NSTAGE;
        if (it + 2 < niter) PREFETCH((it + 2) % NSTAGE, (it + 2) * BK);

        const __half* sA = (const __half*)(smem + st*STAGE_BYTES + 0*PLANE_BYTES);
        const __half* sB = (const __half*)(smem + st*STAGE_BYTES + 1*PLANE_BYTES);

#pragma unroll
        for (int ks = 0; ks < 2; ks++) {
            unsigned Af[4][4], Bf[4][2];
            int acol = ks * 16 + acol_l;
            int bcol = ks * 16 + bcol_l;
#pragma unroll
            for (int mt = 0; mt < 4; mt++) {
                unsigned sa = smem_u32(&sA[(wm + mt*16 + arow_l) * SPAD + acol]);
                asm volatile("ldmatrix.sync.aligned.m8n8.x4.shared.b16 {%0,%1,%2,%3}, [%4];\n"
                    : "=r"(Af[mt][0]), "=r"(Af[mt][1]), "=r"(Af[mt][2]), "=r"(Af[mt][3]) : "r"(sa));
            }
#pragma unroll
            for (int p = 0; p < 2; p++) {
                unsigned sb = smem_u32(&sB[(wn + p*16 + brow_l) * SPAD + bcol]);
                unsigned q0, q1, q2, q3;
                asm volatile("ldmatrix.sync.aligned.m8n8.x4.shared.b16 {%0,%1,%2,%3}, [%4];\n"
                    : "=r"(q0), "=r"(q1), "=r"(q2), "=r"(q3) : "r"(sb));
                Bf[p*2][0] = q0; Bf[p*2][1] = q1; Bf[p*2+1][0] = q2; Bf[p*2+1][1] = q3;
            }
#pragma unroll
            for (int mt = 0; mt < 4; mt++)
#pragma unroll
                for (int nt = 0; nt < 4; nt++)
                    MMA_F16(c[mt][nt], Af[mt], Bf[nt]);
        }

        if (it + 1 < niter) {
            if (it + 2 < niter) { CP_WAIT(1); } else { CP_WAIT(0); }
            __syncthreads();
        }
    }

    // epilogue
    float sc = scalarLog ? __expf(*scalarLog) : 1.0f;
    int g  = lane >> 2;
    int t2 = (lane & 3) * 2;
#pragma unroll
    for (int mt = 0; mt < 4; mt++) {
#pragma unroll
        for (int nt = 0; nt < 4; nt++) {
            int row = bm + wm + mt*16 + g;
            int col = bn + wn + nt*8 + t2;
            float cs0 = colScale ? colScale[col]   : 1.0f;
            float cs1 = colScale ? colScale[col+1] : 1.0f;
            float v0 = c[mt][nt][0] * sc * cs0;
            float v1 = c[mt][nt][1] * sc * cs1;
            float v2 = c[mt][nt][2] * sc * cs0;
            float v3 = c[mt][nt][3] * sc * cs1;
            if (C) {
                float* p0 = C + (size_t)row * N + col;
                float* p1 = C + (size_t)(row + 8) * N + col;
                if (accumulate) {
                    v0 += p0[0]; v1 += p0[1];
                    v2 += p1[0]; v3 += p1[1];
                }
                float2 a; a.x = v0; a.y = v1; *(float2*)p0 = a;
                float2 b; b.x = v2; b.y = v3; *(float2*)p1 = b;
            }
            if (Chalf) {
                *(__half2*)(Chalf + (size_t)row * N + col)       = __floats2half2_rn(v0, v1);
                *(__half2*)(Chalf + (size_t)(row + 8) * N + col) = __floats2half2_rn(v2, v3);
            }
        }
    }
}

// ---------------- per-head normalize + MiPE rotate + g_hat (fp16 qkvg) ----------------
__global__ void normrot_kernel(__half* __restrict__ qkvg, const float* __restrict__ sw) {
    int gwarp = (blockIdx.x * blockDim.x + threadIdx.x) >> 5;
    int lane = threadIdx.x & 31;
    int h = gwarp & (NH - 1);
    int m = gwarp >> 4;
    int t = m & (SEQ - 1);
    size_t base = (size_t)m * QS + h * DK + 2 * lane;

    float2 qv = __half22float2(*(__half2*)(qkvg + base));
    float2 kv = __half22float2(*(__half2*)(qkvg + base + DE));
    float2 vv = __half22float2(*(__half2*)(qkvg + base + 2*DE));
    float2 gv = __half22float2(*(__half2*)(qkvg + base + 3*DE));

    float sq = wredsum(qv.x * qv.x + qv.y * qv.y);
    float sk = wredsum(kv.x * kv.x + kv.y * kv.y);
    float sv = wredsum(vv.x * vv.x + vv.y * vv.y);
    float iq = 1.0f / fmaxf(sqrtf(sq), 1e-12f);
    float ik = 1.0f / fmaxf(sqrtf(sk), 1e-12f);
    float iv = 1.0f / fmaxf(sqrtf(sv), 1e-12f);
    qv.x *= iq; qv.y *= iq;
    kv.x *= ik; kv.y *= ik;
    vv.x *= iv; vv.y *= iv;

    float w = __expf(sw[h]) + 1.0f;
    float phi = (w < 128.0f) ? 0.5f * (cosf(PI_F * w / 128.0f) + 1.0f) : 0.0f;
    float ang = (float)t * (phi / w);
    float cc = cosf(ang), ss = sinf(ang);   // large args: keep precise range reduction
    if (lane == 0) {
        float q0 = qv.x, q1 = qv.y;
        qv.x = q0 * cc - q1 * ss; qv.y = q0 * ss + q1 * cc;
        float k0 = kv.x, k1 = kv.y;
        kv.x = k0 * cc - k1 * ss; kv.y = k0 * ss + k1 * cc;
    }

    // g_hat = tanh(silu(g)) with fast intrinsics
    float s0 = gv.x / (1.0f + __expf(-gv.x));
    float s1 = gv.y / (1.0f + __expf(-gv.y));
    gv.x = ftanh(s0); gv.y = ftanh(s1);

    *(__half2*)(qkvg + base)        = __floats2half2_rn(qv.x, qv.y);
    *(__half2*)(qkvg + base + DE)   = __floats2half2_rn(kv.x, kv.y);
    *(__half2*)(qkvg + base + 2*DE) = __floats2half2_rn(vv.x, vv.y);
    *(__half2*)(qkvg + base + 3*DE) = __floats2half2_rn(gv.x, gv.y);
}

// ---------------- windowed attention + epilogue; fp16 in, fp16 out ----------------
__global__ void attn_kernel(const __half* __restrict__ qkvg,
                            const float* __restrict__ sw, const float* __restrict__ sr,
                            const float* __restrict__ sO, __half* __restrict__ hhh) {
    int gwarp = (blockIdx.x * blockDim.x + threadIdx.x) >> 5;
    int lane = threadIdx.x & 31;
    int h = gwarp & (NH - 1);
    int m = gwarp >> 4;
    int t = m & (SEQ - 1);

    float w  = __expf(sw[h]) + 1.0f;
    float r  = __expf(sr[h]) + 1.0f;
    float es = __expf(sO[h]);
    float piw = PI_F / w;

    size_t base = (size_t)m * QS + h * DK + 2 * lane;
    float2 qv = __half22float2(*(const __half2*)(qkvg + base));

    float acc0 = 0.f, acc1 = 0.f;
    int lb = (int)ceilf(w) - 1;     // lb < w always => rel > -w for all visited s
    if (lb > t) lb = t;

    for (int s = t - lb; s <= t; ++s) {
        float rel = (float)(s - t);
        size_t kb = (size_t)(m - t + s) * QS + h * DK + 2 * lane;
        float2 kv = __half22float2(*(const __half2*)(qkvg + kb + DE));
        float sim = wredsum(fmaf(qv.x, kv.x, qv.y * kv.y));
        float mask = 0.5f * (__cosf(piw * rel) + 1.0f);   // |arg| < pi
        float tmp = fmaxf(fmaf(r, sim - 1.0f, 1.0f), 0.0f);  // 1 - r*(1-sim)
        float rho = tmp * tmp * mask;
        float2 vv = __half22float2(*(const __half2*)(qkvg + kb + 2*DE));
        acc0 = fmaf(rho, vv.x, acc0);
        acc1 = fmaf(rho, vv.y, acc1);
    }

    float hn2 = wredsum(fmaf(acc0, acc0, acc1 * acc1));
    float hn = fmaxf(sqrtf(hn2), 1e-8f);
    float us = ftanh(hn) / hn;

    float2 gv = __half22float2(*(const __half2*)(qkvg + base + 3*DE));
    float o0 = acc0 * us * gv.x * es;
    float o1 = acc1 * us * gv.y * es;
    size_t ob = (size_t)m * DE + h * DK + 2 * lane;
    *(__half2*)(hhh + ob) = __floats2half2_rn(o0, o1);
}

// ---------------- launch ----------------
extern "C" void kernel_launch(void* const* d_in, const int* in_sizes, int n_in,
                              void* d_out, int out_size) {
    const int*   ids   = (const int*)d_in[0];
    const float* embed = (const float*)d_in[1];
    const float* sE    = (const float*)d_in[2];
    const float* sF    = (const float*)d_in[3];
    const float* Wq    = (const float*)d_in[4];
    const float* Wk    = (const float*)d_in[5];
    const float* Wv    = (const float*)d_in[6];
    const float* Wg    = (const float*)d_in[7];
    const float* Wo    = (const float*)d_in[8];
    const float* sw    = (const float*)d_in[9];
    const float* sr    = (const float*)d_in[10];
    const float* sO    = (const float*)d_in[11];
    float* out = (float*)d_out;

    cudaFuncSetAttribute(gemm_f16, cudaFuncAttributeMaxDynamicSharedMemorySize, SMEM_GEMM);

    float *x, *rn;
    cudaGetSymbolAddress((void**)&x,  d_x);
    cudaGetSymbolAddress((void**)&rn, d_rnorm);
    __half *qkvg, *xh, *hhh, *eh, *wh;
    cudaGetSymbolAddress((void**)&qkvg, d_qkvg);
    cudaGetSymbolAddress((void**)&xh,  d_xh);
    cudaGetSymbolAddress((void**)&hhh, d_hhh);
    cudaGetSymbolAddress((void**)&eh,  d_eh);
    cudaGetSymbolAddress((void**)&wh,  d_wh);

    const size_t LW = (size_t)DE * DE;           // one weight matrix
    const size_t WO_BASE = (size_t)NL * 4 * LW;  // wo planes start here

    rnormconv_kernel<<<VOCAB, 256>>>(embed, rn, eh);
    embed_kernel<<<MTOT, 256>>>(ids, embed, rn, sE, x, xh);
    convall_kernel<<<(int)(20 * LW / 4 / 256), 256>>>(Wq, Wk, Wv, Wg, Wo, wh);

    dim3 gfused(QS / BN, MTOT / BM);   // (32, 32)
    dim3 gwo(DE / BN, MTOT / BM);      // (8, 32)
    int warps_total = MTOT * NH;
    int nblk = (warps_total * 32) / 256;

    for (int l = 0; l < NL; ++l) {
        size_t fb = (size_t)l * 4 * LW;
        const float* swl = sw + l * NH;
        const float* srl = sr + l * NH;
        const float* sOl = sO + l * NH;

        gemm_f16<<<gfused, 256, SMEM_GEMM>>>(xh, wh + fb, nullptr,
                                             MTOT, QS, DE, nullptr, nullptr, 0, qkvg);
        normrot_kernel<<<nblk, 256>>>(qkvg, swl);
        attn_kernel<<<nblk, 256>>>(qkvg, swl, srl, sOl, hhh);
        gemm_f16<<<gwo, 256, SMEM_GEMM>>>(hhh, wh + WO_BASE + l*LW, x,
                                          MTOT, DE, DE, nullptr, nullptr, 1, xh);
    }

    dim3 gfin(VOCAB / BN, MTOT / BM);  // (250, 32)
    gemm_f16<<<gfin, 256, SMEM_GEMM>>>(xh, eh, out, MTOT, VOCAB, DE, rn, sF, 0, nullptr);
}

// round 10
// speedup vs baseline: 6.7790x; 1.0469x over previous
#include <cuda_runtime.h>
#include <cuda_fp16.h>
#include <math.h>
#include <stdint.h>

#define BATCH 2
#define SEQ   2048
#define MTOT  (BATCH*SEQ)      // 4096
#define DE    1024
#define NH    16
#define DK    64
#define VOCAB 32000
#define NL    4
#define QS    (4*DE)           // fused qkvg row stride
#define PI_F  3.14159265358979323846f

#define BM 128
#define BN 128
#define BK 64
#define SPAD 72                     // fp16 elems per smem row (144B, conflict-free)
#define PLANE_BYTES (128*SPAD*2)    // 18432
#define STAGE_BYTES (2*PLANE_BYTES) // 36864 (A, B)
#define NSTAGE 3
#define SMEM_GEMM (NSTAGE*STAGE_BYTES) // 110592

// ---------------- scratch (static device globals; no allocation) ----------------
__device__ float d_rnorm[VOCAB];
__device__ float d_x   [MTOT*DE];
__device__ __half d_qkvg[(size_t)MTOT*QS];
__device__ __half d_xh [MTOT*DE];
__device__ __half d_hhh[MTOT*DE];
__device__ __half d_eh [(size_t)VOCAB*DE];
__device__ __half d_wh [(size_t)5*NL*DE*DE];   // [l][Wq,Wk,Wv,Wg], then [l][Wo]
__device__ float d_ikn[MTOT*NH];
__device__ float d_ivn[MTOT*NH];

__device__ __forceinline__ float wredsum(float x) {
#pragma unroll
    for (int o = 16; o > 0; o >>= 1) x += __shfl_xor_sync(0xFFFFFFFFu, x, o);
    return x;
}
__device__ __forceinline__ unsigned smem_u32(const void* p) {
    return (unsigned)__cvta_generic_to_shared(p);
}
__device__ __forceinline__ float ftanh(float x) {
    float y;
    asm("tanh.approx.f32 %0, %1;" : "=f"(y) : "f"(x));
    return y;
}

#define CP16(dst_u32, src_ptr) \
    asm volatile("cp.async.cg.shared.global [%0], [%1], 16;" :: "r"(dst_u32), "l"(src_ptr))
#define CP_COMMIT() asm volatile("cp.async.commit_group;" ::: "memory")
#define CP_WAIT(N)  asm volatile("cp.async.wait_group %0;" :: "n"(N) : "memory")

// ---------------- fused: embed row norm + fp16 conversion ----------------
__global__ void rnormconv_kernel(const float* __restrict__ embed, float* __restrict__ rnorm,
                                 __half* __restrict__ eh) {
    int v = blockIdx.x;
    const float4* row = (const float4*)(embed + (size_t)v * DE);
    float4 f = row[threadIdx.x];
    float s = f.x*f.x + f.y*f.y + f.z*f.z + f.w*f.w;
    __shared__ float sh[256];
    sh[threadIdx.x] = s; __syncthreads();
    for (int o = 128; o > 0; o >>= 1) {
        if (threadIdx.x < o) sh[threadIdx.x] += sh[threadIdx.x + o];
        __syncthreads();
    }
    if (threadIdx.x == 0) rnorm[v] = 1.0f / fmaxf(sqrtf(sh[0]), 1e-12f);
    __half2* H = (__half2*)(eh + (size_t)v * DE);
    H[2*threadIdx.x]   = __floats2half2_rn(f.x, f.y);
    H[2*threadIdx.x+1] = __floats2half2_rn(f.z, f.w);
}

// ---------------- embedding lookup: writes x fp32 and xh fp16 ----------------
__global__ void embed_kernel(const int* __restrict__ ids, const float* __restrict__ embed,
                             const float* __restrict__ rnorm, const float* __restrict__ sE,
                             float* __restrict__ x, __half* __restrict__ xh) {
    int m = blockIdx.x;
    int id = ids[m];
    float sc = rnorm[id] * expf(*sE);
    const float4* row = (const float4*)(embed + (size_t)id * DE);
    int i = threadIdx.x;
    float4 r = row[i];
    r.x *= sc; r.y *= sc; r.z *= sc; r.w *= sc;
    ((float4*)(x + (size_t)m * DE))[i] = r;
    __half2* hp = (__half2*)(xh + (size_t)m * DE);
    hp[2*i]   = __floats2half2_rn(r.x, r.y);
    hp[2*i+1] = __floats2half2_rn(r.z, r.w);
}

// ---------------- ALL weights fp32 -> fp16, one launch ----------------
__global__ void convall_kernel(const float* __restrict__ Wq, const float* __restrict__ Wk,
                               const float* __restrict__ Wv, const float* __restrict__ Wg,
                               const float* __restrict__ Wo, __half* __restrict__ wh) {
    const size_t LW  = (size_t)DE * DE;
    const size_t QPM = LW / 4;
    size_t q = (size_t)blockIdx.x * blockDim.x + threadIdx.x;
    int mat = (int)(q / QPM);
    size_t off = q % QPM;
    const float* src;
    size_t dst;
    if (mat < 16) {
        int l = mat >> 2, f = mat & 3;
        src = (f == 0 ? Wq : f == 1 ? Wk : f == 2 ? Wv : Wg) + (size_t)l * LW;
        dst = (size_t)l * 4 * LW + (size_t)f * LW;
    } else {
        int l = mat - 16;
        src = Wo + (size_t)l * LW;
        dst = (size_t)NL * 4 * LW + (size_t)l * LW;
    }
    float4 v = ((const float4*)src)[off];
    __half2* H = (__half2*)(wh + dst);
    H[2*off]   = __floats2half2_rn(v.x, v.y);
    H[2*off+1] = __floats2half2_rn(v.z, v.w);
}

// ---------------- fp16 tensor-core NT GEMM, cp.async 3-stage, BK=64 ----------------
#define MMA_F16(C, A, B)                                                       \
    asm volatile(                                                              \
        "mma.sync.aligned.m16n8k16.row.col.f32.f16.f16.f32 "                   \
        "{%0,%1,%2,%3}, {%4,%5,%6,%7}, {%8,%9}, {%0,%1,%2,%3};\n"              \
        : "+f"((C)[0]), "+f"((C)[1]), "+f"((C)[2]), "+f"((C)[3])               \
        : "r"((A)[0]), "r"((A)[1]), "r"((A)[2]), "r"((A)[3]),                  \
          "r"((B)[0]), "r"((B)[1]))

__global__ __launch_bounds__(256, 2) void gemm_f16(
    const __half* __restrict__ A, const __half* __restrict__ B,
    float* __restrict__ C, int M, int N, int K,
    const float* __restrict__ colScale, const float* __restrict__ scalarLog,
    int accumulate, __half* __restrict__ Chalf)
{
    extern __shared__ __align__(128) char smem[];
    uint32_t sbase = smem_u32(smem);

    int tid  = threadIdx.x;
    int lane = tid & 31;
    int warp = tid >> 5;
    int wm = (warp >> 2) * 64;
    int wn = (warp & 3) * 32;
    int bm = blockIdx.y * BM;
    int bn = blockIdx.x * BN;

    // cp.async mapping: per plane, 128 rows x 128B = 1024 16B-chunks; 4 per thread
    int r0  = tid >> 3;            // 0..31
    int c16 = tid & 7;             // 0..7
    const char* gA0 = (const char*)(A + (size_t)(bm + r0) * K + c16 * 8);
    const char* gB0 = (const char*)(B + (size_t)(bn + r0) * K + c16 * 8);
    uint32_t s0 = r0 * (SPAD*2) + c16 * 16;
    const size_t rowstep = (size_t)32 * K * 2;   // 32 rows in bytes
    const uint32_t srowstep = 32 * (SPAD*2);     // 4608

#define PREFETCH(st, k0)                                                       \
    {                                                                          \
        uint32_t sd = sbase + (st) * STAGE_BYTES;                              \
        size_t gk = (size_t)(k0) * 2;                                          \
        _Pragma("unroll")                                                      \
        for (int i = 0; i < 4; i++) {                                          \
            CP16(sd + 0*PLANE_BYTES + s0 + i*srowstep, gA0 + gk + i*rowstep);  \
            CP16(sd + 1*PLANE_BYTES + s0 + i*srowstep, gB0 + gk + i*rowstep);  \
        }                                                                      \
        CP_COMMIT();                                                           \
    }

    float c[4][4][4];
#pragma unroll
    for (int i = 0; i < 4; i++)
#pragma unroll
        for (int j = 0; j < 4; j++)
#pragma unroll
            for (int q = 0; q < 4; q++) c[i][j][q] = 0.f;

    int arow_l = lane & 15;
    int acol_l = (lane >> 4) << 3;
    int brow_l = (lane & 7) + ((lane >> 4) << 3);
    int bcol_l = ((lane >> 3) & 1) << 3;

    int niter = K / BK;
    PREFETCH(0, 0);
    if (niter > 1) PREFETCH(1, BK);
    CP_WAIT(1);
    __syncthreads();

    for (int it = 0; it < niter; ++it) {
        int st = it % NSTAGE;
        if (it + 2 < niter) PREFETCH((it + 2) % NSTAGE, (it + 2) * BK);

        const __half* sA = (const __half*)(smem + st*STAGE_BYTES + 0*PLANE_BYTES);
        const __half* sB = (const __half*)(smem + st*STAGE_BYTES + 1*PLANE_BYTES);

#pragma unroll
        for (int ks = 0; ks < 4; ks++) {
            unsigned Af[4][4], Bf[4][2];
            int acol = ks * 16 + acol_l;
            int bcol = ks * 16 + bcol_l;
#pragma unroll
            for (int mt = 0; mt < 4; mt++) {
                unsigned sa = smem_u32(&sA[(wm + mt*16 + arow_l) * SPAD + acol]);
                asm volatile("ldmatrix.sync.aligned.m8n8.x4.shared.b16 {%0,%1,%2,%3}, [%4];\n"
                    : "=r"(Af[mt][0]), "=r"(Af[mt][1]), "=r"(Af[mt][2]), "=r"(Af[mt][3]) : "r"(sa));
            }
#pragma unroll
            for (int p = 0; p < 2; p++) {
                unsigned sb = smem_u32(&sB[(wn + p*16 + brow_l) * SPAD + bcol]);
                unsigned q0, q1, q2, q3;
                asm volatile("ldmatrix.sync.aligned.m8n8.x4.shared.b16 {%0,%1,%2,%3}, [%4];\n"
                    : "=r"(q0), "=r"(q1), "=r"(q2), "=r"(q3) : "r"(sb));
                Bf[p*2][0] = q0; Bf[p*2][1] = q1; Bf[p*2+1][0] = q2; Bf[p*2+1][1] = q3;
            }
#pragma unroll
            for (int mt = 0; mt < 4; mt++)
#pragma unroll
                for (int nt = 0; nt < 4; nt++)
                    MMA_F16(c[mt][nt], Af[mt], Bf[nt]);
        }

        if (it + 1 < niter) {
            if (it + 2 < niter) { CP_WAIT(1); } else { CP_WAIT(0); }
            __syncthreads();
        }
    }

    // epilogue
    float sc = scalarLog ? __expf(*scalarLog) : 1.0f;
    int g  = lane >> 2;
    int t2 = (lane & 3) * 2;
#pragma unroll
    for (int mt = 0; mt < 4; mt++) {
#pragma unroll
        for (int nt = 0; nt < 4; nt++) {
            int row = bm + wm + mt*16 + g;
            int col = bn + wn + nt*8 + t2;
            float cs0 = colScale ? colScale[col]   : 1.0f;
            float cs1 = colScale ? colScale[col+1] : 1.0f;
            float v0 = c[mt][nt][0] * sc * cs0;
            float v1 = c[mt][nt][1] * sc * cs1;
            float v2 = c[mt][nt][2] * sc * cs0;
            float v3 = c[mt][nt][3] * sc * cs1;
            if (C) {
                float* p0 = C + (size_t)row * N + col;
                float* p1 = C + (size_t)(row + 8) * N + col;
                if (accumulate) {
                    v0 += p0[0]; v1 += p0[1];
                    v2 += p1[0]; v3 += p1[1];
                }
                float2 a; a.x = v0; a.y = v1; *(float2*)p0 = a;
                float2 b; b.x = v2; b.y = v3; *(float2*)p1 = b;
            }
            if (Chalf) {
                *(__half2*)(Chalf + (size_t)row * N + col)       = __floats2half2_rn(v0, v1);
                *(__half2*)(Chalf + (size_t)(row + 8) * N + col) = __floats2half2_rn(v2, v3);
            }
        }
    }
}

// ---------------- per-(m,h) inverse norms of raw k, v ----------------
__global__ void norms_kernel(const __half* __restrict__ qkvg,
                             float* __restrict__ ikn, float* __restrict__ ivn) {
    int gwarp = (blockIdx.x * blockDim.x + threadIdx.x) >> 5;
    int lane = threadIdx.x & 31;
    int h = gwarp & (NH - 1);
    int m = gwarp >> 4;
    size_t base = (size_t)m * QS + h * DK + 2 * lane;
    float2 kv = __half22float2(*(const __half2*)(qkvg + base + DE));
    float2 vv = __half22float2(*(const __half2*)(qkvg + base + 2*DE));
    float sk = wredsum(fmaf(kv.x, kv.x, kv.y * kv.y));
    float sv = wredsum(fmaf(vv.x, vv.x, vv.y * vv.y));
    if (lane == 0) {
        ikn[m * NH + h] = 1.0f / fmaxf(sqrtf(sk), 1e-12f);
        ivn[m * NH + h] = 1.0f / fmaxf(sqrtf(sv), 1e-12f);
    }
}

// ---------------- fused attention on RAW qkvg (rotation-free identity) ----------------
// sim(t,s) = iq*ikn[s] * [ dot(q,k) with lane-0 pair replaced by
//            cosD*(q0k0+q1k1) + sinD*(q0k1-q1k0) ],  D = rel*phi/w
__global__ void attn_kernel(const __half* __restrict__ qkvg,
                            const float* __restrict__ ikn, const float* __restrict__ ivn,
                            const float* __restrict__ sw, const float* __restrict__ sr,
                            const float* __restrict__ sO, __half* __restrict__ hhh) {
    int gwarp = (blockIdx.x * blockDim.x + threadIdx.x) >> 5;
    int lane = threadIdx.x & 31;
    int h = gwarp & (NH - 1);
    int m = gwarp >> 4;
    int t = m & (SEQ - 1);

    float w  = __expf(sw[h]) + 1.0f;
    float r  = __expf(sr[h]) + 1.0f;
    float es = __expf(sO[h]);
    float piw = PI_F / w;
    float phi = (w < 128.0f) ? 0.5f * (cosf(PI_F * w / 128.0f) + 1.0f) : 0.0f;
    float phiw = phi / w;

    size_t base = (size_t)m * QS + h * DK + 2 * lane;
    float2 qv = __half22float2(*(const __half2*)(qkvg + base));
    float sq = wredsum(fmaf(qv.x, qv.x, qv.y * qv.y));
    float iq = 1.0f / fmaxf(sqrtf(sq), 1e-12f);

    float acc0 = 0.f, acc1 = 0.f;
    int lb = (int)ceilf(w) - 1;     // lb < w => rel > -w for all visited s
    if (lb > t) lb = t;

    for (int s = t - lb; s <= t; ++s) {
        float rel = (float)(s - t);
        int mr = m - t + s;
        size_t kb = (size_t)mr * QS + h * DK + 2 * lane;
        float2 kv = __half22float2(*(const __half2*)(qkvg + kb + DE));
        float contrib = fmaf(qv.x, kv.x, qv.y * kv.y);
        float D = rel * phiw;                        // |D| <= phi <= 1
        float cd = __cosf(D), sd = __sinf(D);
        if (lane == 0)
            contrib = fmaf(cd, contrib, sd * (qv.x * kv.y - qv.y * kv.x));
        float sim = wredsum(contrib) * iq * ikn[mr * NH + h];
        float mask = 0.5f * (__cosf(piw * rel) + 1.0f);
        float tmp = fmaxf(fmaf(r, sim - 1.0f, 1.0f), 0.0f);
        float rho = tmp * tmp * mask * ivn[mr * NH + h];
        float2 vv = __half22float2(*(const __half2*)(qkvg + kb + 2*DE));
        acc0 = fmaf(rho, vv.x, acc0);
        acc1 = fmaf(rho, vv.y, acc1);
    }

    float hn2 = wredsum(fmaf(acc0, acc0, acc1 * acc1));
    float hn = fmaxf(sqrtf(hn2), 1e-8f);
    float us = ftanh(hn) / hn;

    // g_hat = tanh(silu(g)) on raw g
    float2 gv = __half22float2(*(const __half2*)(qkvg + base + 3*DE));
    float s0 = gv.x / (1.0f + __expf(-gv.x));
    float s1 = gv.y / (1.0f + __expf(-gv.y));
    float g0 = ftanh(s0), g1 = ftanh(s1);

    float o0 = acc0 * us * g0 * es;
    float o1 = acc1 * us * g1 * es;
    size_t ob = (size_t)m * DE + h * DK + 2 * lane;
    *(__half2*)(hhh + ob) = __floats2half2_rn(o0, o1);
}

// ---------------- launch ----------------
extern "C" void kernel_launch(void* const* d_in, const int* in_sizes, int n_in,
                              void* d_out, int out_size) {
    const int*   ids   = (const int*)d_in[0];
    const float* embed = (const float*)d_in[1];
    const float* sE    = (const float*)d_in[2];
    const float* sF    = (const float*)d_in[3];
    const float* Wq    = (const float*)d_in[4];
    const float* Wk    = (const float*)d_in[5];
    const float* Wv    = (const float*)d_in[6];
    const float* Wg    = (const float*)d_in[7];
    const float* Wo    = (const float*)d_in[8];
    const float* sw    = (const float*)d_in[9];
    const float* sr    = (const float*)d_in[10];
    const float* sO    = (const float*)d_in[11];
    float* out = (float*)d_out;

    cudaFuncSetAttribute(gemm_f16, cudaFuncAttributeMaxDynamicSharedMemorySize, SMEM_GEMM);

    float *x, *rn, *ikn, *ivn;
    cudaGetSymbolAddress((void**)&x,   d_x);
    cudaGetSymbolAddress((void**)&rn,  d_rnorm);
    cudaGetSymbolAddress((void**)&ikn, d_ikn);
    cudaGetSymbolAddress((void**)&ivn, d_ivn);
    __half *qkvg, *xh, *hhh, *eh, *wh;
    cudaGetSymbolAddress((void**)&qkvg, d_qkvg);
    cudaGetSymbolAddress((void**)&xh,  d_xh);
    cudaGetSymbolAddress((void**)&hhh, d_hhh);
    cudaGetSymbolAddress((void**)&eh,  d_eh);
    cudaGetSymbolAddress((void**)&wh,  d_wh);

    const size_t LW = (size_t)DE * DE;
    const size_t WO_BASE = (size_t)NL * 4 * LW;

    rnormconv_kernel<<<VOCAB, 256>>>(embed, rn, eh);
    embed_kernel<<<MTOT, 256>>>(ids, embed, rn, sE, x, xh);
    convall_kernel<<<(int)(20 * LW / 4 / 256), 256>>>(Wq, Wk, Wv, Wg, Wo, wh);

    dim3 gfused(QS / BN, MTOT / BM);   // (32, 32)
    dim3 gwo(DE / BN, MTOT / BM);      // (8, 32)
    int warps_total = MTOT * NH;
    int nblk = (warps_total * 32) / 256;

    for (int l = 0; l < NL; ++l) {
        size_t fb = (size_t)l * 4 * LW;
        const float* swl = sw + l * NH;
        const float* srl = sr + l * NH;
        const float* sOl = sO + l * NH;

        gemm_f16<<<gfused, 256, SMEM_GEMM>>>(xh, wh + fb, nullptr,
                                             MTOT, QS, DE, nullptr, nullptr, 0, qkvg);
        norms_kernel<<<nblk, 256>>>(qkvg, ikn, ivn);
        attn_kernel<<<nblk, 256>>>(qkvg, ikn, ivn, swl, srl, sOl, hhh);
        gemm_f16<<<gwo, 256, SMEM_GEMM>>>(hhh, wh + WO_BASE + l*LW, x,
                                          MTOT, DE, DE, nullptr, nullptr, 1, xh);
    }

    dim3 gfin(VOCAB / BN, MTOT / BM);  // (250, 32)
    gemm_f16<<<gfin, 256, SMEM_GEMM>>>(xh, eh, out, MTOT, VOCAB, DE, rn, sF, 0, nullptr);
}

// round 11
// speedup vs baseline: 7.7416x; 1.1420x over previous
#include <cuda_runtime.h>
#include <cuda_fp16.h>
#include <math.h>
#include <stdint.h>

#define BATCH 2
#define SEQ   2048
#define MTOT  (BATCH*SEQ)      // 4096
#define DE    1024
#define NH    16
#define DK    64
#define VOCAB 32000
#define NL    4
#define QS    (4*DE)           // fused qkvg row stride
#define PI_F  3.14159265358979323846f
#define TABSTRIDE 132          // float4 entries per (l,h)

#define BM 128
#define BN 128
#define BK 64
#define SPAD 72                     // fp16 elems per smem row (144B, conflict-free)
#define PLANE_BYTES (128*SPAD*2)    // 18432
#define STAGE_BYTES (2*PLANE_BYTES) // 36864 (A, B)
#define NSTAGE 3
#define SMEM_GEMM (NSTAGE*STAGE_BYTES) // 110592

// ---------------- scratch (static device globals; no allocation) ----------------
__device__ float d_rnorm[VOCAB];
__device__ float d_x   [MTOT*DE];
__device__ __half d_qkvg[(size_t)MTOT*QS];
__device__ __half d_xh [MTOT*DE];
__device__ __half d_hhh[MTOT*DE];
__device__ __half d_eh [(size_t)VOCAB*DE];
__device__ __half d_wh [(size_t)5*NL*DE*DE];   // [l][Wq,Wk,Wv,Wg], then [l][Wo]
__device__ float4 d_tab[NL*NH*TABSTRIDE];      // (mask, cosD, sinD, 0) per (l,h,-rel)

__device__ __forceinline__ float wredsum(float x) {
#pragma unroll
    for (int o = 16; o > 0; o >>= 1) x += __shfl_xor_sync(0xFFFFFFFFu, x, o);
    return x;
}
__device__ __forceinline__ unsigned smem_u32(const void* p) {
    return (unsigned)__cvta_generic_to_shared(p);
}
__device__ __forceinline__ float ftanh(float x) {
    float y;
    asm("tanh.approx.f32 %0, %1;" : "=f"(y) : "f"(x));
    return y;
}

#define CP16(dst_u32, src_ptr) \
    asm volatile("cp.async.cg.shared.global [%0], [%1], 16;" :: "r"(dst_u32), "l"(src_ptr))
#define CP_COMMIT() asm volatile("cp.async.commit_group;" ::: "memory")
#define CP_WAIT(N)  asm volatile("cp.async.wait_group %0;" :: "n"(N) : "memory")

// ---------------- fused: embed row norm + fp16 conversion ----------------
__global__ void rnormconv_kernel(const float* __restrict__ embed, float* __restrict__ rnorm,
                                 __half* __restrict__ eh) {
    int v = blockIdx.x;
    const float4* row = (const float4*)(embed + (size_t)v * DE);
    float4 f = row[threadIdx.x];
    float s = f.x*f.x + f.y*f.y + f.z*f.z + f.w*f.w;
    __shared__ float sh[256];
    sh[threadIdx.x] = s; __syncthreads();
    for (int o = 128; o > 0; o >>= 1) {
        if (threadIdx.x < o) sh[threadIdx.x] += sh[threadIdx.x + o];
        __syncthreads();
    }
    if (threadIdx.x == 0) rnorm[v] = 1.0f / fmaxf(sqrtf(sh[0]), 1e-12f);
    __half2* H = (__half2*)(eh + (size_t)v * DE);
    H[2*threadIdx.x]   = __floats2half2_rn(f.x, f.y);
    H[2*threadIdx.x+1] = __floats2half2_rn(f.z, f.w);
}

// ---------------- embedding lookup: writes x fp32 and xh fp16 ----------------
__global__ void embed_kernel(const int* __restrict__ ids, const float* __restrict__ embed,
                             const float* __restrict__ rnorm, const float* __restrict__ sE,
                             float* __restrict__ x, __half* __restrict__ xh) {
    int m = blockIdx.x;
    int id = ids[m];
    float sc = rnorm[id] * expf(*sE);
    const float4* row = (const float4*)(embed + (size_t)id * DE);
    int i = threadIdx.x;
    float4 r = row[i];
    r.x *= sc; r.y *= sc; r.z *= sc; r.w *= sc;
    ((float4*)(x + (size_t)m * DE))[i] = r;
    __half2* hp = (__half2*)(xh + (size_t)m * DE);
    hp[2*i]   = __floats2half2_rn(r.x, r.y);
    hp[2*i+1] = __floats2half2_rn(r.z, r.w);
}

// ---------------- ALL weights fp32 -> fp16, one launch ----------------
__global__ void convall_kernel(const float* __restrict__ Wq, const float* __restrict__ Wk,
                               const float* __restrict__ Wv, const float* __restrict__ Wg,
                               const float* __restrict__ Wo, __half* __restrict__ wh) {
    const size_t LW  = (size_t)DE * DE;
    const size_t QPM = LW / 4;
    size_t q = (size_t)blockIdx.x * blockDim.x + threadIdx.x;
    int mat = (int)(q / QPM);
    size_t off = q % QPM;
    const float* src;
    size_t dst;
    if (mat < 16) {
        int l = mat >> 2, f = mat & 3;
        src = (f == 0 ? Wq : f == 1 ? Wk : f == 2 ? Wv : Wg) + (size_t)l * LW;
        dst = (size_t)l * 4 * LW + (size_t)f * LW;
    } else {
        int l = mat - 16;
        src = Wo + (size_t)l * LW;
        dst = (size_t)NL * 4 * LW + (size_t)l * LW;
    }
    float4 v = ((const float4*)src)[off];
    __half2* H = (__half2*)(wh + dst);
    H[2*off]   = __floats2half2_rn(v.x, v.y);
    H[2*off+1] = __floats2half2_rn(v.z, v.w);
}

// ---------------- per-(l,h,rel) mask/rotation table (precise trig, one launch) --------
__global__ void tab_kernel(const float* __restrict__ sw_all, float4* __restrict__ tab) {
    int l = blockIdx.x >> 4;
    int h = blockIdx.x & 15;
    int j = threadIdx.x;                 // j = -rel
    if (j >= 129) return;
    float w = expf(sw_all[l*NH + h]) + 1.0f;
    float phi = (w < 128.0f) ? 0.5f * (cosf(PI_F * w / 128.0f) + 1.0f) : 0.0f;
    float phiw = phi / w;
    float rel = -(float)j;
    float mask = 0.5f * (cosf(PI_F * rel / w) + 1.0f);
    float D = rel * phiw;
    tab[(size_t)(l*NH + h) * TABSTRIDE + j] = make_float4(mask, cosf(D), sinf(D), 0.0f);
}

// ---------------- fp16 tensor-core NT GEMM, cp.async 3-stage, BK=64 ----------------
#define MMA_F16(C, A, B)                                                       \
    asm volatile(                                                              \
        "mma.sync.aligned.m16n8k16.row.col.f32.f16.f16.f32 "                   \
        "{%0,%1,%2,%3}, {%4,%5,%6,%7}, {%8,%9}, {%0,%1,%2,%3};\n"              \
        : "+f"((C)[0]), "+f"((C)[1]), "+f"((C)[2]), "+f"((C)[3])               \
        : "r"((A)[0]), "r"((A)[1]), "r"((A)[2]), "r"((A)[3]),                  \
          "r"((B)[0]), "r"((B)[1]))

__global__ __launch_bounds__(256, 2) void gemm_f16(
    const __half* __restrict__ A, const __half* __restrict__ B,
    float* __restrict__ C, int M, int N, int K,
    const float* __restrict__ colScale, const float* __restrict__ scalarLog,
    int accumulate, __half* __restrict__ Chalf)
{
    extern __shared__ __align__(128) char smem[];
    uint32_t sbase = smem_u32(smem);

    int tid  = threadIdx.x;
    int lane = tid & 31;
    int warp = tid >> 5;
    int wm = (warp >> 2) * 64;
    int wn = (warp & 3) * 32;
    int bm = blockIdx.y * BM;
    int bn = blockIdx.x * BN;

    int r0  = tid >> 3;            // 0..31
    int c16 = tid & 7;             // 0..7
    const char* gA0 = (const char*)(A + (size_t)(bm + r0) * K + c16 * 8);
    const char* gB0 = (const char*)(B + (size_t)(bn + r0) * K + c16 * 8);
    uint32_t s0 = r0 * (SPAD*2) + c16 * 16;
    const size_t rowstep = (size_t)32 * K * 2;
    const uint32_t srowstep = 32 * (SPAD*2);

#define PREFETCH(st, k0)                                                       \
    {                                                                          \
        uint32_t sd = sbase + (st) * STAGE_BYTES;                              \
        size_t gk = (size_t)(k0) * 2;                                          \
        _Pragma("unroll")                                                      \
        for (int i = 0; i < 4; i++) {                                          \
            CP16(sd + 0*PLANE_BYTES + s0 + i*srowstep, gA0 + gk + i*rowstep);  \
            CP16(sd + 1*PLANE_BYTES + s0 + i*srowstep, gB0 + gk + i*rowstep);  \
        }                                                                      \
        CP_COMMIT();                                                           \
    }

    float c[4][4][4];
#pragma unroll
    for (int i = 0; i < 4; i++)
#pragma unroll
        for (int j = 0; j < 4; j++)
#pragma unroll
            for (int q = 0; q < 4; q++) c[i][j][q] = 0.f;

    int arow_l = lane & 15;
    int acol_l = (lane >> 4) << 3;
    int brow_l = (lane & 7) + ((lane >> 4) << 3);
    int bcol_l = ((lane >> 3) & 1) << 3;

    int niter = K / BK;
    PREFETCH(0, 0);
    if (niter > 1) PREFETCH(1, BK);
    CP_WAIT(1);
    __syncthreads();

    for (int it = 0; it < niter; ++it) {
        int st = it % NSTAGE;
        if (it + 2 < niter) PREFETCH((it + 2) % NSTAGE, (it + 2) * BK);

        const __half* sA = (const __half*)(smem + st*STAGE_BYTES + 0*PLANE_BYTES);
        const __half* sB = (const __half*)(smem + st*STAGE_BYTES + 1*PLANE_BYTES);

#pragma unroll
        for (int ks = 0; ks < 4; ks++) {
            unsigned Af[4][4], Bf[4][2];
            int acol = ks * 16 + acol_l;
            int bcol = ks * 16 + bcol_l;
#pragma unroll
            for (int mt = 0; mt < 4; mt++) {
                unsigned sa = smem_u32(&sA[(wm + mt*16 + arow_l) * SPAD + acol]);
                asm volatile("ldmatrix.sync.aligned.m8n8.x4.shared.b16 {%0,%1,%2,%3}, [%4];\n"
                    : "=r"(Af[mt][0]), "=r"(Af[mt][1]), "=r"(Af[mt][2]), "=r"(Af[mt][3]) : "r"(sa));
            }
#pragma unroll
            for (int p = 0; p < 2; p++) {
                unsigned sb = smem_u32(&sB[(wn + p*16 + brow_l) * SPAD + bcol]);
                unsigned q0, q1, q2, q3;
                asm volatile("ldmatrix.sync.aligned.m8n8.x4.shared.b16 {%0,%1,%2,%3}, [%4];\n"
                    : "=r"(q0), "=r"(q1), "=r"(q2), "=r"(q3) : "r"(sb));
                Bf[p*2][0] = q0; Bf[p*2][1] = q1; Bf[p*2+1][0] = q2; Bf[p*2+1][1] = q3;
            }
#pragma unroll
            for (int mt = 0; mt < 4; mt++)
#pragma unroll
                for (int nt = 0; nt < 4; nt++)
                    MMA_F16(c[mt][nt], Af[mt], Bf[nt]);
        }

        if (it + 1 < niter) {
            if (it + 2 < niter) { CP_WAIT(1); } else { CP_WAIT(0); }
            __syncthreads();
        }
    }

    // epilogue
    float sc = scalarLog ? __expf(*scalarLog) : 1.0f;
    int g  = lane >> 2;
    int t2 = (lane & 3) * 2;
#pragma unroll
    for (int mt = 0; mt < 4; mt++) {
#pragma unroll
        for (int nt = 0; nt < 4; nt++) {
            int row = bm + wm + mt*16 + g;
            int col = bn + wn + nt*8 + t2;
            float cs0 = colScale ? colScale[col]   : 1.0f;
            float cs1 = colScale ? colScale[col+1] : 1.0f;
            float v0 = c[mt][nt][0] * sc * cs0;
            float v1 = c[mt][nt][1] * sc * cs1;
            float v2 = c[mt][nt][2] * sc * cs0;
            float v3 = c[mt][nt][3] * sc * cs1;
            if (C) {
                float* p0 = C + (size_t)row * N + col;
                float* p1 = C + (size_t)(row + 8) * N + col;
                if (accumulate) {
                    v0 += p0[0]; v1 += p0[1];
                    v2 += p1[0]; v3 += p1[1];
                }
                float2 a; a.x = v0; a.y = v1; *(float2*)p0 = a;
                float2 b; b.x = v2; b.y = v3; *(float2*)p1 = b;
            }
            if (Chalf) {
                *(__half2*)(Chalf + (size_t)row * N + col)       = __floats2half2_rn(v0, v1);
                *(__half2*)(Chalf + (size_t)(row + 8) * N + col) = __floats2half2_rn(v2, v3);
            }
        }
    }
}

// ---------------- normalize k, v in place (per (m,h)) ----------------
__global__ void normkv_kernel(__half* __restrict__ qkvg) {
    int gwarp = (blockIdx.x * blockDim.x + threadIdx.x) >> 5;
    int lane = threadIdx.x & 31;
    int h = gwarp & (NH - 1);
    int m = gwarp >> 4;
    size_t base = (size_t)m * QS + h * DK + 2 * lane;
    float2 kv = __half22float2(*(const __half2*)(qkvg + base + DE));
    float2 vv = __half22float2(*(const __half2*)(qkvg + base + 2*DE));
    float sk = wredsum(fmaf(kv.x, kv.x, kv.y * kv.y));
    float sv = wredsum(fmaf(vv.x, vv.x, vv.y * vv.y));
    float ik = 1.0f / fmaxf(sqrtf(sk), 1e-12f);
    float iv = 1.0f / fmaxf(sqrtf(sv), 1e-12f);
    *(__half2*)(qkvg + base + DE)   = __floats2half2_rn(kv.x * ik, kv.y * ik);
    *(__half2*)(qkvg + base + 2*DE) = __floats2half2_rn(vv.x * iv, vv.y * iv);
}

// ---------------- fused attention (table-driven, unroll-4) ----------------
// k,v pre-normalized in qkvg; q normalized in registers; MiPE via rotation-free
// identity with table (mask, cosD, sinD) indexed by j = t - s.
__global__ void attn_kernel(const __half* __restrict__ qkvg,
                            const float4* __restrict__ tabl,
                            const float* __restrict__ sw, const float* __restrict__ sr,
                            const float* __restrict__ sO, __half* __restrict__ hhh) {
    int gwarp = (blockIdx.x * blockDim.x + threadIdx.x) >> 5;
    int lane = threadIdx.x & 31;
    int h = gwarp & (NH - 1);
    int m = gwarp >> 4;
    int t = m & (SEQ - 1);

    float w  = __expf(sw[h]) + 1.0f;
    float r  = __expf(sr[h]) + 1.0f;
    float es = __expf(sO[h]);
    const float4* th = tabl + h * TABSTRIDE;

    size_t base = (size_t)m * QS + h * DK + 2 * lane;
    float2 qv = __half22float2(*(const __half2*)(qkvg + base));
    float sq = wredsum(fmaf(qv.x, qv.x, qv.y * qv.y));
    float iq = 1.0f / fmaxf(sqrtf(sq), 1e-12f);
    qv.x *= iq; qv.y *= iq;

    int lb = (int)ceilf(w) - 1;     // lb < w => rel > -w for all visited s
    if (lb > t) lb = t;
    int n = lb + 1;
    // key/value pointers for s = t-lb (advance by QS per s)
    const __half* kp0 = qkvg + (size_t)(m - lb) * QS + h * DK + 2 * lane + DE;

    float acc0 = 0.f, acc1 = 0.f;
    int i = 0;
    for (; i + 4 <= n; i += 4) {
        float ctr[4];
        float mk[4];
        float2 vvv[4];
#pragma unroll
        for (int u = 0; u < 4; u++) {
            int j = lb - (i + u);                 // j = t - s
            float4 tb = th[j];
            const __half* kp = kp0 + (size_t)(i + u) * QS;
            float2 kv = __half22float2(*(const __half2*)kp);
            vvv[u] = __half22float2(*(const __half2*)(kp + DE));
            float cc = fmaf(qv.x, kv.x, qv.y * kv.y);
            if (lane == 0)
                cc = fmaf(tb.y, cc, tb.z * (qv.x * kv.y - qv.y * kv.x));
            ctr[u] = cc;
            mk[u] = tb.x;
        }
#pragma unroll
        for (int o = 16; o > 0; o >>= 1) {
#pragma unroll
            for (int u = 0; u < 4; u++)
                ctr[u] += __shfl_xor_sync(0xFFFFFFFFu, ctr[u], o);
        }
#pragma unroll
        for (int u = 0; u < 4; u++) {
            float tmp = fmaxf(fmaf(r, ctr[u] - 1.0f, 1.0f), 0.0f);
            float rho = tmp * tmp * mk[u];
            acc0 = fmaf(rho, vvv[u].x, acc0);
            acc1 = fmaf(rho, vvv[u].y, acc1);
        }
    }
    for (; i < n; ++i) {
        int j = lb - i;
        float4 tb = th[j];
        const __half* kp = kp0 + (size_t)i * QS;
        float2 kv = __half22float2(*(const __half2*)kp);
        float2 vv = __half22float2(*(const __half2*)(kp + DE));
        float cc = fmaf(qv.x, kv.x, qv.y * kv.y);
        if (lane == 0)
            cc = fmaf(tb.y, cc, tb.z * (qv.x * kv.y - qv.y * kv.x));
        float sim = wredsum(cc);
        float tmp = fmaxf(fmaf(r, sim - 1.0f, 1.0f), 0.0f);
        float rho = tmp * tmp * tb.x;
        acc0 = fmaf(rho, vv.x, acc0);
        acc1 = fmaf(rho, vv.y, acc1);
    }

    float hn2 = wredsum(fmaf(acc0, acc0, acc1 * acc1));
    float hn = fmaxf(sqrtf(hn2), 1e-8f);
    float us = ftanh(hn) / hn;

    // g_hat = tanh(silu(g)) on raw g
    float2 gv = __half22float2(*(const __half2*)(qkvg + base + 3*DE));
    float s0 = gv.x / (1.0f + __expf(-gv.x));
    float s1 = gv.y / (1.0f + __expf(-gv.y));
    float g0 = ftanh(s0), g1 = ftanh(s1);

    float o0 = acc0 * us * g0 * es;
    float o1 = acc1 * us * g1 * es;
    size_t ob = (size_t)m * DE + h * DK + 2 * lane;
    *(__half2*)(hhh + ob) = __floats2half2_rn(o0, o1);
}

// ---------------- launch ----------------
extern "C" void kernel_launch(void* const* d_in, const int* in_sizes, int n_in,
                              void* d_out, int out_size) {
    const int*   ids   = (const int*)d_in[0];
    const float* embed = (const float*)d_in[1];
    const float* sE    = (const float*)d_in[2];
    const float* sF    = (const float*)d_in[3];
    const float* Wq    = (const float*)d_in[4];
    const float* Wk    = (const float*)d_in[5];
    const float* Wv    = (const float*)d_in[6];
    const float* Wg    = (const float*)d_in[7];
    const float* Wo    = (const float*)d_in[8];
    const float* sw    = (const float*)d_in[9];
    const float* sr    = (const float*)d_in[10];
    const float* sO    = (const float*)d_in[11];
    float* out = (float*)d_out;

    cudaFuncSetAttribute(gemm_f16, cudaFuncAttributeMaxDynamicSharedMemorySize, SMEM_GEMM);

    float *x, *rn;
    cudaGetSymbolAddress((void**)&x,   d_x);
    cudaGetSymbolAddress((void**)&rn,  d_rnorm);
    float4* tab;
    cudaGetSymbolAddress((void**)&tab, d_tab);
    __half *qkvg, *xh, *hhh, *eh, *wh;
    cudaGetSymbolAddress((void**)&qkvg, d_qkvg);
    cudaGetSymbolAddress((void**)&xh,  d_xh);
    cudaGetSymbolAddress((void**)&hhh, d_hhh);
    cudaGetSymbolAddress((void**)&eh,  d_eh);
    cudaGetSymbolAddress((void**)&wh,  d_wh);

    const size_t LW = (size_t)DE * DE;
    const size_t WO_BASE = (size_t)NL * 4 * LW;

    rnormconv_kernel<<<VOCAB, 256>>>(embed, rn, eh);
    embed_kernel<<<MTOT, 256>>>(ids, embed, rn, sE, x, xh);
    convall_kernel<<<(int)(20 * LW / 4 / 256), 256>>>(Wq, Wk, Wv, Wg, Wo, wh);
    tab_kernel<<<NL*NH, 160>>>(sw, tab);

    dim3 gfused(QS / BN, MTOT / BM);   // (32, 32)
    dim3 gwo(DE / BN, MTOT / BM);      // (8, 32)
    int warps_total = MTOT * NH;
    int nblk = (warps_total * 32) / 256;

    for (int l = 0; l < NL; ++l) {
        size_t fb = (size_t)l * 4 * LW;
        const float* swl = sw + l * NH;
        const float* srl = sr + l * NH;
        const float* sOl = sO + l * NH;
        const float4* tabl = tab + (size_t)l * NH * TABSTRIDE;

        gemm_f16<<<gfused, 256, SMEM_GEMM>>>(xh, wh + fb, nullptr,
                                             MTOT, QS, DE, nullptr, nullptr, 0, qkvg);
        normkv_kernel<<<nblk, 256>>>(qkvg);
        attn_kernel<<<nblk, 256>>>(qkvg, tabl, swl, srl, sOl, hhh);
        gemm_f16<<<gwo, 256, SMEM_GEMM>>>(hhh, wh + WO_BASE + l*LW, x,
                                          MTOT, DE, DE, nullptr, nullptr, 1, xh);
    }

    dim3 gfin(VOCAB / BN, MTOT / BM);  // (250, 32)
    gemm_f16<<<gfin, 256, SMEM_GEMM>>>(xh, eh, out, MTOT, VOCAB, DE, rn, sF, 0, nullptr);
}

// round 12
// speedup vs baseline: 7.8380x; 1.0124x over previous
#include <cuda_runtime.h>
#include <cuda_fp16.h>
#include <math.h>
#include <stdint.h>

#define BATCH 2
#define SEQ   2048
#define MTOT  (BATCH*SEQ)      // 4096
#define DE    1024
#define NH    16
#define DK    64
#define VOCAB 32000
#define NL    4
#define QS    (4*DE)           // fused qkvg row stride
#define PI_F  3.14159265358979323846f
#define TABSTRIDE 132          // float4 entries per (l,h)

#define BM 128
#define BN 128
#define BK 64
#define SPAD 72                     // fp16 elems per smem row (144B, conflict-free)
#define PLANE_BYTES (128*SPAD*2)    // 18432
#define STAGE_BYTES (2*PLANE_BYTES) // 36864 (A, B)
#define NSTAGE 3
#define SMEM_GEMM (NSTAGE*STAGE_BYTES) // 110592

// ---------------- scratch (static device globals; no allocation) ----------------
__device__ float d_rnorm[VOCAB];
__device__ float d_x   [MTOT*DE];
__device__ __half d_qkvg[(size_t)MTOT*QS];
__device__ __half d_xh [MTOT*DE];
__device__ __half d_hhh[MTOT*DE];
__device__ __half d_eh [(size_t)VOCAB*DE];
__device__ __half d_wh [(size_t)5*NL*DE*DE];   // [l][Wq,Wk,Wv,Wg], then [l][Wo]
__device__ float4 d_tab[NL*NH*TABSTRIDE];      // (mask, cosD, sinD, 0) per (l,h,-rel)

__device__ __forceinline__ float wredsum(float x) {
#pragma unroll
    for (int o = 16; o > 0; o >>= 1) x += __shfl_xor_sync(0xFFFFFFFFu, x, o);
    return x;
}
__device__ __forceinline__ unsigned smem_u32(const void* p) {
    return (unsigned)__cvta_generic_to_shared(p);
}
__device__ __forceinline__ float ftanh(float x) {
    float y;
    asm("tanh.approx.f32 %0, %1;" : "=f"(y) : "f"(x));
    return y;
}

#define CP16(dst_u32, src_ptr) \
    asm volatile("cp.async.cg.shared.global [%0], [%1], 16;" :: "r"(dst_u32), "l"(src_ptr))
#define CP_COMMIT() asm volatile("cp.async.commit_group;" ::: "memory")
#define CP_WAIT(N)  asm volatile("cp.async.wait_group %0;" :: "n"(N) : "memory")

// ---------------- fused: embed row norm + fp16 conversion ----------------
__global__ void rnormconv_kernel(const float* __restrict__ embed, float* __restrict__ rnorm,
                                 __half* __restrict__ eh) {
    int v = blockIdx.x;
    const float4* row = (const float4*)(embed + (size_t)v * DE);
    float4 f = row[threadIdx.x];
    float s = f.x*f.x + f.y*f.y + f.z*f.z + f.w*f.w;
    __shared__ float sh[256];
    sh[threadIdx.x] = s; __syncthreads();
    for (int o = 128; o > 0; o >>= 1) {
        if (threadIdx.x < o) sh[threadIdx.x] += sh[threadIdx.x + o];
        __syncthreads();
    }
    if (threadIdx.x == 0) rnorm[v] = 1.0f / fmaxf(sqrtf(sh[0]), 1e-12f);
    __half2* H = (__half2*)(eh + (size_t)v * DE);
    H[2*threadIdx.x]   = __floats2half2_rn(f.x, f.y);
    H[2*threadIdx.x+1] = __floats2half2_rn(f.z, f.w);
}

// ---------------- embedding lookup: writes x fp32 and xh fp16 ----------------
__global__ void embed_kernel(const int* __restrict__ ids, const float* __restrict__ embed,
                             const float* __restrict__ rnorm, const float* __restrict__ sE,
                             float* __restrict__ x, __half* __restrict__ xh) {
    int m = blockIdx.x;
    int id = ids[m];
    float sc = rnorm[id] * expf(*sE);
    const float4* row = (const float4*)(embed + (size_t)id * DE);
    int i = threadIdx.x;
    float4 r = row[i];
    r.x *= sc; r.y *= sc; r.z *= sc; r.w *= sc;
    ((float4*)(x + (size_t)m * DE))[i] = r;
    __half2* hp = (__half2*)(xh + (size_t)m * DE);
    hp[2*i]   = __floats2half2_rn(r.x, r.y);
    hp[2*i+1] = __floats2half2_rn(r.z, r.w);
}

// ---------------- ALL weights fp32 -> fp16, one launch, 2 float4/thread ----------------
__global__ void convall_kernel(const float* __restrict__ Wq, const float* __restrict__ Wk,
                               const float* __restrict__ Wv, const float* __restrict__ Wg,
                               const float* __restrict__ Wo, __half* __restrict__ wh) {
    const size_t LW  = (size_t)DE * DE;
    const size_t QPM = LW / 4;
    size_t qbase = ((size_t)blockIdx.x * blockDim.x + threadIdx.x) * 2;
#pragma unroll
    for (int u = 0; u < 2; u++) {
        size_t q = qbase + u;
        int mat = (int)(q / QPM);
        size_t off = q % QPM;
        const float* src;
        size_t dst;
        if (mat < 16) {
            int l = mat >> 2, f = mat & 3;
            src = (f == 0 ? Wq : f == 1 ? Wk : f == 2 ? Wv : Wg) + (size_t)l * LW;
            dst = (size_t)l * 4 * LW + (size_t)f * LW;
        } else {
            int l = mat - 16;
            src = Wo + (size_t)l * LW;
            dst = (size_t)NL * 4 * LW + (size_t)l * LW;
        }
        float4 v = ((const float4*)src)[off];
        __half2* H = (__half2*)(wh + dst);
        H[2*off]   = __floats2half2_rn(v.x, v.y);
        H[2*off+1] = __floats2half2_rn(v.z, v.w);
    }
}

// ---------------- per-(l,h,rel) mask/rotation table (precise trig, one launch) --------
__global__ void tab_kernel(const float* __restrict__ sw_all, float4* __restrict__ tab) {
    int l = blockIdx.x >> 4;
    int h = blockIdx.x & 15;
    int j = threadIdx.x;                 // j = -rel
    if (j >= 129) return;
    float w = expf(sw_all[l*NH + h]) + 1.0f;
    float phi = (w < 128.0f) ? 0.5f * (cosf(PI_F * w / 128.0f) + 1.0f) : 0.0f;
    float phiw = phi / w;
    float rel = -(float)j;
    float mask = 0.5f * (cosf(PI_F * rel / w) + 1.0f);
    float D = rel * phiw;
    tab[(size_t)(l*NH + h) * TABSTRIDE + j] = make_float4(mask, cosf(D), sinf(D), 0.0f);
}

// ---------------- fp16 tensor-core NT GEMM, cp.async 3-stage, BK=64 ----------------
#define MMA_F16(C, A, B)                                                       \
    asm volatile(                                                              \
        "mma.sync.aligned.m16n8k16.row.col.f32.f16.f16.f32 "                   \
        "{%0,%1,%2,%3}, {%4,%5,%6,%7}, {%8,%9}, {%0,%1,%2,%3};\n"              \
        : "+f"((C)[0]), "+f"((C)[1]), "+f"((C)[2]), "+f"((C)[3])               \
        : "r"((A)[0]), "r"((A)[1]), "r"((A)[2]), "r"((A)[3]),                  \
          "r"((B)[0]), "r"((B)[1]))

__global__ __launch_bounds__(256, 2) void gemm_f16(
    const __half* __restrict__ A, const __half* __restrict__ B,
    float* __restrict__ C, int M, int N, int K,
    const float* __restrict__ colScale, const float* __restrict__ scalarLog,
    int accumulate, __half* __restrict__ Chalf)
{
    extern __shared__ __align__(128) char smem[];
    uint32_t sbase = smem_u32(smem);

    int tid  = threadIdx.x;
    int lane = tid & 31;
    int warp = tid >> 5;
    int wm = (warp >> 2) * 64;
    int wn = (warp & 3) * 32;
    int bm = blockIdx.y * BM;
    int bn = blockIdx.x * BN;

    int r0  = tid >> 3;            // 0..31
    int c16 = tid & 7;             // 0..7
    const char* gA0 = (const char*)(A + (size_t)(bm + r0) * K + c16 * 8);
    const char* gB0 = (const char*)(B + (size_t)(bn + r0) * K + c16 * 8);
    uint32_t s0 = r0 * (SPAD*2) + c16 * 16;
    const size_t rowstep = (size_t)32 * K * 2;
    const uint32_t srowstep = 32 * (SPAD*2);

#define PREFETCH(st, k0)                                                       \
    {                                                                          \
        uint32_t sd = sbase + (st) * STAGE_BYTES;                              \
        size_t gk = (size_t)(k0) * 2;                                          \
        _Pragma("unroll")                                                      \
        for (int i = 0; i < 4; i++) {                                          \
            CP16(sd + 0*PLANE_BYTES + s0 + i*srowstep, gA0 + gk + i*rowstep);  \
            CP16(sd + 1*PLANE_BYTES + s0 + i*srowstep, gB0 + gk + i*rowstep);  \
        }                                                                      \
        CP_COMMIT();                                                           \
    }

    float c[4][4][4];
#pragma unroll
    for (int i = 0; i < 4; i++)
#pragma unroll
        for (int j = 0; j < 4; j++)
#pragma unroll
            for (int q = 0; q < 4; q++) c[i][j][q] = 0.f;

    int arow_l = lane & 15;
    int acol_l = (lane >> 4) << 3;
    int brow_l = (lane & 7) + ((lane >> 4) << 3);
    int bcol_l = ((lane >> 3) & 1) << 3;

    int niter = K / BK;
    PREFETCH(0, 0);
    if (niter > 1) PREFETCH(1, BK);
    CP_WAIT(1);
    __syncthreads();

    for (int it = 0; it < niter; ++it) {
        int st = it % NSTAGE;
        if (it + 2 < niter) PREFETCH((it + 2) % NSTAGE, (it + 2) * BK);

        const __half* sA = (const __half*)(smem + st*STAGE_BYTES + 0*PLANE_BYTES);
        const __half* sB = (const __half*)(smem + st*STAGE_BYTES + 1*PLANE_BYTES);

#pragma unroll
        for (int ks = 0; ks < 4; ks++) {
            unsigned Af[4][4], Bf[4][2];
            int acol = ks * 16 + acol_l;
            int bcol = ks * 16 + bcol_l;
#pragma unroll
            for (int mt = 0; mt < 4; mt++) {
                unsigned sa = smem_u32(&sA[(wm + mt*16 + arow_l) * SPAD + acol]);
                asm volatile("ldmatrix.sync.aligned.m8n8.x4.shared.b16 {%0,%1,%2,%3}, [%4];\n"
                    : "=r"(Af[mt][0]), "=r"(Af[mt][1]), "=r"(Af[mt][2]), "=r"(Af[mt][3]) : "r"(sa));
            }
#pragma unroll
            for (int p = 0; p < 2; p++) {
                unsigned sb = smem_u32(&sB[(wn + p*16 + brow_l) * SPAD + bcol]);
                unsigned q0, q1, q2, q3;
                asm volatile("ldmatrix.sync.aligned.m8n8.x4.shared.b16 {%0,%1,%2,%3}, [%4];\n"
                    : "=r"(q0), "=r"(q1), "=r"(q2), "=r"(q3) : "r"(sb));
                Bf[p*2][0] = q0; Bf[p*2][1] = q1; Bf[p*2+1][0] = q2; Bf[p*2+1][1] = q3;
            }
#pragma unroll
            for (int mt = 0; mt < 4; mt++)
#pragma unroll
                for (int nt = 0; nt < 4; nt++)
                    MMA_F16(c[mt][nt], Af[mt], Bf[nt]);
        }

        if (it + 1 < niter) {
            if (it + 2 < niter) { CP_WAIT(1); } else { CP_WAIT(0); }
            __syncthreads();
        }
    }

    // epilogue
    float sc = scalarLog ? __expf(*scalarLog) : 1.0f;
    int g  = lane >> 2;
    int t2 = (lane & 3) * 2;
#pragma unroll
    for (int mt = 0; mt < 4; mt++) {
#pragma unroll
        for (int nt = 0; nt < 4; nt++) {
            int row = bm + wm + mt*16 + g;
            int col = bn + wn + nt*8 + t2;
            float cs0 = colScale ? colScale[col]   : 1.0f;
            float cs1 = colScale ? colScale[col+1] : 1.0f;
            float v0 = c[mt][nt][0] * sc * cs0;
            float v1 = c[mt][nt][1] * sc * cs1;
            float v2 = c[mt][nt][2] * sc * cs0;
            float v3 = c[mt][nt][3] * sc * cs1;
            if (C) {
                float* p0 = C + (size_t)row * N + col;
                float* p1 = C + (size_t)(row + 8) * N + col;
                if (accumulate) {
                    v0 += p0[0]; v1 += p0[1];
                    v2 += p1[0]; v3 += p1[1];
                }
                float2 a; a.x = v0; a.y = v1; *(float2*)p0 = a;
                float2 b; b.x = v2; b.y = v3; *(float2*)p1 = b;
            }
            if (Chalf) {
                *(__half2*)(Chalf + (size_t)row * N + col)       = __floats2half2_rn(v0, v1);
                *(__half2*)(Chalf + (size_t)(row + 8) * N + col) = __floats2half2_rn(v2, v3);
            }
        }
    }
}

// ---------------- normalize k, v in place (per (m,h)) ----------------
__global__ void normkv_kernel(__half* __restrict__ qkvg) {
    int gwarp = (blockIdx.x * blockDim.x + threadIdx.x) >> 5;
    int lane = threadIdx.x & 31;
    int h = gwarp & (NH - 1);
    int m = gwarp >> 4;
    size_t base = (size_t)m * QS + h * DK + 2 * lane;
    float2 kv = __half22float2(*(const __half2*)(qkvg + base + DE));
    float2 vv = __half22float2(*(const __half2*)(qkvg + base + 2*DE));
    float sk = wredsum(fmaf(kv.x, kv.x, kv.y * kv.y));
    float sv = wredsum(fmaf(vv.x, vv.x, vv.y * vv.y));
    float ik = 1.0f / fmaxf(sqrtf(sk), 1e-12f);
    float iv = 1.0f / fmaxf(sqrtf(sv), 1e-12f);
    *(__half2*)(qkvg + base + DE)   = __floats2half2_rn(kv.x * ik, kv.y * ik);
    *(__half2*)(qkvg + base + 2*DE) = __floats2half2_rn(vv.x * iv, vv.y * iv);
}

// ---------------- fused attention (table-driven, unroll-8, head-uniform blocks) -------
// Warp mapping: h = gwarp >> 12, m = gwarp & 4095 -> all warps in a block share one
// head (uniform window size => no intra-block imbalance; overlapping windows => L1 hits)
__global__ void attn_kernel(const __half* __restrict__ qkvg,
                            const float4* __restrict__ tabl,
                            const float* __restrict__ sw, const float* __restrict__ sr,
                            const float* __restrict__ sO, __half* __restrict__ hhh) {
    int gwarp = (blockIdx.x * blockDim.x + threadIdx.x) >> 5;
    int lane = threadIdx.x & 31;
    int h = gwarp >> 12;
    int m = gwarp & (MTOT - 1);
    int t = m & (SEQ - 1);

    float w  = __expf(sw[h]) + 1.0f;
    float r  = __expf(sr[h]) + 1.0f;
    float es = __expf(sO[h]);
    const float4* th = tabl + h * TABSTRIDE;

    size_t base = (size_t)m * QS + h * DK + 2 * lane;
    float2 qv = __half22float2(*(const __half2*)(qkvg + base));
    float sq = wredsum(fmaf(qv.x, qv.x, qv.y * qv.y));
    float iq = 1.0f / fmaxf(sqrtf(sq), 1e-12f);
    qv.x *= iq; qv.y *= iq;

    int lb = (int)ceilf(w) - 1;     // lb < w => rel > -w for all visited s
    if (lb > t) lb = t;
    int n = lb + 1;
    const __half* kp0 = qkvg + (size_t)(m - lb) * QS + h * DK + 2 * lane + DE;

    float acc0 = 0.f, acc1 = 0.f;
    int i = 0;
    for (; i + 8 <= n; i += 8) {
        float ctr[8];
        float mk[8];
        float2 vvv[8];
#pragma unroll
        for (int u = 0; u < 8; u++) {
            int j = lb - (i + u);                 // j = t - s
            float4 tb = th[j];
            const __half* kp = kp0 + (size_t)(i + u) * QS;
            float2 kv = __half22float2(*(const __half2*)kp);
            vvv[u] = __half22float2(*(const __half2*)(kp + DE));
            float cc = fmaf(qv.x, kv.x, qv.y * kv.y);
            if (lane == 0)
                cc = fmaf(tb.y, cc, tb.z * (qv.x * kv.y - qv.y * kv.x));
            ctr[u] = cc;
            mk[u] = tb.x;
        }
#pragma unroll
        for (int o = 16; o > 0; o >>= 1) {
#pragma unroll
            for (int u = 0; u < 8; u++)
                ctr[u] += __shfl_xor_sync(0xFFFFFFFFu, ctr[u], o);
        }
#pragma unroll
        for (int u = 0; u < 8; u++) {
            float tmp = fmaxf(fmaf(r, ctr[u] - 1.0f, 1.0f), 0.0f);
            float rho = tmp * tmp * mk[u];
            acc0 = fmaf(rho, vvv[u].x, acc0);
            acc1 = fmaf(rho, vvv[u].y, acc1);
        }
    }
    for (; i < n; ++i) {
        int j = lb - i;
        float4 tb = th[j];
        const __half* kp = kp0 + (size_t)i * QS;
        float2 kv = __half22float2(*(const __half2*)kp);
        float2 vv = __half22float2(*(const __half2*)(kp + DE));
        float cc = fmaf(qv.x, kv.x, qv.y * kv.y);
        if (lane == 0)
            cc = fmaf(tb.y, cc, tb.z * (qv.x * kv.y - qv.y * kv.x));
        float sim = wredsum(cc);
        float tmp = fmaxf(fmaf(r, sim - 1.0f, 1.0f), 0.0f);
        float rho = tmp * tmp * tb.x;
        acc0 = fmaf(rho, vv.x, acc0);
        acc1 = fmaf(rho, vv.y, acc1);
    }

    float hn2 = wredsum(fmaf(acc0, acc0, acc1 * acc1));
    float hn = fmaxf(sqrtf(hn2), 1e-8f);
    float us = ftanh(hn) / hn;

    // g_hat = tanh(silu(g)) on raw g
    float2 gv = __half22float2(*(const __half2*)(qkvg + base + 3*DE));
    float s0 = gv.x / (1.0f + __expf(-gv.x));
    float s1 = gv.y / (1.0f + __expf(-gv.y));
    float g0 = ftanh(s0), g1 = ftanh(s1);

    float o0 = acc0 * us * g0 * es;
    float o1 = acc1 * us * g1 * es;
    size_t ob = (size_t)m * DE + h * DK + 2 * lane;
    *(__half2*)(hhh + ob) = __floats2half2_rn(o0, o1);
}

// ---------------- launch ----------------
extern "C" void kernel_launch(void* const* d_in, const int* in_sizes, int n_in,
                              void* d_out, int out_size) {
    const int*   ids   = (const int*)d_in[0];
    const float* embed = (const float*)d_in[1];
    const float* sE    = (const float*)d_in[2];
    const float* sF    = (const float*)d_in[3];
    const float* Wq    = (const float*)d_in[4];
    const float* Wk    = (const float*)d_in[5];
    const float* Wv    = (const float*)d_in[6];
    const float* Wg    = (const float*)d_in[7];
    const float* Wo    = (const float*)d_in[8];
    const float* sw    = (const float*)d_in[9];
    const float* sr    = (const float*)d_in[10];
    const float* sO    = (const float*)d_in[11];
    float* out = (float*)d_out;

    cudaFuncSetAttribute(gemm_f16, cudaFuncAttributeMaxDynamicSharedMemorySize, SMEM_GEMM);

    float *x, *rn;
    cudaGetSymbolAddress((void**)&x,   d_x);
    cudaGetSymbolAddress((void**)&rn,  d_rnorm);
    float4* tab;
    cudaGetSymbolAddress((void**)&tab, d_tab);
    __half *qkvg, *xh, *hhh, *eh, *wh;
    cudaGetSymbolAddress((void**)&qkvg, d_qkvg);
    cudaGetSymbolAddress((void**)&xh,  d_xh);
    cudaGetSymbolAddress((void**)&hhh, d_hhh);
    cudaGetSymbolAddress((void**)&eh,  d_eh);
    cudaGetSymbolAddress((void**)&wh,  d_wh);

    const size_t LW = (size_t)DE * DE;
    const size_t WO_BASE = (size_t)NL * 4 * LW;

    rnormconv_kernel<<<VOCAB, 256>>>(embed, rn, eh);
    embed_kernel<<<MTOT, 256>>>(ids, embed, rn, sE, x, xh);
    convall_kernel<<<(int)(20 * LW / 4 / 512), 256>>>(Wq, Wk, Wv, Wg, Wo, wh);
    tab_kernel<<<NL*NH, 160>>>(sw, tab);

    dim3 gfused(QS / BN, MTOT / BM);   // (32, 32)
    dim3 gwo(DE / BN, MTOT / BM);      // (8, 32)
    int warps_total = MTOT * NH;
    int nblk = (warps_total * 32) / 256;

    for (int l = 0; l < NL; ++l) {
        size_t fb = (size_t)l * 4 * LW;
        const float* swl = sw + l * NH;
        const float* srl = sr + l * NH;
        const float* sOl = sO + l * NH;
        const float4* tabl = tab + (size_t)l * NH * TABSTRIDE;

        gemm_f16<<<gfused, 256, SMEM_GEMM>>>(xh, wh + fb, nullptr,
                                             MTOT, QS, DE, nullptr, nullptr, 0, qkvg);
        normkv_kernel<<<nblk, 256>>>(qkvg);
        attn_kernel<<<nblk, 256>>>(qkvg, tabl, swl, srl, sOl, hhh);
        gemm_f16<<<gwo, 256, SMEM_GEMM>>>(hhh, wh + WO_BASE + l*LW, x,
                                          MTOT, DE, DE, nullptr, nullptr, 1, xh);
    }

    dim3 gfin(VOCAB / BN, MTOT / BM);  // (250, 32)
    gemm_f16<<<gfin, 256, SMEM_GEMM>>>(xh, eh, out, MTOT, VOCAB, DE, rn, sF, 0, nullptr);
}

// round 13
// speedup vs baseline: 8.0188x; 1.0231x over previous
#include <cuda_runtime.h>
#include <cuda_fp16.h>
#include <math.h>
#include <stdint.h>

#define BATCH 2
#define SEQ   2048
#define MTOT  (BATCH*SEQ)      // 4096
#define DE    1024
#define NH    16
#define DK    64
#define VOCAB 32000
#define NL    4
#define QS    (4*DE)           // fused qkvg row stride
#define PI_F  3.14159265358979323846f
#define TABSTRIDE 132          // float4 entries per (l,h)

#define BM 128
#define BN 128
#define BK 64
#define SPAD 72                     // fp16 elems per smem row (144B, conflict-free)
#define PLANE_BYTES (128*SPAD*2)    // 18432
#define STAGE_BYTES (2*PLANE_BYTES) // 36864 (A, B)
#define NSTAGE 3
#define SMEM_GEMM (NSTAGE*STAGE_BYTES) // 110592

// ---------------- scratch (static device globals; no allocation) ----------------
__device__ float d_rnorm[VOCAB];
__device__ float d_x   [MTOT*DE];
__device__ __half d_qkvg[(size_t)MTOT*QS];
__device__ __half d_xh [MTOT*DE];
__device__ __half d_hhh[MTOT*DE];
__device__ __half d_eh [(size_t)VOCAB*DE];
__device__ __half d_wh [(size_t)5*NL*DE*DE];   // [l][Wq,Wk,Wv,Wg], then [l][Wo]
__device__ float4 d_tab[NL*NH*TABSTRIDE];      // (mask, cosD, sinD, 0) per (l,h,-rel)

__device__ __forceinline__ float wredsum(float x) {
#pragma unroll
    for (int o = 16; o > 0; o >>= 1) x += __shfl_xor_sync(0xFFFFFFFFu, x, o);
    return x;
}
__device__ __forceinline__ unsigned smem_u32(const void* p) {
    return (unsigned)__cvta_generic_to_shared(p);
}
__device__ __forceinline__ float ftanh(float x) {
    float y;
    asm("tanh.approx.f32 %0, %1;" : "=f"(y) : "f"(x));
    return y;
}

#define CP16(dst_u32, src_ptr) \
    asm volatile("cp.async.cg.shared.global [%0], [%1], 16;" :: "r"(dst_u32), "l"(src_ptr))
#define CP_COMMIT() asm volatile("cp.async.commit_group;" ::: "memory")
#define CP_WAIT(N)  asm volatile("cp.async.wait_group %0;" :: "n"(N) : "memory")

// ---------------- fused: embed row norm + fp16 conversion ----------------
__global__ void rnormconv_kernel(const float* __restrict__ embed, float* __restrict__ rnorm,
                                 __half* __restrict__ eh) {
    int v = blockIdx.x;
    const float4* row = (const float4*)(embed + (size_t)v * DE);
    float4 f = row[threadIdx.x];
    float s = f.x*f.x + f.y*f.y + f.z*f.z + f.w*f.w;
    __shared__ float sh[256];
    sh[threadIdx.x] = s; __syncthreads();
    for (int o = 128; o > 0; o >>= 1) {
        if (threadIdx.x < o) sh[threadIdx.x] += sh[threadIdx.x + o];
        __syncthreads();
    }
    if (threadIdx.x == 0) rnorm[v] = 1.0f / fmaxf(sqrtf(sh[0]), 1e-12f);
    __half2* H = (__half2*)(eh + (size_t)v * DE);
    H[2*threadIdx.x]   = __floats2half2_rn(f.x, f.y);
    H[2*threadIdx.x+1] = __floats2half2_rn(f.z, f.w);
}

// ---------------- embedding lookup: writes x fp32 and xh fp16 ----------------
__global__ void embed_kernel(const int* __restrict__ ids, const float* __restrict__ embed,
                             const float* __restrict__ rnorm, const float* __restrict__ sE,
                             float* __restrict__ x, __half* __restrict__ xh) {
    int m = blockIdx.x;
    int id = ids[m];
    float sc = rnorm[id] * expf(*sE);
    const float4* row = (const float4*)(embed + (size_t)id * DE);
    int i = threadIdx.x;
    float4 r = row[i];
    r.x *= sc; r.y *= sc; r.z *= sc; r.w *= sc;
    ((float4*)(x + (size_t)m * DE))[i] = r;
    __half2* hp = (__half2*)(xh + (size_t)m * DE);
    hp[2*i]   = __floats2half2_rn(r.x, r.y);
    hp[2*i+1] = __floats2half2_rn(r.z, r.w);
}

// ---------------- ALL weights fp32 -> fp16, one launch, 2 float4/thread ----------------
__global__ void convall_kernel(const float* __restrict__ Wq, const float* __restrict__ Wk,
                               const float* __restrict__ Wv, const float* __restrict__ Wg,
                               const float* __restrict__ Wo, __half* __restrict__ wh) {
    const size_t LW  = (size_t)DE * DE;
    const size_t QPM = LW / 4;
    size_t qbase = ((size_t)blockIdx.x * blockDim.x + threadIdx.x) * 2;
#pragma unroll
    for (int u = 0; u < 2; u++) {
        size_t q = qbase + u;
        int mat = (int)(q / QPM);
        size_t off = q % QPM;
        const float* src;
        size_t dst;
        if (mat < 16) {
            int l = mat >> 2, f = mat & 3;
            src = (f == 0 ? Wq : f == 1 ? Wk : f == 2 ? Wv : Wg) + (size_t)l * LW;
            dst = (size_t)l * 4 * LW + (size_t)f * LW;
        } else {
            int l = mat - 16;
            src = Wo + (size_t)l * LW;
            dst = (size_t)NL * 4 * LW + (size_t)l * LW;
        }
        float4 v = ((const float4*)src)[off];
        __half2* H = (__half2*)(wh + dst);
        H[2*off]   = __floats2half2_rn(v.x, v.y);
        H[2*off+1] = __floats2half2_rn(v.z, v.w);
    }
}

// ---------------- per-(l,h,rel) mask/rotation table (precise trig, one launch) --------
__global__ void tab_kernel(const float* __restrict__ sw_all, float4* __restrict__ tab) {
    int l = blockIdx.x >> 4;
    int h = blockIdx.x & 15;
    int j = threadIdx.x;                 // j = -rel
    if (j >= 129) return;
    float w = expf(sw_all[l*NH + h]) + 1.0f;
    float phi = (w < 128.0f) ? 0.5f * (cosf(PI_F * w / 128.0f) + 1.0f) : 0.0f;
    float phiw = phi / w;
    float rel = -(float)j;
    float mask = 0.5f * (cosf(PI_F * rel / w) + 1.0f);
    float D = rel * phiw;
    tab[(size_t)(l*NH + h) * TABSTRIDE + j] = make_float4(mask, cosf(D), sinf(D), 0.0f);
}

// ---------------- fp16 tensor-core NT GEMM, cp.async 3-stage, BK=64 ----------------
// normKV: for the fused qkvg GEMM, tiles in the k/v column ranges get their
// per-(row,head) L2 normalization fused into the epilogue (head = 64 cols; each
// 128-col tile holds exactly 2 heads; warps (wn 0,32) and (wn 64,96) pair up).
#define MMA_F16(C, A, B)                                                       \
    asm volatile(                                                              \
        "mma.sync.aligned.m16n8k16.row.col.f32.f16.f16.f32 "                   \
        "{%0,%1,%2,%3}, {%4,%5,%6,%7}, {%8,%9}, {%0,%1,%2,%3};\n"              \
        : "+f"((C)[0]), "+f"((C)[1]), "+f"((C)[2]), "+f"((C)[3])               \
        : "r"((A)[0]), "r"((A)[1]), "r"((A)[2]), "r"((A)[3]),                  \
          "r"((B)[0]), "r"((B)[1]))

__global__ __launch_bounds__(256, 2) void gemm_f16(
    const __half* __restrict__ A, const __half* __restrict__ B,
    float* __restrict__ C, int M, int N, int K,
    const float* __restrict__ colScale, const float* __restrict__ scalarLog,
    int accumulate, __half* __restrict__ Chalf, int normKV)
{
    extern __shared__ __align__(128) char smem[];
    uint32_t sbase = smem_u32(smem);

    int tid  = threadIdx.x;
    int lane = tid & 31;
    int warp = tid >> 5;
    int wm = (warp >> 2) * 64;
    int wn = (warp & 3) * 32;
    int bm = blockIdx.y * BM;
    int bn = blockIdx.x * BN;

    int r0  = tid >> 3;            // 0..31
    int c16 = tid & 7;             // 0..7
    const char* gA0 = (const char*)(A + (size_t)(bm + r0) * K + c16 * 8);
    const char* gB0 = (const char*)(B + (size_t)(bn + r0) * K + c16 * 8);
    uint32_t s0 = r0 * (SPAD*2) + c16 * 16;
    const size_t rowstep = (size_t)32 * K * 2;
    const uint32_t srowstep = 32 * (SPAD*2);

#define PREFETCH(st, k0)                                                       \
    {                                                                          \
        uint32_t sd = sbase + (st) * STAGE_BYTES;                              \
        size_t gk = (size_t)(k0) * 2;                                          \
        _Pragma("unroll")                                                      \
        for (int i = 0; i < 4; i++) {                                          \
            CP16(sd + 0*PLANE_BYTES + s0 + i*srowstep, gA0 + gk + i*rowstep);  \
            CP16(sd + 1*PLANE_BYTES + s0 + i*srowstep, gB0 + gk + i*rowstep);  \
        }                                                                      \
        CP_COMMIT();                                                           \
    }

    float c[4][4][4];
#pragma unroll
    for (int i = 0; i < 4; i++)
#pragma unroll
        for (int j = 0; j < 4; j++)
#pragma unroll
            for (int q = 0; q < 4; q++) c[i][j][q] = 0.f;

    int arow_l = lane & 15;
    int acol_l = (lane >> 4) << 3;
    int brow_l = (lane & 7) + ((lane >> 4) << 3);
    int bcol_l = ((lane >> 3) & 1) << 3;

    int niter = K / BK;
    PREFETCH(0, 0);
    if (niter > 1) PREFETCH(1, BK);
    CP_WAIT(1);
    __syncthreads();

    for (int it = 0; it < niter; ++it) {
        int st = it % NSTAGE;
        if (it + 2 < niter) PREFETCH((it + 2) % NSTAGE, (it + 2) * BK);

        const __half* sA = (const __half*)(smem + st*STAGE_BYTES + 0*PLANE_BYTES);
        const __half* sB = (const __half*)(smem + st*STAGE_BYTES + 1*PLANE_BYTES);

#pragma unroll
        for (int ks = 0; ks < 4; ks++) {
            unsigned Af[4][4], Bf[4][2];
            int acol = ks * 16 + acol_l;
            int bcol = ks * 16 + bcol_l;
#pragma unroll
            for (int mt = 0; mt < 4; mt++) {
                unsigned sa = smem_u32(&sA[(wm + mt*16 + arow_l) * SPAD + acol]);
                asm volatile("ldmatrix.sync.aligned.m8n8.x4.shared.b16 {%0,%1,%2,%3}, [%4];\n"
                    : "=r"(Af[mt][0]), "=r"(Af[mt][1]), "=r"(Af[mt][2]), "=r"(Af[mt][3]) : "r"(sa));
            }
#pragma unroll
            for (int p = 0; p < 2; p++) {
                unsigned sb = smem_u32(&sB[(wn + p*16 + brow_l) * SPAD + bcol]);
                unsigned q0, q1, q2, q3;
                asm volatile("ldmatrix.sync.aligned.m8n8.x4.shared.b16 {%0,%1,%2,%3}, [%4];\n"
                    : "=r"(q0), "=r"(q1), "=r"(q2), "=r"(q3) : "r"(sb));
                Bf[p*2][0] = q0; Bf[p*2][1] = q1; Bf[p*2+1][0] = q2; Bf[p*2+1][1] = q3;
            }
#pragma unroll
            for (int mt = 0; mt < 4; mt++)
#pragma unroll
                for (int nt = 0; nt < 4; nt++)
                    MMA_F16(c[mt][nt], Af[mt], Bf[nt]);
        }

        if (it + 1 < niter) {
            if (it + 2 < niter) { CP_WAIT(1); } else { CP_WAIT(0); }
            __syncthreads();
        }
    }

    int g  = lane >> 2;
    int t2 = (lane & 3) * 2;

    // ---- fused k/v head normalization (fused qkvg GEMM only) ----
    if (normKV && ((bn >> 10) == 1 || (bn >> 10) == 2)) {
        float* ssum = (float*)smem;          // 128 rows x 4 col-groups
        __syncthreads();                     // mainloop smem reads done
#pragma unroll
        for (int mt = 0; mt < 4; mt++) {
#pragma unroll
            for (int rh = 0; rh < 2; rh++) {
                float p = 0.f;
#pragma unroll
                for (int nt = 0; nt < 4; nt++) {
                    float a = c[mt][nt][rh*2], b = c[mt][nt][rh*2+1];
                    p = fmaf(a, a, p); p = fmaf(b, b, p);
                }
                p += __shfl_xor_sync(0xFFFFFFFFu, p, 1);
                p += __shfl_xor_sync(0xFFFFFFFFu, p, 2);
                if ((lane & 3) == 0)
                    ssum[(wm + mt*16 + g + rh*8) * 4 + (wn >> 5)] = p;
            }
        }
        __syncthreads();
        int basegrp = (wn >> 5) & ~1;
#pragma unroll
        for (int mt = 0; mt < 4; mt++) {
#pragma unroll
            for (int rh = 0; rh < 2; rh++) {
                int rl = wm + mt*16 + g + rh*8;
                float hs = ssum[rl*4 + basegrp] + ssum[rl*4 + basegrp + 1];
                float ik = 1.0f / fmaxf(sqrtf(hs), 1e-12f);
#pragma unroll
                for (int nt = 0; nt < 4; nt++) {
                    c[mt][nt][rh*2]   *= ik;
                    c[mt][nt][rh*2+1] *= ik;
                }
            }
        }
    }

    // epilogue
    float sc = scalarLog ? __expf(*scalarLog) : 1.0f;
#pragma unroll
    for (int mt = 0; mt < 4; mt++) {
#pragma unroll
        for (int nt = 0; nt < 4; nt++) {
            int row = bm + wm + mt*16 + g;
            int col = bn + wn + nt*8 + t2;
            float cs0 = colScale ? colScale[col]   : 1.0f;
            float cs1 = colScale ? colScale[col+1] : 1.0f;
            float v0 = c[mt][nt][0] * sc * cs0;
            float v1 = c[mt][nt][1] * sc * cs1;
            float v2 = c[mt][nt][2] * sc * cs0;
            float v3 = c[mt][nt][3] * sc * cs1;
            if (C) {
                float* p0 = C + (size_t)row * N + col;
                float* p1 = C + (size_t)(row + 8) * N + col;
                if (accumulate) {
                    v0 += p0[0]; v1 += p0[1];
                    v2 += p1[0]; v3 += p1[1];
                }
                float2 a; a.x = v0; a.y = v1; *(float2*)p0 = a;
                float2 b; b.x = v2; b.y = v3; *(float2*)p1 = b;
            }
            if (Chalf) {
                *(__half2*)(Chalf + (size_t)row * N + col)       = __floats2half2_rn(v0, v1);
                *(__half2*)(Chalf + (size_t)(row + 8) * N + col) = __floats2half2_rn(v2, v3);
            }
        }
    }
}

// ---------------- fused attention (table-driven, unroll-8, head-uniform blocks) -------
__global__ void attn_kernel(const __half* __restrict__ qkvg,
                            const float4* __restrict__ tabl,
                            const float* __restrict__ sw, const float* __restrict__ sr,
                            const float* __restrict__ sO, __half* __restrict__ hhh) {
    int gwarp = (blockIdx.x * blockDim.x + threadIdx.x) >> 5;
    int lane = threadIdx.x & 31;
    int h = gwarp >> 12;
    int m = gwarp & (MTOT - 1);
    int t = m & (SEQ - 1);

    float w  = __expf(sw[h]) + 1.0f;
    float r  = __expf(sr[h]) + 1.0f;
    float es = __expf(sO[h]);
    const float4* th = tabl + h * TABSTRIDE;

    size_t base = (size_t)m * QS + h * DK + 2 * lane;
    float2 qv = __half22float2(*(const __half2*)(qkvg + base));
    float sq = wredsum(fmaf(qv.x, qv.x, qv.y * qv.y));
    float iq = 1.0f / fmaxf(sqrtf(sq), 1e-12f);
    qv.x *= iq; qv.y *= iq;

    int lb = (int)ceilf(w) - 1;     // lb < w => rel > -w for all visited s
    if (lb > t) lb = t;
    int n = lb + 1;
    const __half* kp0 = qkvg + (size_t)(m - lb) * QS + h * DK + 2 * lane + DE;

    float acc0 = 0.f, acc1 = 0.f;
    int i = 0;
    for (; i + 8 <= n; i += 8) {
        float ctr[8];
        float mk[8];
        float2 vvv[8];
#pragma unroll
        for (int u = 0; u < 8; u++) {
            int j = lb - (i + u);                 // j = t - s
            float4 tb = th[j];
            const __half* kp = kp0 + (size_t)(i + u) * QS;
            float2 kv = __half22float2(*(const __half2*)kp);
            vvv[u] = __half22float2(*(const __half2*)(kp + DE));
            float cc = fmaf(qv.x, kv.x, qv.y * kv.y);
            if (lane == 0)
                cc = fmaf(tb.y, cc, tb.z * (qv.x * kv.y - qv.y * kv.x));
            ctr[u] = cc;
            mk[u] = tb.x;
        }
#pragma unroll
        for (int o = 16; o > 0; o >>= 1) {
#pragma unroll
            for (int u = 0; u < 8; u++)
                ctr[u] += __shfl_xor_sync(0xFFFFFFFFu, ctr[u], o);
        }
#pragma unroll
        for (int u = 0; u < 8; u++) {
            float tmp = fmaxf(fmaf(r, ctr[u] - 1.0f, 1.0f), 0.0f);
            float rho = tmp * tmp * mk[u];
            acc0 = fmaf(rho, vvv[u].x, acc0);
            acc1 = fmaf(rho, vvv[u].y, acc1);
        }
    }
    for (; i < n; ++i) {
        int j = lb - i;
        float4 tb = th[j];
        const __half* kp = kp0 + (size_t)i * QS;
        float2 kv = __half22float2(*(const __half2*)kp);
        float2 vv = __half22float2(*(const __half2*)(kp + DE));
        float cc = fmaf(qv.x, kv.x, qv.y * kv.y);
        if (lane == 0)
            cc = fmaf(tb.y, cc, tb.z * (qv.x * kv.y - qv.y * kv.x));
        float sim = wredsum(cc);
        float tmp = fmaxf(fmaf(r, sim - 1.0f, 1.0f), 0.0f);
        float rho = tmp * tmp * tb.x;
        acc0 = fmaf(rho, vv.x, acc0);
        acc1 = fmaf(rho, vv.y, acc1);
    }

    float hn2 = wredsum(fmaf(acc0, acc0, acc1 * acc1));
    float hn = fmaxf(sqrtf(hn2), 1e-8f);
    float us = ftanh(hn) / hn;

    // g_hat = tanh(silu(g)) on raw g
    float2 gv = __half22float2(*(const __half2*)(qkvg + base + 3*DE));
    float s0 = gv.x / (1.0f + __expf(-gv.x));
    float s1 = gv.y / (1.0f + __expf(-gv.y));
    float g0 = ftanh(s0), g1 = ftanh(s1);

    float o0 = acc0 * us * g0 * es;
    float o1 = acc1 * us * g1 * es;
    size_t ob = (size_t)m * DE + h * DK + 2 * lane;
    *(__half2*)(hhh + ob) = __floats2half2_rn(o0, o1);
}

// ---------------- launch ----------------
extern "C" void kernel_launch(void* const* d_in, const int* in_sizes, int n_in,
                              void* d_out, int out_size) {
    const int*   ids   = (const int*)d_in[0];
    const float* embed = (const float*)d_in[1];
    const float* sE    = (const float*)d_in[2];
    const float* sF    = (const float*)d_in[3];
    const float* Wq    = (const float*)d_in[4];
    const float* Wk    = (const float*)d_in[5];
    const float* Wv    = (const float*)d_in[6];
    const float* Wg    = (const float*)d_in[7];
    const float* Wo    = (const float*)d_in[8];
    const float* sw    = (const float*)d_in[9];
    const float* sr    = (const float*)d_in[10];
    const float* sO    = (const float*)d_in[11];
    float* out = (float*)d_out;

    cudaFuncSetAttribute(gemm_f16, cudaFuncAttributeMaxDynamicSharedMemorySize, SMEM_GEMM);

    float *x, *rn;
    cudaGetSymbolAddress((void**)&x,   d_x);
    cudaGetSymbolAddress((void**)&rn,  d_rnorm);
    float4* tab;
    cudaGetSymbolAddress((void**)&tab, d_tab);
    __half *qkvg, *xh, *hhh, *eh, *wh;
    cudaGetSymbolAddress((void**)&qkvg, d_qkvg);
    cudaGetSymbolAddress((void**)&xh,  d_xh);
    cudaGetSymbolAddress((void**)&hhh, d_hhh);
    cudaGetSymbolAddress((void**)&eh,  d_eh);
    cudaGetSymbolAddress((void**)&wh,  d_wh);

    const size_t LW = (size_t)DE * DE;
    const size_t WO_BASE = (size_t)NL * 4 * LW;

    rnormconv_kernel<<<VOCAB, 256>>>(embed, rn, eh);
    embed_kernel<<<MTOT, 256>>>(ids, embed, rn, sE, x, xh);
    convall_kernel<<<(int)(20 * LW / 4 / 512), 256>>>(Wq, Wk, Wv, Wg, Wo, wh);
    tab_kernel<<<NL*NH, 160>>>(sw, tab);

    dim3 gfused(QS / BN, MTOT / BM);   // (32, 32)
    dim3 gwo(DE / BN, MTOT / BM);      // (8, 32)
    int warps_total = MTOT * NH;
    int nblk = (warps_total * 32) / 256;

    for (int l = 0; l < NL; ++l) {
        size_t fb = (size_t)l * 4 * LW;
        const float* swl = sw + l * NH;
        const float* srl = sr + l * NH;
        const float* sOl = sO + l * NH;
        const float4* tabl = tab + (size_t)l * NH * TABSTRIDE;

        gemm_f16<<<gfused, 256, SMEM_GEMM>>>(xh, wh + fb, nullptr,
                                             MTOT, QS, DE, nullptr, nullptr, 0, qkvg, 1);
        attn_kernel<<<nblk, 256>>>(qkvg, tabl, swl, srl, sOl, hhh);
        gemm_f16<<<gwo, 256, SMEM_GEMM>>>(hhh, wh + WO_BASE + l*LW, x,
                                          MTOT, DE, DE, nullptr, nullptr, 1, xh, 0);
    }

    dim3 gfin(VOCAB / BN, MTOT / BM);  // (250, 32)
    gemm_f16<<<gfin, 256, SMEM_GEMM>>>(xh, eh, out, MTOT, VOCAB, DE, rn, sF, 0, nullptr, 0);
}